// round 1
// baseline (speedup 1.0000x reference)
#include <cuda_runtime.h>
#include <cstdint>

#define B_ 2
#define L_ 2048
#define D_ 768
#define H_ 12
#define DH_ 64
#define M_ (B_*L_)        // 4096 rows
#define DFF_ 2304
#define UPN_ (2*DFF_)     // 4608

// ---------------- scratch (device globals; no allocs allowed) ----------------
__device__ float g_norm [M_*D_];
__device__ float g_normc[M_*D_];
__device__ float g_big  [M_*UPN_];    // qkv (4096x2304) / kv (4096x1536) / ff up (4096x4608)
__device__ float g_lin2 [M_*D_];      // ca q linear
__device__ float g_q    [B_*H_*L_*DH_];
__device__ float g_k    [B_*H_*L_*DH_];
__device__ float g_v    [B_*H_*L_*DH_];
__device__ float g_ao   [M_*D_];      // attention out, [B,L,D] layout
__device__ float g_x1   [M_*D_];
__device__ float g_x2   [M_*D_];
__device__ float g_ag   [M_*DFF_];

// ---------------- rmsnorm: one block per row of 768 ----------------
__global__ void rmsnorm_kernel(const float* __restrict__ x, const float* __restrict__ sc,
                               float* __restrict__ out) {
    int row = blockIdx.x;
    const float* xr = x + (size_t)row * D_;
    float s = 0.f;
    for (int i = threadIdx.x; i < D_; i += 256) { float v = xr[i]; s += v * v; }
    #pragma unroll
    for (int o = 16; o > 0; o >>= 1) s += __shfl_xor_sync(0xffffffffu, s, o);
    __shared__ float red[8];
    __shared__ float rtot;
    if ((threadIdx.x & 31) == 0) red[threadIdx.x >> 5] = s;
    __syncthreads();
    if (threadIdx.x == 0) {
        float t = 0.f;
        #pragma unroll
        for (int i = 0; i < 8; i++) t += red[i];
        rtot = rsqrtf(t / (float)D_ + 1e-6f);
    }
    __syncthreads();
    float r = rtot;
    for (int i = threadIdx.x; i < D_; i += 256)
        out[(size_t)row * D_ + i] = xr[i] * sc[i] * r;
}

// ---------------- SGEMM NT: C[M,N] = A[M,K] * B[N,K]^T (+R) ----------------
// BM=BN=128, BK=16, 256 threads, 8x8 per thread. All dims divide tiles exactly.
template<bool RESID>
__global__ __launch_bounds__(256) void gemm_nt(const float* __restrict__ A,
                                               const float* __restrict__ Bw,
                                               const float* __restrict__ R,
                                               float* __restrict__ C,
                                               int M, int N, int K) {
    __shared__ float As[16][132];
    __shared__ float Bs[16][132];
    const int t = threadIdx.x;
    const int m0 = blockIdx.y * 128, n0 = blockIdx.x * 128;
    const int tx = t & 15, ty = t >> 4;
    float acc[8][8];
    #pragma unroll
    for (int i = 0; i < 8; i++)
        #pragma unroll
        for (int j = 0; j < 8; j++) acc[i][j] = 0.f;

    for (int k0 = 0; k0 < K; k0 += 16) {
        #pragma unroll
        for (int i = 0; i < 2; i++) {
            int idx = t + i * 256;            // 0..511 float4 slots
            int r = idx >> 2, c4 = idx & 3;
            float4 va = *(const float4*)(A  + (size_t)(m0 + r) * K + k0 + c4 * 4);
            As[c4*4+0][r] = va.x; As[c4*4+1][r] = va.y;
            As[c4*4+2][r] = va.z; As[c4*4+3][r] = va.w;
            float4 vb = *(const float4*)(Bw + (size_t)(n0 + r) * K + k0 + c4 * 4);
            Bs[c4*4+0][r] = vb.x; Bs[c4*4+1][r] = vb.y;
            Bs[c4*4+2][r] = vb.z; Bs[c4*4+3][r] = vb.w;
        }
        __syncthreads();
        #pragma unroll
        for (int kk = 0; kk < 16; kk++) {
            float a[8], b[8];
            *(float4*)&a[0] = *(const float4*)&As[kk][ty * 8];
            *(float4*)&a[4] = *(const float4*)&As[kk][ty * 8 + 4];
            *(float4*)&b[0] = *(const float4*)&Bs[kk][tx * 8];
            *(float4*)&b[4] = *(const float4*)&Bs[kk][tx * 8 + 4];
            #pragma unroll
            for (int i = 0; i < 8; i++)
                #pragma unroll
                for (int j = 0; j < 8; j++) acc[i][j] += a[i] * b[j];
        }
        __syncthreads();
    }

    #pragma unroll
    for (int i = 0; i < 8; i++) {
        int m = m0 + ty * 8 + i;
        #pragma unroll
        for (int j4 = 0; j4 < 2; j4++) {
            int n = n0 + tx * 8 + j4 * 4;
            float4 v = make_float4(acc[i][j4*4+0], acc[i][j4*4+1],
                                   acc[i][j4*4+2], acc[i][j4*4+3]);
            if (RESID) {
                float4 rr = *(const float4*)(R + (size_t)m * N + n);
                v.x += rr.x; v.y += rr.y; v.z += rr.z; v.w += rr.w;
            }
            *(float4*)(C + (size_t)m * N + n) = v;
        }
    }
}

// ---------------- cos_scale + RoPE pack: one warp per (b,l,h) ----------------
__device__ __forceinline__ float theta_of(int j, int h, float p0, float p1, float p2) {
    int i = j >> 3, f = j & 7;
    float pc = (i == 0) ? p0 : ((i == 1) ? p1 : p2);
    // F[h,f] = pi * exp((f*12 + h) * ln(10)/96)
    float freq = 3.14159265358979f * __expf((float)(f * 12 + h) * 0.02398526136f);
    return pc * freq;
}

__global__ void qk_transform(const float* __restrict__ src, int rowStride, int colOff,
                             const float* __restrict__ pos, const float* __restrict__ hscale,
                             float* __restrict__ dst) {
    int w = (blockIdx.x * blockDim.x + threadIdx.x) >> 5;
    int lane = threadIdx.x & 31;
    if (w >= B_ * L_ * H_) return;
    int h = w % H_;
    int bl = w / H_;
    int b = bl / L_, l = bl % L_;

    const float* sp = src + (size_t)bl * rowStride + colOff + h * DH_;
    float v0 = sp[lane], v1 = sp[lane + 32];
    float ss = v0 * v0 + v1 * v1;
    #pragma unroll
    for (int o = 16; o > 0; o >>= 1) ss += __shfl_xor_sync(0xffffffffu, ss, o);
    float f = sqrtf(hscale[h]) * rsqrtf(ss + 1e-6f);
    v0 *= f; v1 *= f;

    __shared__ float sh[8][64];
    int wl = threadIdx.x >> 5;
    sh[wl][lane] = v0; sh[wl][lane + 32] = v1;
    __syncwarp();

    float p0 = pos[(size_t)bl * 3 + 0];
    float p1 = pos[(size_t)bl * 3 + 1];
    float p2 = pos[(size_t)bl * 3 + 2];

    float out0, out1;
    {
        int d = lane;                  // 0..31
        if (d < 24) {
            float th = theta_of(d, h, p0, p1, p2);
            float s, c; __sincosf(th, &s, &c);
            out0 = sh[wl][d] * c - sh[wl][d + 24] * s;
        } else {                       // 24..31 -> pair j = d-24
            float th = theta_of(d - 24, h, p0, p1, p2);
            float s, c; __sincosf(th, &s, &c);
            out0 = sh[wl][d] * c + sh[wl][d - 24] * s;
        }
    }
    {
        int d = lane + 32;             // 32..63
        if (d < 48) {
            float th = theta_of(d - 24, h, p0, p1, p2);
            float s, c; __sincosf(th, &s, &c);
            out1 = sh[wl][d] * c + sh[wl][d - 24] * s;
        } else {
            out1 = sh[wl][d];
        }
    }
    float* dp = dst + ((size_t)(b * H_ + h) * L_ + l) * DH_;
    dp[lane] = out0; dp[lane + 32] = out1;
}

// ---------------- v copy (layout change only) ----------------
__global__ void copy_v(const float* __restrict__ src, int rowStride, int colOff,
                       float* __restrict__ dst) {
    int idx = blockIdx.x * 256 + threadIdx.x;
    if (idx >= M_ * D_) return;
    int d = idx & 63;
    int h = (idx >> 6) % H_;
    int bl = idx / D_;
    int b = bl / L_, l = bl % L_;
    dst[((size_t)(b * H_ + h) * L_ + l) * DH_ + d] =
        src[(size_t)bl * rowStride + colOff + h * DH_ + d];
}

// ---------------- attention: one thread = one query row, online softmax ------
__global__ __launch_bounds__(128, 1) void attn_kernel(const float* __restrict__ Q,
                                                      const float* __restrict__ K,
                                                      const float* __restrict__ V,
                                                      float* __restrict__ O) {
    __shared__ float ks[64 * 64];
    __shared__ float vs[64 * 64];
    int bh = blockIdx.y;
    int qi = blockIdx.x * 128 + threadIdx.x;

    const float* qp = Q + ((size_t)bh * L_ + qi) * DH_;
    float q[64];
    #pragma unroll
    for (int d = 0; d < 64; d++) q[d] = qp[d];

    float m = -1e30f, l = 0.f;
    float acc[64];
    #pragma unroll
    for (int d = 0; d < 64; d++) acc[d] = 0.f;

    const float* kb = K + (size_t)bh * L_ * DH_;
    const float* vb = V + (size_t)bh * L_ * DH_;

    for (int kt = 0; kt < L_; kt += 64) {
        __syncthreads();
        #pragma unroll
        for (int i = 0; i < 8; i++) {
            int idx = threadIdx.x + i * 128;   // 1024 float4 per tile
            ((float4*)ks)[idx] = ((const float4*)(kb + (size_t)kt * 64))[idx];
            ((float4*)vs)[idx] = ((const float4*)(vb + (size_t)kt * 64))[idx];
        }
        __syncthreads();

        #pragma unroll 1
        for (int j = 0; j < 64; j++) {
            const float4* kr = (const float4*)(ks + j * 64);
            float s0 = 0.f, s1 = 0.f;
            #pragma unroll
            for (int d4 = 0; d4 < 16; d4 += 2) {
                float4 ka = kr[d4], kbv = kr[d4 + 1];
                s0 += q[d4*4+0]*ka.x + q[d4*4+1]*ka.y + q[d4*4+2]*ka.z + q[d4*4+3]*ka.w;
                s1 += q[d4*4+4]*kbv.x + q[d4*4+5]*kbv.y + q[d4*4+6]*kbv.z + q[d4*4+7]*kbv.w;
            }
            float s = s0 + s1;
            if (s > m) {
                float corr = __expf(m - s);
                m = s; l *= corr;
                #pragma unroll
                for (int d = 0; d < 64; d++) acc[d] *= corr;
            }
            float p = __expf(s - m);
            l += p;
            const float4* vr = (const float4*)(vs + j * 64);
            #pragma unroll
            for (int d4 = 0; d4 < 16; d4++) {
                float4 vv = vr[d4];
                acc[d4*4+0] += p * vv.x; acc[d4*4+1] += p * vv.y;
                acc[d4*4+2] += p * vv.z; acc[d4*4+3] += p * vv.w;
            }
        }
    }

    float inv = 1.f / l;
    int b = bh / H_, h = bh % H_;
    float* op = O + ((size_t)(b * L_ + qi)) * D_ + h * DH_;
    #pragma unroll
    for (int d = 0; d < 64; d++) op[d] = acc[d] * inv;
}

// ---------------- a * silu(g) ----------------
__global__ void silu_mul(const float* __restrict__ u, float* __restrict__ ag) {
    int idx = blockIdx.x * 256 + threadIdx.x;
    if (idx >= M_ * DFF_) return;
    int r = idx / DFF_, j = idx - r * DFF_;
    float a = u[(size_t)r * UPN_ + j];
    float g = u[(size_t)r * UPN_ + j + DFF_];
    ag[idx] = a * (g / (1.f + __expf(-g)));
}

// ---------------- host launcher ----------------
extern "C" void kernel_launch(void* const* d_in, const int* in_sizes, int n_in,
                              void* d_out, int out_size) {
    const float* x        = (const float*)d_in[0];
    const float* pos      = (const float*)d_in[1];
    const float* x_cross  = (const float*)d_in[2];
    const float* pos_cross= (const float*)d_in[3];
    const float* sa_norm  = (const float*)d_in[4];
    const float* sa_wqkv  = (const float*)d_in[5];
    const float* sa_scale = (const float*)d_in[6];
    const float* sa_wout  = (const float*)d_in[7];
    const float* ca_norm  = (const float*)d_in[8];
    const float* ca_normc = (const float*)d_in[9];
    const float* ca_wq    = (const float*)d_in[10];
    const float* ca_wkv   = (const float*)d_in[11];
    const float* ca_scale = (const float*)d_in[12];
    const float* ca_wout  = (const float*)d_in[13];
    const float* ff_norm  = (const float*)d_in[14];
    const float* ff_wup   = (const float*)d_in[15];
    const float* ff_wdown = (const float*)d_in[16];
    float* out = (float*)d_out;

    float *norm, *normc, *big, *lin2, *q, *k, *v, *ao, *x1, *x2, *ag;
    cudaGetSymbolAddress((void**)&norm,  g_norm);
    cudaGetSymbolAddress((void**)&normc, g_normc);
    cudaGetSymbolAddress((void**)&big,   g_big);
    cudaGetSymbolAddress((void**)&lin2,  g_lin2);
    cudaGetSymbolAddress((void**)&q,     g_q);
    cudaGetSymbolAddress((void**)&k,     g_k);
    cudaGetSymbolAddress((void**)&v,     g_v);
    cudaGetSymbolAddress((void**)&ao,    g_ao);
    cudaGetSymbolAddress((void**)&x1,    g_x1);
    cudaGetSymbolAddress((void**)&x2,    g_x2);
    cudaGetSymbolAddress((void**)&ag,    g_ag);

    const int packBlocks = (B_ * L_ * H_ * 32 + 255) / 256;
    const int elemBlocks = (M_ * D_ + 255) / 256;

    // ---- self attention ----
    rmsnorm_kernel<<<M_, 256>>>(x, sa_norm, norm);
    gemm_nt<false><<<dim3(2304/128, M_/128), 256>>>(norm, sa_wqkv, nullptr, big, M_, 2304, D_);
    qk_transform<<<packBlocks, 256>>>(big, 2304, 0,    pos, sa_scale, q);
    qk_transform<<<packBlocks, 256>>>(big, 2304, 768,  pos, sa_scale, k);
    copy_v     <<<elemBlocks, 256>>>(big, 2304, 1536, v);
    attn_kernel<<<dim3(L_/128, B_*H_), 128>>>(q, k, v, ao);
    gemm_nt<true><<<dim3(D_/128, M_/128), 256>>>(ao, sa_wout, x, x1, M_, D_, D_);

    // ---- cross attention ----
    rmsnorm_kernel<<<M_, 256>>>(x1, ca_norm, norm);
    rmsnorm_kernel<<<M_, 256>>>(x_cross, ca_normc, normc);
    gemm_nt<false><<<dim3(D_/128, M_/128), 256>>>(norm,  ca_wq,  nullptr, lin2, M_, D_,   D_);
    gemm_nt<false><<<dim3(1536/128, M_/128), 256>>>(normc, ca_wkv, nullptr, big,  M_, 1536, D_);
    qk_transform<<<packBlocks, 256>>>(lin2, 768,  0,   pos,       ca_scale, q);
    qk_transform<<<packBlocks, 256>>>(big,  1536, 0,   pos_cross, ca_scale, k);
    copy_v     <<<elemBlocks, 256>>>(big,  1536, 768, v);
    attn_kernel<<<dim3(L_/128, B_*H_), 128>>>(q, k, v, ao);
    gemm_nt<true><<<dim3(D_/128, M_/128), 256>>>(ao, ca_wout, x1, x2, M_, D_, D_);

    // ---- feed forward ----
    rmsnorm_kernel<<<M_, 256>>>(x2, ff_norm, norm);
    gemm_nt<false><<<dim3(UPN_/128, M_/128), 256>>>(norm, ff_wup, nullptr, big, M_, UPN_, D_);
    silu_mul<<<(M_ * DFF_ + 255) / 256, 256>>>(big, ag);
    gemm_nt<true><<<dim3(D_/128, M_/128), 256>>>(ag, ff_wdown, x2, out, M_, D_, DFF_);
}

// round 2
// speedup vs baseline: 1.5343x; 1.5343x over previous
#include <cuda_runtime.h>
#include <cstdint>

#define B_ 2
#define L_ 2048
#define D_ 768
#define H_ 12
#define DH_ 64
#define M_ (B_*L_)        // 4096 rows
#define DFF_ 2304
#define UPN_ (2*DFF_)     // 4608

// ---------------- scratch (device globals; no allocs allowed) ----------------
__device__ float g_norm [M_*D_];
__device__ float g_normc[M_*D_];
__device__ float g_big  [M_*UPN_];    // qkv (4096x2304) / kv (4096x1536) / ff up (4096x4608)
__device__ float g_lin2 [M_*D_];      // ca q linear
__device__ float g_q    [B_*H_*L_*DH_];
__device__ float g_k    [B_*H_*L_*DH_];
__device__ float g_v    [B_*H_*L_*DH_];
__device__ float g_ao   [M_*D_];      // attention out, [B,L,D] layout
__device__ float g_x1   [M_*D_];
__device__ float g_x2   [M_*D_];
__device__ float g_ag   [M_*DFF_];

// ---------------- rmsnorm: one block per row of 768 ----------------
__global__ void rmsnorm_kernel(const float* __restrict__ x, const float* __restrict__ sc,
                               float* __restrict__ out) {
    int row = blockIdx.x;
    const float* xr = x + (size_t)row * D_;
    float s = 0.f;
    for (int i = threadIdx.x; i < D_; i += 256) { float v = xr[i]; s += v * v; }
    #pragma unroll
    for (int o = 16; o > 0; o >>= 1) s += __shfl_xor_sync(0xffffffffu, s, o);
    __shared__ float red[8];
    __shared__ float rtot;
    if ((threadIdx.x & 31) == 0) red[threadIdx.x >> 5] = s;
    __syncthreads();
    if (threadIdx.x == 0) {
        float t = 0.f;
        #pragma unroll
        for (int i = 0; i < 8; i++) t += red[i];
        rtot = rsqrtf(t / (float)D_ + 1e-6f);
    }
    __syncthreads();
    float r = rtot;
    for (int i = threadIdx.x; i < D_; i += 256)
        out[(size_t)row * D_ + i] = xr[i] * sc[i] * r;
}

// ---------------- tf32 tensor-core GEMM NT: C[M,N] = A[M,K] * B[N,K]^T (+R) ---
// BM=BN=128, BK=32, 256 threads (8 warps, 2x4 warp grid, 64x32 warp tile).
// Smem ld = 36 floats -> fragment LDS loads are bank-conflict free.
#define SLD 36
#define GSMEM_BYTES (4 * 128 * SLD * 4 * 2 / 2)   // 2 bufs * 2 tiles * 128*36*4 = 73728

__device__ __forceinline__ uint32_t f2tf(float x) {
    uint32_t r;
    asm("cvt.rna.tf32.f32 %0, %1;" : "=r"(r) : "f"(x));
    return r;
}

__device__ __forceinline__ void mma_tf32(float c[4], const uint32_t a[4], const uint32_t b[2]) {
    asm volatile("mma.sync.aligned.m16n8k8.row.col.f32.tf32.tf32.f32 "
                 "{%0,%1,%2,%3},{%4,%5,%6,%7},{%8,%9},{%0,%1,%2,%3};\n"
                 : "+f"(c[0]), "+f"(c[1]), "+f"(c[2]), "+f"(c[3])
                 : "r"(a[0]), "r"(a[1]), "r"(a[2]), "r"(a[3]), "r"(b[0]), "r"(b[1]));
}

template<bool RESID>
__global__ __launch_bounds__(256, 2) void gemm_tf32(const float* __restrict__ A,
                                                    const float* __restrict__ Bw,
                                                    const float* __restrict__ R,
                                                    float* __restrict__ C,
                                                    int M, int N, int K) {
    extern __shared__ float sm[];
    float* As = sm;                       // [2][128*SLD]
    float* Bs = sm + 2 * 128 * SLD;       // [2][128*SLD]

    const int tid = threadIdx.x;
    const int m0 = blockIdx.y * 128, n0 = blockIdx.x * 128;
    const int w = tid >> 5, lane = tid & 31;
    const int wm = w >> 2, wn = w & 3;            // 2 x 4
    const int g = lane >> 2, t4 = lane & 3;

    float acc[4][4][4];
    #pragma unroll
    for (int i = 0; i < 4; i++)
        #pragma unroll
        for (int j = 0; j < 4; j++)
            #pragma unroll
            for (int r = 0; r < 4; r++) acc[i][j][r] = 0.f;

    auto load_tiles = [&](int stage, int k0) {
        float* as = As + stage * 128 * SLD;
        float* bs = Bs + stage * 128 * SLD;
        #pragma unroll
        for (int i = 0; i < 4; i++) {
            int id = tid + i * 256;            // 0..1023
            int r = id >> 3, kc = (id & 7) * 4;
            uint32_t sa = (uint32_t)__cvta_generic_to_shared(as + r * SLD + kc);
            const float* ga = A + (size_t)(m0 + r) * K + k0 + kc;
            asm volatile("cp.async.cg.shared.global [%0], [%1], 16;\n" :: "r"(sa), "l"(ga));
            uint32_t sb = (uint32_t)__cvta_generic_to_shared(bs + r * SLD + kc);
            const float* gb = Bw + (size_t)(n0 + r) * K + k0 + kc;
            asm volatile("cp.async.cg.shared.global [%0], [%1], 16;\n" :: "r"(sb), "l"(gb));
        }
        asm volatile("cp.async.commit_group;\n");
    };

    const int numK = K >> 5;
    load_tiles(0, 0);

    for (int kt = 0; kt < numK; kt++) {
        if (kt + 1 < numK) {
            load_tiles((kt + 1) & 1, (kt + 1) * 32);
            asm volatile("cp.async.wait_group 1;\n");
        } else {
            asm volatile("cp.async.wait_group 0;\n");
        }
        __syncthreads();

        const float* as = As + (kt & 1) * 128 * SLD;
        const float* bs = Bs + (kt & 1) * 128 * SLD;
        #pragma unroll
        for (int kk = 0; kk < 4; kk++) {
            uint32_t af[4][4], bf[4][2];
            #pragma unroll
            for (int mi = 0; mi < 4; mi++) {
                int mr = wm * 64 + mi * 16 + g;
                int kc = kk * 8 + t4;
                af[mi][0] = f2tf(as[(mr    ) * SLD + kc    ]);
                af[mi][1] = f2tf(as[(mr + 8) * SLD + kc    ]);
                af[mi][2] = f2tf(as[(mr    ) * SLD + kc + 4]);
                af[mi][3] = f2tf(as[(mr + 8) * SLD + kc + 4]);
            }
            #pragma unroll
            for (int ni = 0; ni < 4; ni++) {
                int nr = wn * 32 + ni * 8 + g;
                int kc = kk * 8 + t4;
                bf[ni][0] = f2tf(bs[nr * SLD + kc    ]);
                bf[ni][1] = f2tf(bs[nr * SLD + kc + 4]);
            }
            #pragma unroll
            for (int mi = 0; mi < 4; mi++)
                #pragma unroll
                for (int ni = 0; ni < 4; ni++)
                    mma_tf32(acc[mi][ni], af[mi], bf[ni]);
        }
        __syncthreads();
    }

    // epilogue
    #pragma unroll
    for (int mi = 0; mi < 4; mi++) {
        int r0 = m0 + wm * 64 + mi * 16 + g;
        #pragma unroll
        for (int ni = 0; ni < 4; ni++) {
            int cc = n0 + wn * 32 + ni * 8 + 2 * t4;
            float2 v0 = make_float2(acc[mi][ni][0], acc[mi][ni][1]);
            float2 v1 = make_float2(acc[mi][ni][2], acc[mi][ni][3]);
            if (RESID) {
                float2 r0v = *(const float2*)(R + (size_t)r0 * N + cc);
                float2 r1v = *(const float2*)(R + (size_t)(r0 + 8) * N + cc);
                v0.x += r0v.x; v0.y += r0v.y;
                v1.x += r1v.x; v1.y += r1v.y;
            }
            *(float2*)(C + (size_t)r0 * N + cc) = v0;
            *(float2*)(C + (size_t)(r0 + 8) * N + cc) = v1;
        }
    }
}

// ---------------- cos_scale + RoPE pack: one warp per (b,l,h) ----------------
__device__ __forceinline__ float theta_of(int j, int h, float p0, float p1, float p2) {
    int i = j >> 3, f = j & 7;
    float pc = (i == 0) ? p0 : ((i == 1) ? p1 : p2);
    float freq = 3.14159265358979f * __expf((float)(f * 12 + h) * 0.02398526136f);
    return pc * freq;
}

__global__ void qk_transform(const float* __restrict__ src, int rowStride, int colOff,
                             const float* __restrict__ pos, const float* __restrict__ hscale,
                             float* __restrict__ dst) {
    int w = (blockIdx.x * blockDim.x + threadIdx.x) >> 5;
    int lane = threadIdx.x & 31;
    if (w >= B_ * L_ * H_) return;
    int h = w % H_;
    int bl = w / H_;
    int b = bl / L_, l = bl % L_;

    const float* sp = src + (size_t)bl * rowStride + colOff + h * DH_;
    float v0 = sp[lane], v1 = sp[lane + 32];
    float ss = v0 * v0 + v1 * v1;
    #pragma unroll
    for (int o = 16; o > 0; o >>= 1) ss += __shfl_xor_sync(0xffffffffu, ss, o);
    float f = sqrtf(hscale[h]) * rsqrtf(ss + 1e-6f);
    v0 *= f; v1 *= f;

    __shared__ float sh[8][64];
    int wl = threadIdx.x >> 5;
    sh[wl][lane] = v0; sh[wl][lane + 32] = v1;
    __syncwarp();

    float p0 = pos[(size_t)bl * 3 + 0];
    float p1 = pos[(size_t)bl * 3 + 1];
    float p2 = pos[(size_t)bl * 3 + 2];

    float out0, out1;
    {
        int d = lane;
        if (d < 24) {
            float th = theta_of(d, h, p0, p1, p2);
            float s, c; __sincosf(th, &s, &c);
            out0 = sh[wl][d] * c - sh[wl][d + 24] * s;
        } else {
            float th = theta_of(d - 24, h, p0, p1, p2);
            float s, c; __sincosf(th, &s, &c);
            out0 = sh[wl][d] * c + sh[wl][d - 24] * s;
        }
    }
    {
        int d = lane + 32;
        if (d < 48) {
            float th = theta_of(d - 24, h, p0, p1, p2);
            float s, c; __sincosf(th, &s, &c);
            out1 = sh[wl][d] * c + sh[wl][d - 24] * s;
        } else {
            out1 = sh[wl][d];
        }
    }
    float* dp = dst + ((size_t)(b * H_ + h) * L_ + l) * DH_;
    dp[lane] = out0; dp[lane + 32] = out1;
}

// ---------------- v copy (layout change only) ----------------
__global__ void copy_v(const float* __restrict__ src, int rowStride, int colOff,
                       float* __restrict__ dst) {
    int idx = blockIdx.x * 256 + threadIdx.x;
    if (idx >= M_ * D_) return;
    int d = idx & 63;
    int h = (idx >> 6) % H_;
    int bl = idx / D_;
    int b = bl / L_, l = bl % L_;
    dst[((size_t)(b * H_ + h) * L_ + l) * DH_ + d] =
        src[(size_t)bl * rowStride + colOff + h * DH_ + d];
}

// ---------------- attention: one thread = one query row, online softmax ------
__global__ __launch_bounds__(128, 1) void attn_kernel(const float* __restrict__ Q,
                                                      const float* __restrict__ K,
                                                      const float* __restrict__ V,
                                                      float* __restrict__ O) {
    __shared__ float ks[64 * 64];
    __shared__ float vs[64 * 64];
    int bh = blockIdx.y;
    int qi = blockIdx.x * 128 + threadIdx.x;

    const float* qp = Q + ((size_t)bh * L_ + qi) * DH_;
    float q[64];
    #pragma unroll
    for (int d = 0; d < 64; d++) q[d] = qp[d];

    float m = -1e30f, l = 0.f;
    float acc[64];
    #pragma unroll
    for (int d = 0; d < 64; d++) acc[d] = 0.f;

    const float* kb = K + (size_t)bh * L_ * DH_;
    const float* vb = V + (size_t)bh * L_ * DH_;

    for (int kt = 0; kt < L_; kt += 64) {
        __syncthreads();
        #pragma unroll
        for (int i = 0; i < 8; i++) {
            int idx = threadIdx.x + i * 128;
            ((float4*)ks)[idx] = ((const float4*)(kb + (size_t)kt * 64))[idx];
            ((float4*)vs)[idx] = ((const float4*)(vb + (size_t)kt * 64))[idx];
        }
        __syncthreads();

        #pragma unroll 1
        for (int j = 0; j < 64; j++) {
            const float4* kr = (const float4*)(ks + j * 64);
            float s0 = 0.f, s1 = 0.f;
            #pragma unroll
            for (int d4 = 0; d4 < 16; d4 += 2) {
                float4 ka = kr[d4], kbv = kr[d4 + 1];
                s0 += q[d4*4+0]*ka.x + q[d4*4+1]*ka.y + q[d4*4+2]*ka.z + q[d4*4+3]*ka.w;
                s1 += q[d4*4+4]*kbv.x + q[d4*4+5]*kbv.y + q[d4*4+6]*kbv.z + q[d4*4+7]*kbv.w;
            }
            float s = s0 + s1;
            if (s > m) {
                float corr = __expf(m - s);
                m = s; l *= corr;
                #pragma unroll
                for (int d = 0; d < 64; d++) acc[d] *= corr;
            }
            float p = __expf(s - m);
            l += p;
            const float4* vr = (const float4*)(vs + j * 64);
            #pragma unroll
            for (int d4 = 0; d4 < 16; d4++) {
                float4 vv = vr[d4];
                acc[d4*4+0] += p * vv.x; acc[d4*4+1] += p * vv.y;
                acc[d4*4+2] += p * vv.z; acc[d4*4+3] += p * vv.w;
            }
        }
    }

    float inv = 1.f / l;
    int b = bh / H_, h = bh % H_;
    float* op = O + ((size_t)(b * L_ + qi)) * D_ + h * DH_;
    #pragma unroll
    for (int d = 0; d < 64; d++) op[d] = acc[d] * inv;
}

// ---------------- a * silu(g) ----------------
__global__ void silu_mul(const float* __restrict__ u, float* __restrict__ ag) {
    int idx = blockIdx.x * 256 + threadIdx.x;
    if (idx >= M_ * DFF_) return;
    int r = idx / DFF_, j = idx - r * DFF_;
    float a = u[(size_t)r * UPN_ + j];
    float g = u[(size_t)r * UPN_ + j + DFF_];
    ag[idx] = a * (g / (1.f + __expf(-g)));
}

// ---------------- host launcher ----------------
extern "C" void kernel_launch(void* const* d_in, const int* in_sizes, int n_in,
                              void* d_out, int out_size) {
    const float* x        = (const float*)d_in[0];
    const float* pos      = (const float*)d_in[1];
    const float* x_cross  = (const float*)d_in[2];
    const float* pos_cross= (const float*)d_in[3];
    const float* sa_norm  = (const float*)d_in[4];
    const float* sa_wqkv  = (const float*)d_in[5];
    const float* sa_scale = (const float*)d_in[6];
    const float* sa_wout  = (const float*)d_in[7];
    const float* ca_norm  = (const float*)d_in[8];
    const float* ca_normc = (const float*)d_in[9];
    const float* ca_wq    = (const float*)d_in[10];
    const float* ca_wkv   = (const float*)d_in[11];
    const float* ca_scale = (const float*)d_in[12];
    const float* ca_wout  = (const float*)d_in[13];
    const float* ff_norm  = (const float*)d_in[14];
    const float* ff_wup   = (const float*)d_in[15];
    const float* ff_wdown = (const float*)d_in[16];
    float* out = (float*)d_out;

    float *norm, *normc, *big, *lin2, *q, *k, *v, *ao, *x1, *x2, *ag;
    cudaGetSymbolAddress((void**)&norm,  g_norm);
    cudaGetSymbolAddress((void**)&normc, g_normc);
    cudaGetSymbolAddress((void**)&big,   g_big);
    cudaGetSymbolAddress((void**)&lin2,  g_lin2);
    cudaGetSymbolAddress((void**)&q,     g_q);
    cudaGetSymbolAddress((void**)&k,     g_k);
    cudaGetSymbolAddress((void**)&v,     g_v);
    cudaGetSymbolAddress((void**)&ao,    g_ao);
    cudaGetSymbolAddress((void**)&x1,    g_x1);
    cudaGetSymbolAddress((void**)&x2,    g_x2);
    cudaGetSymbolAddress((void**)&ag,    g_ag);

    static bool attr_done = false;
    if (!attr_done) {
        cudaFuncSetAttribute(gemm_tf32<false>, cudaFuncAttributeMaxDynamicSharedMemorySize, GSMEM_BYTES);
        cudaFuncSetAttribute(gemm_tf32<true>,  cudaFuncAttributeMaxDynamicSharedMemorySize, GSMEM_BYTES);
        attr_done = true;
    }

    const int packBlocks = (B_ * L_ * H_ * 32 + 255) / 256;
    const int elemBlocks = (M_ * D_ + 255) / 256;

    // ---- self attention ----
    rmsnorm_kernel<<<M_, 256>>>(x, sa_norm, norm);
    gemm_tf32<false><<<dim3(2304/128, M_/128), 256, GSMEM_BYTES>>>(norm, sa_wqkv, nullptr, big, M_, 2304, D_);
    qk_transform<<<packBlocks, 256>>>(big, 2304, 0,    pos, sa_scale, q);
    qk_transform<<<packBlocks, 256>>>(big, 2304, 768,  pos, sa_scale, k);
    copy_v     <<<elemBlocks, 256>>>(big, 2304, 1536, v);
    attn_kernel<<<dim3(L_/128, B_*H_), 128>>>(q, k, v, ao);
    gemm_tf32<true><<<dim3(D_/128, M_/128), 256, GSMEM_BYTES>>>(ao, sa_wout, x, x1, M_, D_, D_);

    // ---- cross attention ----
    rmsnorm_kernel<<<M_, 256>>>(x1, ca_norm, norm);
    rmsnorm_kernel<<<M_, 256>>>(x_cross, ca_normc, normc);
    gemm_tf32<false><<<dim3(D_/128, M_/128), 256, GSMEM_BYTES>>>(norm,  ca_wq,  nullptr, lin2, M_, D_,   D_);
    gemm_tf32<false><<<dim3(1536/128, M_/128), 256, GSMEM_BYTES>>>(normc, ca_wkv, nullptr, big,  M_, 1536, D_);
    qk_transform<<<packBlocks, 256>>>(lin2, 768,  0,   pos,       ca_scale, q);
    qk_transform<<<packBlocks, 256>>>(big,  1536, 0,   pos_cross, ca_scale, k);
    copy_v     <<<elemBlocks, 256>>>(big,  1536, 768, v);
    attn_kernel<<<dim3(L_/128, B_*H_), 128>>>(q, k, v, ao);
    gemm_tf32<true><<<dim3(D_/128, M_/128), 256, GSMEM_BYTES>>>(ao, ca_wout, x1, x2, M_, D_, D_);

    // ---- feed forward ----
    rmsnorm_kernel<<<M_, 256>>>(x2, ff_norm, norm);
    gemm_tf32<false><<<dim3(UPN_/128, M_/128), 256, GSMEM_BYTES>>>(norm, ff_wup, nullptr, big, M_, UPN_, D_);
    silu_mul<<<(M_ * DFF_ + 255) / 256, 256>>>(big, ag);
    gemm_tf32<true><<<dim3(D_/128, M_/128), 256, GSMEM_BYTES>>>(ag, ff_wdown, x2, out, M_, D_, DFF_);
}

// round 3
// speedup vs baseline: 3.4403x; 2.2422x over previous
#include <cuda_runtime.h>
#include <cstdint>

#define B_ 2
#define L_ 2048
#define D_ 768
#define H_ 12
#define DH_ 64
#define M_ (B_*L_)        // 4096 rows
#define DFF_ 2304
#define UPN_ (2*DFF_)     // 4608

// ---------------- scratch (device globals; no allocs allowed) ----------------
__device__ float g_norm [M_*D_];
__device__ float g_normc[M_*D_];
__device__ float g_big  [M_*UPN_];
__device__ float g_lin2 [M_*D_];
__device__ float g_q    [B_*H_*L_*DH_];
__device__ float g_k    [B_*H_*L_*DH_];
__device__ float g_v    [B_*H_*L_*DH_];
__device__ float g_ao   [M_*D_];
__device__ float g_x1   [M_*D_];
__device__ float g_x2   [M_*D_];
__device__ float g_ag   [M_*DFF_];

// ---------------- mma helpers ----------------
__device__ __forceinline__ uint32_t f2tf(float x) {
    uint32_t r;
    asm("cvt.rna.tf32.f32 %0, %1;" : "=r"(r) : "f"(x));
    return r;
}
__device__ __forceinline__ void mma_tf32(float c[4], const uint32_t a[4], const uint32_t b[2]) {
    asm volatile("mma.sync.aligned.m16n8k8.row.col.f32.tf32.tf32.f32 "
                 "{%0,%1,%2,%3},{%4,%5,%6,%7},{%8,%9},{%0,%1,%2,%3};\n"
                 : "+f"(c[0]), "+f"(c[1]), "+f"(c[2]), "+f"(c[3])
                 : "r"(a[0]), "r"(a[1]), "r"(a[2]), "r"(a[3]), "r"(b[0]), "r"(b[1]));
}

// ---------------- rmsnorm ----------------
__global__ void rmsnorm_kernel(const float* __restrict__ x, const float* __restrict__ sc,
                               float* __restrict__ out) {
    int row = blockIdx.x;
    const float* xr = x + (size_t)row * D_;
    float s = 0.f;
    for (int i = threadIdx.x; i < D_; i += 256) { float v = xr[i]; s += v * v; }
    #pragma unroll
    for (int o = 16; o > 0; o >>= 1) s += __shfl_xor_sync(0xffffffffu, s, o);
    __shared__ float red[8];
    __shared__ float rtot;
    if ((threadIdx.x & 31) == 0) red[threadIdx.x >> 5] = s;
    __syncthreads();
    if (threadIdx.x == 0) {
        float t = 0.f;
        #pragma unroll
        for (int i = 0; i < 8; i++) t += red[i];
        rtot = rsqrtf(t / (float)D_ + 1e-6f);
    }
    __syncthreads();
    float r = rtot;
    for (int i = threadIdx.x; i < D_; i += 256)
        out[(size_t)row * D_ + i] = xr[i] * sc[i] * r;
}

// ---------------- tf32 GEMM NT (unchanged from round 2) ----------------
#define SLD 36
#define GSMEM_BYTES (4 * 128 * SLD * 4 * 2 / 2)

template<bool RESID>
__global__ __launch_bounds__(256, 2) void gemm_tf32(const float* __restrict__ A,
                                                    const float* __restrict__ Bw,
                                                    const float* __restrict__ R,
                                                    float* __restrict__ C,
                                                    int M, int N, int K) {
    extern __shared__ float sm[];
    float* As = sm;
    float* Bs = sm + 2 * 128 * SLD;

    const int tid = threadIdx.x;
    const int m0 = blockIdx.y * 128, n0 = blockIdx.x * 128;
    const int w = tid >> 5, lane = tid & 31;
    const int wm = w >> 2, wn = w & 3;
    const int g = lane >> 2, t4 = lane & 3;

    float acc[4][4][4];
    #pragma unroll
    for (int i = 0; i < 4; i++)
        #pragma unroll
        for (int j = 0; j < 4; j++)
            #pragma unroll
            for (int r = 0; r < 4; r++) acc[i][j][r] = 0.f;

    auto load_tiles = [&](int stage, int k0) {
        float* as = As + stage * 128 * SLD;
        float* bs = Bs + stage * 128 * SLD;
        #pragma unroll
        for (int i = 0; i < 4; i++) {
            int id = tid + i * 256;
            int r = id >> 3, kc = (id & 7) * 4;
            uint32_t sa = (uint32_t)__cvta_generic_to_shared(as + r * SLD + kc);
            const float* ga = A + (size_t)(m0 + r) * K + k0 + kc;
            asm volatile("cp.async.cg.shared.global [%0], [%1], 16;\n" :: "r"(sa), "l"(ga));
            uint32_t sb = (uint32_t)__cvta_generic_to_shared(bs + r * SLD + kc);
            const float* gb = Bw + (size_t)(n0 + r) * K + k0 + kc;
            asm volatile("cp.async.cg.shared.global [%0], [%1], 16;\n" :: "r"(sb), "l"(gb));
        }
        asm volatile("cp.async.commit_group;\n");
    };

    const int numK = K >> 5;
    load_tiles(0, 0);

    for (int kt = 0; kt < numK; kt++) {
        if (kt + 1 < numK) {
            load_tiles((kt + 1) & 1, (kt + 1) * 32);
            asm volatile("cp.async.wait_group 1;\n");
        } else {
            asm volatile("cp.async.wait_group 0;\n");
        }
        __syncthreads();

        const float* as = As + (kt & 1) * 128 * SLD;
        const float* bs = Bs + (kt & 1) * 128 * SLD;
        #pragma unroll
        for (int kk = 0; kk < 4; kk++) {
            uint32_t af[4][4], bf[4][2];
            #pragma unroll
            for (int mi = 0; mi < 4; mi++) {
                int mr = wm * 64 + mi * 16 + g;
                int kc = kk * 8 + t4;
                af[mi][0] = f2tf(as[(mr    ) * SLD + kc    ]);
                af[mi][1] = f2tf(as[(mr + 8) * SLD + kc    ]);
                af[mi][2] = f2tf(as[(mr    ) * SLD + kc + 4]);
                af[mi][3] = f2tf(as[(mr + 8) * SLD + kc + 4]);
            }
            #pragma unroll
            for (int ni = 0; ni < 4; ni++) {
                int nr = wn * 32 + ni * 8 + g;
                int kc = kk * 8 + t4;
                bf[ni][0] = f2tf(bs[nr * SLD + kc    ]);
                bf[ni][1] = f2tf(bs[nr * SLD + kc + 4]);
            }
            #pragma unroll
            for (int mi = 0; mi < 4; mi++)
                #pragma unroll
                for (int ni = 0; ni < 4; ni++)
                    mma_tf32(acc[mi][ni], af[mi], bf[ni]);
        }
        __syncthreads();
    }

    #pragma unroll
    for (int mi = 0; mi < 4; mi++) {
        int r0 = m0 + wm * 64 + mi * 16 + g;
        #pragma unroll
        for (int ni = 0; ni < 4; ni++) {
            int cc = n0 + wn * 32 + ni * 8 + 2 * t4;
            float2 v0 = make_float2(acc[mi][ni][0], acc[mi][ni][1]);
            float2 v1 = make_float2(acc[mi][ni][2], acc[mi][ni][3]);
            if (RESID) {
                float2 r0v = *(const float2*)(R + (size_t)r0 * N + cc);
                float2 r1v = *(const float2*)(R + (size_t)(r0 + 8) * N + cc);
                v0.x += r0v.x; v0.y += r0v.y;
                v1.x += r1v.x; v1.y += r1v.y;
            }
            *(float2*)(C + (size_t)r0 * N + cc) = v0;
            *(float2*)(C + (size_t)(r0 + 8) * N + cc) = v1;
        }
    }
}

// ---------------- cos_scale + RoPE pack ----------------
__device__ __forceinline__ float theta_of(int j, int h, float p0, float p1, float p2) {
    int i = j >> 3, f = j & 7;
    float pc = (i == 0) ? p0 : ((i == 1) ? p1 : p2);
    float freq = 3.14159265358979f * __expf((float)(f * 12 + h) * 0.02398526136f);
    return pc * freq;
}

__global__ void qk_transform(const float* __restrict__ src, int rowStride, int colOff,
                             const float* __restrict__ pos, const float* __restrict__ hscale,
                             float* __restrict__ dst) {
    int w = (blockIdx.x * blockDim.x + threadIdx.x) >> 5;
    int lane = threadIdx.x & 31;
    if (w >= B_ * L_ * H_) return;
    int h = w % H_;
    int bl = w / H_;
    int b = bl / L_, l = bl % L_;

    const float* sp = src + (size_t)bl * rowStride + colOff + h * DH_;
    float v0 = sp[lane], v1 = sp[lane + 32];
    float ss = v0 * v0 + v1 * v1;
    #pragma unroll
    for (int o = 16; o > 0; o >>= 1) ss += __shfl_xor_sync(0xffffffffu, ss, o);
    float f = sqrtf(hscale[h]) * rsqrtf(ss + 1e-6f);
    v0 *= f; v1 *= f;

    __shared__ float sh[8][64];
    int wl = threadIdx.x >> 5;
    sh[wl][lane] = v0; sh[wl][lane + 32] = v1;
    __syncwarp();

    float p0 = pos[(size_t)bl * 3 + 0];
    float p1 = pos[(size_t)bl * 3 + 1];
    float p2 = pos[(size_t)bl * 3 + 2];

    float out0, out1;
    {
        int d = lane;
        if (d < 24) {
            float th = theta_of(d, h, p0, p1, p2);
            float s, c; __sincosf(th, &s, &c);
            out0 = sh[wl][d] * c - sh[wl][d + 24] * s;
        } else {
            float th = theta_of(d - 24, h, p0, p1, p2);
            float s, c; __sincosf(th, &s, &c);
            out0 = sh[wl][d] * c + sh[wl][d - 24] * s;
        }
    }
    {
        int d = lane + 32;
        if (d < 48) {
            float th = theta_of(d - 24, h, p0, p1, p2);
            float s, c; __sincosf(th, &s, &c);
            out1 = sh[wl][d] * c + sh[wl][d - 24] * s;
        } else {
            out1 = sh[wl][d];
        }
    }
    float* dp = dst + ((size_t)(b * H_ + h) * L_ + l) * DH_;
    dp[lane] = out0; dp[lane + 32] = out1;
}

// ---------------- v copy ----------------
__global__ void copy_v(const float* __restrict__ src, int rowStride, int colOff,
                       float* __restrict__ dst) {
    int idx = blockIdx.x * 256 + threadIdx.x;
    if (idx >= M_ * D_) return;
    int d = idx & 63;
    int h = (idx >> 6) % H_;
    int bl = idx / D_;
    int b = bl / L_, l = bl % L_;
    dst[((size_t)(b * H_ + h) * L_ + l) * DH_ + d] =
        src[(size_t)bl * rowStride + colOff + h * DH_ + d];
}

// ---------------- tensor-core flash attention (tf32) ----------------
// Block: 128 thr (4 warps), 64 q rows, key tiles of 64. grid=(L/64, B*H).
// Smem: Ks[64][68] (ld%32==4 -> conflict-free B/A frag reads),
//       Vs[64][72] (ld%32==8 -> conflict-free PV B-frag reads),
//       Ps[4][16][68] per-warp P staging.
#define KLD 68
#define VLD 72
#define ATT_SMEM ((64*KLD + 64*VLD + 4*16*KLD) * 4)   // 53248 B

__global__ __launch_bounds__(128) void attn_tc(const float* __restrict__ Q,
                                               const float* __restrict__ K,
                                               const float* __restrict__ V,
                                               float* __restrict__ O) {
    extern __shared__ float sm[];
    float* Ks = sm;                         // [64][KLD]
    float* Vs = sm + 64 * KLD;              // [64][VLD]
    float* Ps = sm + 64 * KLD + 64 * VLD;   // [4][16][KLD]

    const int bh = blockIdx.y;
    const int q0 = blockIdx.x * 64;
    const int tid = threadIdx.x;
    const int w = tid >> 5, lane = tid & 31;
    const int g = lane >> 2, t4 = lane & 3;

    // ---- stage Q tile through Ks, build per-warp A fragments ----
    const float* qb = Q + ((size_t)bh * L_ + q0) * DH_;
    #pragma unroll
    for (int i = 0; i < 8; i++) {
        int idx = tid + i * 128;            // 1024 float4
        int r = idx >> 4, c4 = (idx & 15) * 4;
        *(float4*)(Ks + r * KLD + c4) = *(const float4*)(qb + r * 64 + c4);
    }
    __syncthreads();
    uint32_t qf[8][4];
    {
        int r0 = w * 16 + g;
        #pragma unroll
        for (int kb = 0; kb < 8; kb++) {
            int kc = kb * 8 + t4;
            qf[kb][0] = f2tf(Ks[(r0    ) * KLD + kc    ]);
            qf[kb][1] = f2tf(Ks[(r0 + 8) * KLD + kc    ]);
            qf[kb][2] = f2tf(Ks[(r0    ) * KLD + kc + 4]);
            qf[kb][3] = f2tf(Ks[(r0 + 8) * KLD + kc + 4]);
        }
    }
    __syncthreads();

    float ob[8][4];
    #pragma unroll
    for (int n = 0; n < 8; n++)
        #pragma unroll
        for (int r = 0; r < 4; r++) ob[n][r] = 0.f;
    float m0 = -1e30f, m1 = -1e30f, l0 = 0.f, l1 = 0.f;

    const float* kbase = K + (size_t)bh * L_ * DH_;
    const float* vbase = V + (size_t)bh * L_ * DH_;
    float* pw = Ps + w * 16 * KLD;

    for (int kt = 0; kt < L_; kt += 64) {
        // load K and V tiles
        #pragma unroll
        for (int i = 0; i < 8; i++) {
            int idx = tid + i * 128;
            int r = idx >> 4, c4 = (idx & 15) * 4;
            *(float4*)(Ks + r * KLD + c4) = *(const float4*)(kbase + (size_t)(kt + r) * 64 + c4);
            *(float4*)(Vs + r * VLD + c4) = *(const float4*)(vbase + (size_t)(kt + r) * 64 + c4);
        }
        __syncthreads();

        // S = Q @ K^T   (16x64 per warp)
        float sc[8][4];
        #pragma unroll
        for (int n = 0; n < 8; n++)
            #pragma unroll
            for (int r = 0; r < 4; r++) sc[n][r] = 0.f;
        #pragma unroll
        for (int kb = 0; kb < 8; kb++) {
            int kc = kb * 8 + t4;
            #pragma unroll
            for (int n = 0; n < 8; n++) {
                uint32_t bf[2];
                bf[0] = f2tf(Ks[(n * 8 + g) * KLD + kc    ]);
                bf[1] = f2tf(Ks[(n * 8 + g) * KLD + kc + 4]);
                mma_tf32(sc[n], qf[kb], bf);
            }
        }

        // online softmax
        float rm0 = -1e30f, rm1 = -1e30f;
        #pragma unroll
        for (int n = 0; n < 8; n++) {
            rm0 = fmaxf(rm0, fmaxf(sc[n][0], sc[n][1]));
            rm1 = fmaxf(rm1, fmaxf(sc[n][2], sc[n][3]));
        }
        rm0 = fmaxf(rm0, __shfl_xor_sync(0xffffffffu, rm0, 1));
        rm0 = fmaxf(rm0, __shfl_xor_sync(0xffffffffu, rm0, 2));
        rm1 = fmaxf(rm1, __shfl_xor_sync(0xffffffffu, rm1, 1));
        rm1 = fmaxf(rm1, __shfl_xor_sync(0xffffffffu, rm1, 2));
        float nm0 = fmaxf(m0, rm0), nm1 = fmaxf(m1, rm1);
        float c0 = __expf(m0 - nm0), c1 = __expf(m1 - nm1);
        m0 = nm0; m1 = nm1;

        float ps0 = 0.f, ps1 = 0.f;
        #pragma unroll
        for (int n = 0; n < 8; n++) {
            sc[n][0] = __expf(sc[n][0] - nm0);
            sc[n][1] = __expf(sc[n][1] - nm0);
            sc[n][2] = __expf(sc[n][2] - nm1);
            sc[n][3] = __expf(sc[n][3] - nm1);
            ps0 += sc[n][0] + sc[n][1];
            ps1 += sc[n][2] + sc[n][3];
        }
        l0 = l0 * c0 + ps0;
        l1 = l1 * c1 + ps1;
        #pragma unroll
        for (int n = 0; n < 8; n++) {
            ob[n][0] *= c0; ob[n][1] *= c0;
            ob[n][2] *= c1; ob[n][3] *= c1;
        }

        // stage P to smem (per-warp), reload as A fragments
        #pragma unroll
        for (int n = 0; n < 8; n++) {
            *(float2*)(pw + (g    ) * KLD + n * 8 + 2 * t4) = make_float2(sc[n][0], sc[n][1]);
            *(float2*)(pw + (g + 8) * KLD + n * 8 + 2 * t4) = make_float2(sc[n][2], sc[n][3]);
        }
        __syncwarp();

        // O += P @ V
        #pragma unroll
        for (int kb = 0; kb < 8; kb++) {
            int kc = kb * 8 + t4;
            uint32_t af[4];
            af[0] = f2tf(pw[(g    ) * KLD + kc    ]);
            af[1] = f2tf(pw[(g + 8) * KLD + kc    ]);
            af[2] = f2tf(pw[(g    ) * KLD + kc + 4]);
            af[3] = f2tf(pw[(g + 8) * KLD + kc + 4]);
            #pragma unroll
            for (int n = 0; n < 8; n++) {
                uint32_t bf[2];
                bf[0] = f2tf(Vs[(kc    ) * VLD + n * 8 + g]);
                bf[1] = f2tf(Vs[(kc + 4) * VLD + n * 8 + g]);
                mma_tf32(ob[n], af, bf);
            }
        }
        __syncthreads();
    }

    // final normalize + write (O layout [B,L,D])
    l0 += __shfl_xor_sync(0xffffffffu, l0, 1);
    l0 += __shfl_xor_sync(0xffffffffu, l0, 2);
    l1 += __shfl_xor_sync(0xffffffffu, l1, 1);
    l1 += __shfl_xor_sync(0xffffffffu, l1, 2);
    float inv0 = 1.f / l0, inv1 = 1.f / l1;

    int b = bh / H_, h = bh % H_;
    int r0 = q0 + w * 16 + g;
    float* o0 = O + ((size_t)(b * L_ + r0)) * D_ + h * DH_;
    float* o1 = O + ((size_t)(b * L_ + r0 + 8)) * D_ + h * DH_;
    #pragma unroll
    for (int n = 0; n < 8; n++) {
        *(float2*)(o0 + n * 8 + 2 * t4) = make_float2(ob[n][0] * inv0, ob[n][1] * inv0);
        *(float2*)(o1 + n * 8 + 2 * t4) = make_float2(ob[n][2] * inv1, ob[n][3] * inv1);
    }
}

// ---------------- a * silu(g) ----------------
__global__ void silu_mul(const float* __restrict__ u, float* __restrict__ ag) {
    int idx = blockIdx.x * 256 + threadIdx.x;
    if (idx >= M_ * DFF_) return;
    int r = idx / DFF_, j = idx - r * DFF_;
    float a = u[(size_t)r * UPN_ + j];
    float g = u[(size_t)r * UPN_ + j + DFF_];
    ag[idx] = a * (g / (1.f + __expf(-g)));
}

// ---------------- host launcher ----------------
extern "C" void kernel_launch(void* const* d_in, const int* in_sizes, int n_in,
                              void* d_out, int out_size) {
    const float* x        = (const float*)d_in[0];
    const float* pos      = (const float*)d_in[1];
    const float* x_cross  = (const float*)d_in[2];
    const float* pos_cross= (const float*)d_in[3];
    const float* sa_norm  = (const float*)d_in[4];
    const float* sa_wqkv  = (const float*)d_in[5];
    const float* sa_scale = (const float*)d_in[6];
    const float* sa_wout  = (const float*)d_in[7];
    const float* ca_norm  = (const float*)d_in[8];
    const float* ca_normc = (const float*)d_in[9];
    const float* ca_wq    = (const float*)d_in[10];
    const float* ca_wkv   = (const float*)d_in[11];
    const float* ca_scale = (const float*)d_in[12];
    const float* ca_wout  = (const float*)d_in[13];
    const float* ff_norm  = (const float*)d_in[14];
    const float* ff_wup   = (const float*)d_in[15];
    const float* ff_wdown = (const float*)d_in[16];
    float* out = (float*)d_out;

    float *norm, *normc, *big, *lin2, *q, *k, *v, *ao, *x1, *x2, *ag;
    cudaGetSymbolAddress((void**)&norm,  g_norm);
    cudaGetSymbolAddress((void**)&normc, g_normc);
    cudaGetSymbolAddress((void**)&big,   g_big);
    cudaGetSymbolAddress((void**)&lin2,  g_lin2);
    cudaGetSymbolAddress((void**)&q,     g_q);
    cudaGetSymbolAddress((void**)&k,     g_k);
    cudaGetSymbolAddress((void**)&v,     g_v);
    cudaGetSymbolAddress((void**)&ao,    g_ao);
    cudaGetSymbolAddress((void**)&x1,    g_x1);
    cudaGetSymbolAddress((void**)&x2,    g_x2);
    cudaGetSymbolAddress((void**)&ag,    g_ag);

    static bool attr_done = false;
    if (!attr_done) {
        cudaFuncSetAttribute(gemm_tf32<false>, cudaFuncAttributeMaxDynamicSharedMemorySize, GSMEM_BYTES);
        cudaFuncSetAttribute(gemm_tf32<true>,  cudaFuncAttributeMaxDynamicSharedMemorySize, GSMEM_BYTES);
        cudaFuncSetAttribute(attn_tc, cudaFuncAttributeMaxDynamicSharedMemorySize, ATT_SMEM);
        attr_done = true;
    }

    const int packBlocks = (B_ * L_ * H_ * 32 + 255) / 256;
    const int elemBlocks = (M_ * D_ + 255) / 256;

    // ---- self attention ----
    rmsnorm_kernel<<<M_, 256>>>(x, sa_norm, norm);
    gemm_tf32<false><<<dim3(2304/128, M_/128), 256, GSMEM_BYTES>>>(norm, sa_wqkv, nullptr, big, M_, 2304, D_);
    qk_transform<<<packBlocks, 256>>>(big, 2304, 0,    pos, sa_scale, q);
    qk_transform<<<packBlocks, 256>>>(big, 2304, 768,  pos, sa_scale, k);
    copy_v     <<<elemBlocks, 256>>>(big, 2304, 1536, v);
    attn_tc<<<dim3(L_/64, B_*H_), 128, ATT_SMEM>>>(q, k, v, ao);
    gemm_tf32<true><<<dim3(D_/128, M_/128), 256, GSMEM_BYTES>>>(ao, sa_wout, x, x1, M_, D_, D_);

    // ---- cross attention ----
    rmsnorm_kernel<<<M_, 256>>>(x1, ca_norm, norm);
    rmsnorm_kernel<<<M_, 256>>>(x_cross, ca_normc, normc);
    gemm_tf32<false><<<dim3(D_/128, M_/128), 256, GSMEM_BYTES>>>(norm,  ca_wq,  nullptr, lin2, M_, D_,   D_);
    gemm_tf32<false><<<dim3(1536/128, M_/128), 256, GSMEM_BYTES>>>(normc, ca_wkv, nullptr, big,  M_, 1536, D_);
    qk_transform<<<packBlocks, 256>>>(lin2, 768,  0,   pos,       ca_scale, q);
    qk_transform<<<packBlocks, 256>>>(big,  1536, 0,   pos_cross, ca_scale, k);
    copy_v     <<<elemBlocks, 256>>>(big,  1536, 768, v);
    attn_tc<<<dim3(L_/64, B_*H_), 128, ATT_SMEM>>>(q, k, v, ao);
    gemm_tf32<true><<<dim3(D_/128, M_/128), 256, GSMEM_BYTES>>>(ao, ca_wout, x1, x2, M_, D_, D_);

    // ---- feed forward ----
    rmsnorm_kernel<<<M_, 256>>>(x2, ff_norm, norm);
    gemm_tf32<false><<<dim3(UPN_/128, M_/128), 256, GSMEM_BYTES>>>(norm, ff_wup, nullptr, big, M_, UPN_, D_);
    silu_mul<<<(M_ * DFF_ + 255) / 256, 256>>>(big, ag);
    gemm_tf32<true><<<dim3(D_/128, M_/128), 256, GSMEM_BYTES>>>(ag, ff_wdown, x2, out, M_, D_, DFF_);
}

// round 4
// speedup vs baseline: 4.4055x; 1.2806x over previous
#include <cuda_runtime.h>
#include <cuda_bf16.h>
#include <cstdint>

#define B_ 2
#define L_ 2048
#define D_ 768
#define H_ 12
#define DH_ 64
#define M_ (B_*L_)        // 4096 rows
#define DFF_ 2304
#define UPN_ (2*DFF_)     // 4608

// ---------------- scratch (device globals; no allocs allowed) ----------------
__device__ float g_big  [M_*UPN_];
__device__ float g_lin2 [M_*D_];
__device__ float g_q    [B_*H_*L_*DH_];
__device__ float g_k    [B_*H_*L_*DH_];
__device__ float g_v    [B_*H_*L_*DH_];
__device__ float g_x1   [M_*D_];
__device__ float g_x2   [M_*D_];

__device__ __nv_bfloat16 g_norm_bf [M_*D_];
__device__ __nv_bfloat16 g_normc_bf[M_*D_];
__device__ __nv_bfloat16 g_ao_bf   [M_*D_];
__device__ __nv_bfloat16 g_ag_bf   [M_*DFF_];

__device__ __nv_bfloat16 g_wqkv_bf [2304*768];
__device__ __nv_bfloat16 g_wout1_bf[768*768];
__device__ __nv_bfloat16 g_wq_bf   [768*768];
__device__ __nv_bfloat16 g_wkv_bf  [1536*768];
__device__ __nv_bfloat16 g_wout2_bf[768*768];
__device__ __nv_bfloat16 g_wup_bf  [4608*768];
__device__ __nv_bfloat16 g_wdown_bf[768*2304];

// ---------------- mma helpers ----------------
__device__ __forceinline__ uint32_t f2tf(float x) {
    uint32_t r;
    asm("cvt.rna.tf32.f32 %0, %1;" : "=r"(r) : "f"(x));
    return r;
}
__device__ __forceinline__ void mma_tf32(float c[4], const uint32_t a[4], const uint32_t b[2]) {
    asm volatile("mma.sync.aligned.m16n8k8.row.col.f32.tf32.tf32.f32 "
                 "{%0,%1,%2,%3},{%4,%5,%6,%7},{%8,%9},{%0,%1,%2,%3};\n"
                 : "+f"(c[0]), "+f"(c[1]), "+f"(c[2]), "+f"(c[3])
                 : "r"(a[0]), "r"(a[1]), "r"(a[2]), "r"(a[3]), "r"(b[0]), "r"(b[1]));
}
__device__ __forceinline__ void mma_bf16(float c[4], const uint32_t a[4], const uint32_t b[2]) {
    asm volatile("mma.sync.aligned.m16n8k16.row.col.f32.bf16.bf16.f32 "
                 "{%0,%1,%2,%3},{%4,%5,%6,%7},{%8,%9},{%0,%1,%2,%3};\n"
                 : "+f"(c[0]), "+f"(c[1]), "+f"(c[2]), "+f"(c[3])
                 : "r"(a[0]), "r"(a[1]), "r"(a[2]), "r"(a[3]), "r"(b[0]), "r"(b[1]));
}
__device__ __forceinline__ void ldsm_x4(uint32_t r[4], uint32_t addr) {
    asm volatile("ldmatrix.sync.aligned.m8n8.x4.shared.b16 {%0,%1,%2,%3}, [%4];"
                 : "=r"(r[0]), "=r"(r[1]), "=r"(r[2]), "=r"(r[3]) : "r"(addr));
}

// ---------------- f32 -> bf16 convert (vectorized) ----------------
__global__ void f2bf_kernel(const float* __restrict__ in, __nv_bfloat16* __restrict__ out, int n4) {
    int i = blockIdx.x * 256 + threadIdx.x;
    if (i >= n4) return;
    float4 v = ((const float4*)in)[i];
    __nv_bfloat162 lo = __floats2bfloat162_rn(v.x, v.y);
    __nv_bfloat162 hi = __floats2bfloat162_rn(v.z, v.w);
    ((__nv_bfloat162*)out)[2*i]   = lo;
    ((__nv_bfloat162*)out)[2*i+1] = hi;
}

// ---------------- rmsnorm -> bf16 ----------------
__global__ void rmsnorm_kernel(const float* __restrict__ x, const float* __restrict__ sc,
                               __nv_bfloat16* __restrict__ out) {
    int row = blockIdx.x;
    const float* xr = x + (size_t)row * D_;
    float s = 0.f;
    for (int i = threadIdx.x; i < D_; i += 256) { float v = xr[i]; s += v * v; }
    #pragma unroll
    for (int o = 16; o > 0; o >>= 1) s += __shfl_xor_sync(0xffffffffu, s, o);
    __shared__ float red[8];
    __shared__ float rtot;
    if ((threadIdx.x & 31) == 0) red[threadIdx.x >> 5] = s;
    __syncthreads();
    if (threadIdx.x == 0) {
        float t = 0.f;
        #pragma unroll
        for (int i = 0; i < 8; i++) t += red[i];
        rtot = rsqrtf(t / (float)D_ + 1e-6f);
    }
    __syncthreads();
    float r = rtot;
    for (int i = threadIdx.x; i < D_; i += 256)
        out[(size_t)row * D_ + i] = __float2bfloat16(xr[i] * sc[i] * r);
}

// ---------------- bf16 tensor-core GEMM NT: C[M,N] = A[M,K]*B[N,K]^T (+R) ----
// BM=BN=128, BK=32, 3-stage cp.async, 256 thr (2x4 warps, 64x32 per warp),
// m16n8k16 bf16 mma with ldmatrix fragment loads. smem row pad: 40 halves.
#define SLDH 40
#define BF_TILE (128*SLDH)                 // halves per tile
#define BF_SMEM (3 * 2 * BF_TILE * 2)      // 3 stages * 2 tiles * bytes = 61440

template<bool RESID>
__global__ __launch_bounds__(256, 2) void gemm_bf16(const __nv_bfloat16* __restrict__ A,
                                                    const __nv_bfloat16* __restrict__ Bw,
                                                    const float* __restrict__ R,
                                                    float* __restrict__ C,
                                                    int M, int N, int K) {
    extern __shared__ __nv_bfloat16 smh[];
    __nv_bfloat16* As = smh;                       // [3][BF_TILE]
    __nv_bfloat16* Bs = smh + 3 * BF_TILE;         // [3][BF_TILE]

    const int tid = threadIdx.x;
    const int m0 = blockIdx.y * 128, n0 = blockIdx.x * 128;
    const int w = tid >> 5, lane = tid & 31;
    const int wm = w >> 2, wn = w & 3;
    const int g = lane >> 2, t4 = lane & 3;

    // ldmatrix lane-address components
    const int arow = (lane & 7) + ((lane >> 3) & 1) * 8;   // within 16-row A block
    const int acol = (lane >> 4) * 8;                       // k offset within 16
    const int brow = (lane & 7) + (lane >> 4) * 8;          // within 16-row B block
    const int bcol = ((lane >> 3) & 1) * 8;

    float acc[4][4][4];
    #pragma unroll
    for (int i = 0; i < 4; i++)
        #pragma unroll
        for (int j = 0; j < 4; j++)
            #pragma unroll
            for (int r = 0; r < 4; r++) acc[i][j][r] = 0.f;

    auto load_tiles = [&](int stage, int k0) {
        __nv_bfloat16* as = As + stage * BF_TILE;
        __nv_bfloat16* bs = Bs + stage * BF_TILE;
        #pragma unroll
        for (int i = 0; i < 2; i++) {
            int id = tid + i * 256;               // 512 16B-chunks per tile
            int r = id >> 2, c = (id & 3) * 8;
            uint32_t sa = (uint32_t)__cvta_generic_to_shared(as + r * SLDH + c);
            const __nv_bfloat16* ga = A + (size_t)(m0 + r) * K + k0 + c;
            asm volatile("cp.async.cg.shared.global [%0], [%1], 16;\n" :: "r"(sa), "l"(ga));
            uint32_t sb = (uint32_t)__cvta_generic_to_shared(bs + r * SLDH + c);
            const __nv_bfloat16* gb = Bw + (size_t)(n0 + r) * K + k0 + c;
            asm volatile("cp.async.cg.shared.global [%0], [%1], 16;\n" :: "r"(sb), "l"(gb));
        }
        asm volatile("cp.async.commit_group;\n");
    };

    const int numK = K >> 5;
    load_tiles(0, 0);
    load_tiles(1, 32);

    for (int kt = 0; kt < numK; kt++) {
        if (kt + 2 < numK) {
            load_tiles((kt + 2) % 3, (kt + 2) * 32);
            asm volatile("cp.async.wait_group 2;\n");
        } else if (kt + 1 < numK) {
            asm volatile("cp.async.wait_group 1;\n");
        } else {
            asm volatile("cp.async.wait_group 0;\n");
        }
        __syncthreads();

        const __nv_bfloat16* as = As + (kt % 3) * BF_TILE;
        const __nv_bfloat16* bs = Bs + (kt % 3) * BF_TILE;

        #pragma unroll
        for (int kb = 0; kb < 2; kb++) {
            uint32_t af[4][4], bf[4][2];
            #pragma unroll
            for (int mi = 0; mi < 4; mi++) {
                int mr = wm * 64 + mi * 16 + arow;
                uint32_t ad = (uint32_t)__cvta_generic_to_shared(
                    as + mr * SLDH + kb * 16 + acol);
                ldsm_x4(af[mi], ad);
            }
            #pragma unroll
            for (int np = 0; np < 2; np++) {      // ni pair
                int nr = wn * 32 + np * 16 + brow;
                uint32_t bd = (uint32_t)__cvta_generic_to_shared(
                    bs + nr * SLDH + kb * 16 + bcol);
                uint32_t q[4];
                ldsm_x4(q, bd);
                bf[np*2  ][0] = q[0]; bf[np*2  ][1] = q[1];
                bf[np*2+1][0] = q[2]; bf[np*2+1][1] = q[3];
            }
            #pragma unroll
            for (int mi = 0; mi < 4; mi++)
                #pragma unroll
                for (int ni = 0; ni < 4; ni++)
                    mma_bf16(acc[mi][ni], af[mi], bf[ni]);
        }
        __syncthreads();
    }

    #pragma unroll
    for (int mi = 0; mi < 4; mi++) {
        int r0 = m0 + wm * 64 + mi * 16 + g;
        #pragma unroll
        for (int ni = 0; ni < 4; ni++) {
            int cc = n0 + wn * 32 + ni * 8 + 2 * t4;
            float2 v0 = make_float2(acc[mi][ni][0], acc[mi][ni][1]);
            float2 v1 = make_float2(acc[mi][ni][2], acc[mi][ni][3]);
            if (RESID) {
                float2 r0v = *(const float2*)(R + (size_t)r0 * N + cc);
                float2 r1v = *(const float2*)(R + (size_t)(r0 + 8) * N + cc);
                v0.x += r0v.x; v0.y += r0v.y;
                v1.x += r1v.x; v1.y += r1v.y;
            }
            *(float2*)(C + (size_t)r0 * N + cc) = v0;
            *(float2*)(C + (size_t)(r0 + 8) * N + cc) = v1;
        }
    }
}

// ---------------- cos_scale + RoPE pack ----------------
__device__ __forceinline__ float theta_of(int j, int h, float p0, float p1, float p2) {
    int i = j >> 3, f = j & 7;
    float pc = (i == 0) ? p0 : ((i == 1) ? p1 : p2);
    float freq = 3.14159265358979f * __expf((float)(f * 12 + h) * 0.02398526136f);
    return pc * freq;
}

__global__ void qk_transform(const float* __restrict__ src, int rowStride, int colOff,
                             const float* __restrict__ pos, const float* __restrict__ hscale,
                             float* __restrict__ dst) {
    int w = (blockIdx.x * blockDim.x + threadIdx.x) >> 5;
    int lane = threadIdx.x & 31;
    if (w >= B_ * L_ * H_) return;
    int h = w % H_;
    int bl = w / H_;
    int b = bl / L_, l = bl % L_;

    const float* sp = src + (size_t)bl * rowStride + colOff + h * DH_;
    float v0 = sp[lane], v1 = sp[lane + 32];
    float ss = v0 * v0 + v1 * v1;
    #pragma unroll
    for (int o = 16; o > 0; o >>= 1) ss += __shfl_xor_sync(0xffffffffu, ss, o);
    float f = sqrtf(hscale[h]) * rsqrtf(ss + 1e-6f);
    v0 *= f; v1 *= f;

    __shared__ float sh[8][64];
    int wl = threadIdx.x >> 5;
    sh[wl][lane] = v0; sh[wl][lane + 32] = v1;
    __syncwarp();

    float p0 = pos[(size_t)bl * 3 + 0];
    float p1 = pos[(size_t)bl * 3 + 1];
    float p2 = pos[(size_t)bl * 3 + 2];

    float out0, out1;
    {
        int d = lane;
        if (d < 24) {
            float th = theta_of(d, h, p0, p1, p2);
            float s, c; __sincosf(th, &s, &c);
            out0 = sh[wl][d] * c - sh[wl][d + 24] * s;
        } else {
            float th = theta_of(d - 24, h, p0, p1, p2);
            float s, c; __sincosf(th, &s, &c);
            out0 = sh[wl][d] * c + sh[wl][d - 24] * s;
        }
    }
    {
        int d = lane + 32;
        if (d < 48) {
            float th = theta_of(d - 24, h, p0, p1, p2);
            float s, c; __sincosf(th, &s, &c);
            out1 = sh[wl][d] * c + sh[wl][d - 24] * s;
        } else {
            out1 = sh[wl][d];
        }
    }
    float* dp = dst + ((size_t)(b * H_ + h) * L_ + l) * DH_;
    dp[lane] = out0; dp[lane + 32] = out1;
}

// ---------------- v copy ----------------
__global__ void copy_v(const float* __restrict__ src, int rowStride, int colOff,
                       float* __restrict__ dst) {
    int idx = blockIdx.x * 256 + threadIdx.x;
    if (idx >= M_ * D_) return;
    int d = idx & 63;
    int h = (idx >> 6) % H_;
    int bl = idx / D_;
    int b = bl / L_, l = bl % L_;
    dst[((size_t)(b * H_ + h) * L_ + l) * DH_ + d] =
        src[(size_t)bl * rowStride + colOff + h * DH_ + d];
}

// ---------------- tensor-core flash attention (tf32), bf16 output ------------
#define KLD 68
#define VLD 72
#define ATT_SMEM ((64*KLD + 64*VLD + 4*16*KLD) * 4)

__global__ __launch_bounds__(128) void attn_tc(const float* __restrict__ Q,
                                               const float* __restrict__ K,
                                               const float* __restrict__ V,
                                               __nv_bfloat16* __restrict__ O) {
    extern __shared__ float sm[];
    float* Ks = sm;
    float* Vs = sm + 64 * KLD;
    float* Ps = sm + 64 * KLD + 64 * VLD;

    const int bh = blockIdx.y;
    const int q0 = blockIdx.x * 64;
    const int tid = threadIdx.x;
    const int w = tid >> 5, lane = tid & 31;
    const int g = lane >> 2, t4 = lane & 3;

    const float* qb = Q + ((size_t)bh * L_ + q0) * DH_;
    #pragma unroll
    for (int i = 0; i < 8; i++) {
        int idx = tid + i * 128;
        int r = idx >> 4, c4 = (idx & 15) * 4;
        *(float4*)(Ks + r * KLD + c4) = *(const float4*)(qb + r * 64 + c4);
    }
    __syncthreads();
    uint32_t qf[8][4];
    {
        int r0 = w * 16 + g;
        #pragma unroll
        for (int kb = 0; kb < 8; kb++) {
            int kc = kb * 8 + t4;
            qf[kb][0] = f2tf(Ks[(r0    ) * KLD + kc    ]);
            qf[kb][1] = f2tf(Ks[(r0 + 8) * KLD + kc    ]);
            qf[kb][2] = f2tf(Ks[(r0    ) * KLD + kc + 4]);
            qf[kb][3] = f2tf(Ks[(r0 + 8) * KLD + kc + 4]);
        }
    }
    __syncthreads();

    float ob[8][4];
    #pragma unroll
    for (int n = 0; n < 8; n++)
        #pragma unroll
        for (int r = 0; r < 4; r++) ob[n][r] = 0.f;
    float m0 = -1e30f, m1 = -1e30f, l0 = 0.f, l1 = 0.f;

    const float* kbase = K + (size_t)bh * L_ * DH_;
    const float* vbase = V + (size_t)bh * L_ * DH_;
    float* pw = Ps + w * 16 * KLD;

    for (int kt = 0; kt < L_; kt += 64) {
        #pragma unroll
        for (int i = 0; i < 8; i++) {
            int idx = tid + i * 128;
            int r = idx >> 4, c4 = (idx & 15) * 4;
            *(float4*)(Ks + r * KLD + c4) = *(const float4*)(kbase + (size_t)(kt + r) * 64 + c4);
            *(float4*)(Vs + r * VLD + c4) = *(const float4*)(vbase + (size_t)(kt + r) * 64 + c4);
        }
        __syncthreads();

        float sc[8][4];
        #pragma unroll
        for (int n = 0; n < 8; n++)
            #pragma unroll
            for (int r = 0; r < 4; r++) sc[n][r] = 0.f;
        #pragma unroll
        for (int kb = 0; kb < 8; kb++) {
            int kc = kb * 8 + t4;
            #pragma unroll
            for (int n = 0; n < 8; n++) {
                uint32_t bfv[2];
                bfv[0] = f2tf(Ks[(n * 8 + g) * KLD + kc    ]);
                bfv[1] = f2tf(Ks[(n * 8 + g) * KLD + kc + 4]);
                mma_tf32(sc[n], qf[kb], bfv);
            }
        }

        float rm0 = -1e30f, rm1 = -1e30f;
        #pragma unroll
        for (int n = 0; n < 8; n++) {
            rm0 = fmaxf(rm0, fmaxf(sc[n][0], sc[n][1]));
            rm1 = fmaxf(rm1, fmaxf(sc[n][2], sc[n][3]));
        }
        rm0 = fmaxf(rm0, __shfl_xor_sync(0xffffffffu, rm0, 1));
        rm0 = fmaxf(rm0, __shfl_xor_sync(0xffffffffu, rm0, 2));
        rm1 = fmaxf(rm1, __shfl_xor_sync(0xffffffffu, rm1, 1));
        rm1 = fmaxf(rm1, __shfl_xor_sync(0xffffffffu, rm1, 2));
        float nm0 = fmaxf(m0, rm0), nm1 = fmaxf(m1, rm1);
        float c0 = __expf(m0 - nm0), c1 = __expf(m1 - nm1);
        m0 = nm0; m1 = nm1;

        float ps0 = 0.f, ps1 = 0.f;
        #pragma unroll
        for (int n = 0; n < 8; n++) {
            sc[n][0] = __expf(sc[n][0] - nm0);
            sc[n][1] = __expf(sc[n][1] - nm0);
            sc[n][2] = __expf(sc[n][2] - nm1);
            sc[n][3] = __expf(sc[n][3] - nm1);
            ps0 += sc[n][0] + sc[n][1];
            ps1 += sc[n][2] + sc[n][3];
        }
        l0 = l0 * c0 + ps0;
        l1 = l1 * c1 + ps1;
        #pragma unroll
        for (int n = 0; n < 8; n++) {
            ob[n][0] *= c0; ob[n][1] *= c0;
            ob[n][2] *= c1; ob[n][3] *= c1;
        }

        #pragma unroll
        for (int n = 0; n < 8; n++) {
            *(float2*)(pw + (g    ) * KLD + n * 8 + 2 * t4) = make_float2(sc[n][0], sc[n][1]);
            *(float2*)(pw + (g + 8) * KLD + n * 8 + 2 * t4) = make_float2(sc[n][2], sc[n][3]);
        }
        __syncwarp();

        #pragma unroll
        for (int kb = 0; kb < 8; kb++) {
            int kc = kb * 8 + t4;
            uint32_t af[4];
            af[0] = f2tf(pw[(g    ) * KLD + kc    ]);
            af[1] = f2tf(pw[(g + 8) * KLD + kc    ]);
            af[2] = f2tf(pw[(g    ) * KLD + kc + 4]);
            af[3] = f2tf(pw[(g + 8) * KLD + kc + 4]);
            #pragma unroll
            for (int n = 0; n < 8; n++) {
                uint32_t bfv[2];
                bfv[0] = f2tf(Vs[(kc    ) * VLD + n * 8 + g]);
                bfv[1] = f2tf(Vs[(kc + 4) * VLD + n * 8 + g]);
                mma_tf32(ob[n], af, bfv);
            }
        }
        __syncthreads();
    }

    l0 += __shfl_xor_sync(0xffffffffu, l0, 1);
    l0 += __shfl_xor_sync(0xffffffffu, l0, 2);
    l1 += __shfl_xor_sync(0xffffffffu, l1, 1);
    l1 += __shfl_xor_sync(0xffffffffu, l1, 2);
    float inv0 = 1.f / l0, inv1 = 1.f / l1;

    int b = bh / H_, h = bh % H_;
    int r0 = q0 + w * 16 + g;
    __nv_bfloat16* o0 = O + ((size_t)(b * L_ + r0)) * D_ + h * DH_;
    __nv_bfloat16* o1 = O + ((size_t)(b * L_ + r0 + 8)) * D_ + h * DH_;
    #pragma unroll
    for (int n = 0; n < 8; n++) {
        *(__nv_bfloat162*)(o0 + n * 8 + 2 * t4) = __floats2bfloat162_rn(ob[n][0] * inv0, ob[n][1] * inv0);
        *(__nv_bfloat162*)(o1 + n * 8 + 2 * t4) = __floats2bfloat162_rn(ob[n][2] * inv1, ob[n][3] * inv1);
    }
}

// ---------------- a * silu(g) -> bf16 ----------------
__global__ void silu_mul(const float* __restrict__ u, __nv_bfloat16* __restrict__ ag) {
    int idx = blockIdx.x * 256 + threadIdx.x;
    if (idx >= M_ * DFF_) return;
    int r = idx / DFF_, j = idx - r * DFF_;
    float a = u[(size_t)r * UPN_ + j];
    float g = u[(size_t)r * UPN_ + j + DFF_];
    ag[idx] = __float2bfloat16(a * (g / (1.f + __expf(-g))));
}

// ---------------- host launcher ----------------
extern "C" void kernel_launch(void* const* d_in, const int* in_sizes, int n_in,
                              void* d_out, int out_size) {
    const float* x        = (const float*)d_in[0];
    const float* pos      = (const float*)d_in[1];
    const float* x_cross  = (const float*)d_in[2];
    const float* pos_cross= (const float*)d_in[3];
    const float* sa_norm  = (const float*)d_in[4];
    const float* sa_wqkv  = (const float*)d_in[5];
    const float* sa_scale = (const float*)d_in[6];
    const float* sa_wout  = (const float*)d_in[7];
    const float* ca_norm  = (const float*)d_in[8];
    const float* ca_normc = (const float*)d_in[9];
    const float* ca_wq    = (const float*)d_in[10];
    const float* ca_wkv   = (const float*)d_in[11];
    const float* ca_scale = (const float*)d_in[12];
    const float* ca_wout  = (const float*)d_in[13];
    const float* ff_norm  = (const float*)d_in[14];
    const float* ff_wup   = (const float*)d_in[15];
    const float* ff_wdown = (const float*)d_in[16];
    float* out = (float*)d_out;

    float *big, *lin2, *q, *k, *v, *x1, *x2;
    __nv_bfloat16 *norm_bf, *normc_bf, *ao_bf, *ag_bf;
    __nv_bfloat16 *wqkv_bf, *wout1_bf, *wq_bf, *wkv_bf, *wout2_bf, *wup_bf, *wdown_bf;
    cudaGetSymbolAddress((void**)&big,   g_big);
    cudaGetSymbolAddress((void**)&lin2,  g_lin2);
    cudaGetSymbolAddress((void**)&q,     g_q);
    cudaGetSymbolAddress((void**)&k,     g_k);
    cudaGetSymbolAddress((void**)&v,     g_v);
    cudaGetSymbolAddress((void**)&x1,    g_x1);
    cudaGetSymbolAddress((void**)&x2,    g_x2);
    cudaGetSymbolAddress((void**)&norm_bf,  g_norm_bf);
    cudaGetSymbolAddress((void**)&normc_bf, g_normc_bf);
    cudaGetSymbolAddress((void**)&ao_bf,    g_ao_bf);
    cudaGetSymbolAddress((void**)&ag_bf,    g_ag_bf);
    cudaGetSymbolAddress((void**)&wqkv_bf,  g_wqkv_bf);
    cudaGetSymbolAddress((void**)&wout1_bf, g_wout1_bf);
    cudaGetSymbolAddress((void**)&wq_bf,    g_wq_bf);
    cudaGetSymbolAddress((void**)&wkv_bf,   g_wkv_bf);
    cudaGetSymbolAddress((void**)&wout2_bf, g_wout2_bf);
    cudaGetSymbolAddress((void**)&wup_bf,   g_wup_bf);
    cudaGetSymbolAddress((void**)&wdown_bf, g_wdown_bf);

    static bool attr_done = false;
    if (!attr_done) {
        cudaFuncSetAttribute(gemm_bf16<false>, cudaFuncAttributeMaxDynamicSharedMemorySize, BF_SMEM);
        cudaFuncSetAttribute(gemm_bf16<true>,  cudaFuncAttributeMaxDynamicSharedMemorySize, BF_SMEM);
        cudaFuncSetAttribute(attn_tc, cudaFuncAttributeMaxDynamicSharedMemorySize, ATT_SMEM);
        attr_done = true;
    }

    // ---- convert weights to bf16 ----
    auto conv = [&](const float* src, __nv_bfloat16* dst, int n) {
        f2bf_kernel<<<(n/4 + 255)/256, 256>>>(src, dst, n/4);
    };
    conv(sa_wqkv,  wqkv_bf,  2304*768);
    conv(sa_wout,  wout1_bf, 768*768);
    conv(ca_wq,    wq_bf,    768*768);
    conv(ca_wkv,   wkv_bf,   1536*768);
    conv(ca_wout,  wout2_bf, 768*768);
    conv(ff_wup,   wup_bf,   4608*768);
    conv(ff_wdown, wdown_bf, 768*2304);

    const int packBlocks = (B_ * L_ * H_ * 32 + 255) / 256;
    const int elemBlocks = (M_ * D_ + 255) / 256;

    // ---- self attention ----
    rmsnorm_kernel<<<M_, 256>>>(x, sa_norm, norm_bf);
    gemm_bf16<false><<<dim3(2304/128, M_/128), 256, BF_SMEM>>>(norm_bf, wqkv_bf, nullptr, big, M_, 2304, D_);
    qk_transform<<<packBlocks, 256>>>(big, 2304, 0,    pos, sa_scale, q);
    qk_transform<<<packBlocks, 256>>>(big, 2304, 768,  pos, sa_scale, k);
    copy_v     <<<elemBlocks, 256>>>(big, 2304, 1536, v);
    attn_tc<<<dim3(L_/64, B_*H_), 128, ATT_SMEM>>>(q, k, v, ao_bf);
    gemm_bf16<true><<<dim3(D_/128, M_/128), 256, BF_SMEM>>>(ao_bf, wout1_bf, x, x1, M_, D_, D_);

    // ---- cross attention ----
    rmsnorm_kernel<<<M_, 256>>>(x1, ca_norm, norm_bf);
    rmsnorm_kernel<<<M_, 256>>>(x_cross, ca_normc, normc_bf);
    gemm_bf16<false><<<dim3(D_/128, M_/128), 256, BF_SMEM>>>(norm_bf,  wq_bf,  nullptr, lin2, M_, D_,   D_);
    gemm_bf16<false><<<dim3(1536/128, M_/128), 256, BF_SMEM>>>(normc_bf, wkv_bf, nullptr, big,  M_, 1536, D_);
    qk_transform<<<packBlocks, 256>>>(lin2, 768,  0,   pos,       ca_scale, q);
    qk_transform<<<packBlocks, 256>>>(big,  1536, 0,   pos_cross, ca_scale, k);
    copy_v     <<<elemBlocks, 256>>>(big,  1536, 768, v);
    attn_tc<<<dim3(L_/64, B_*H_), 128, ATT_SMEM>>>(q, k, v, ao_bf);
    gemm_bf16<true><<<dim3(D_/128, M_/128), 256, BF_SMEM>>>(ao_bf, wout2_bf, x1, x2, M_, D_, D_);

    // ---- feed forward ----
    rmsnorm_kernel<<<M_, 256>>>(x2, ff_norm, norm_bf);
    gemm_bf16<false><<<dim3(UPN_/128, M_/128), 256, BF_SMEM>>>(norm_bf, wup_bf, nullptr, big, M_, UPN_, D_);
    silu_mul<<<(M_ * DFF_ + 255) / 256, 256>>>(big, ag_bf);
    gemm_bf16<true><<<dim3(D_/128, M_/128), 256, BF_SMEM>>>(ag_bf, wdown_bf, x2, out, M_, D_, DFF_);
}

// round 7
// speedup vs baseline: 6.4424x; 1.4624x over previous
#include <cuda_runtime.h>
#include <cuda_bf16.h>
#include <cstdint>

#define B_ 2
#define L_ 2048
#define D_ 768
#define H_ 12
#define DH_ 64
#define M_ (B_*L_)
#define DFF_ 2304
#define UPN_ (2*DFF_)

// ---------------- scratch ----------------
__device__ float g_x1 [M_*D_];
__device__ float g_x2 [M_*D_];

__device__ __nv_bfloat16 g_norm_bf [M_*D_];
__device__ __nv_bfloat16 g_normc_bf[M_*D_];
__device__ __nv_bfloat16 g_qkv_bf  [M_*2304];
__device__ __nv_bfloat16 g_lin2_bf [M_*D_];
__device__ __nv_bfloat16 g_q_bf    [B_*H_*L_*DH_];
__device__ __nv_bfloat16 g_k_bf    [B_*H_*L_*DH_];
__device__ __nv_bfloat16 g_v_bf    [B_*H_*L_*DH_];
__device__ __nv_bfloat16 g_ao_bf   [M_*D_];
__device__ __nv_bfloat16 g_ag_bf   [M_*DFF_];

__device__ __nv_bfloat16 g_wqkv_bf [2304*768];
__device__ __nv_bfloat16 g_wout1_bf[768*768];
__device__ __nv_bfloat16 g_wq_bf   [768*768];
__device__ __nv_bfloat16 g_wkv_bf  [1536*768];
__device__ __nv_bfloat16 g_wout2_bf[768*768];
__device__ __nv_bfloat16 g_wup_bf  [4608*768];   // permuted: row 2j=a_j, 2j+1=g_j
__device__ __nv_bfloat16 g_wdown_bf[768*2304];

// ---------------- mma / ldmatrix helpers ----------------
__device__ __forceinline__ void mma_bf16(float c[4], const uint32_t a[4], const uint32_t b[2]) {
    asm volatile("mma.sync.aligned.m16n8k16.row.col.f32.bf16.bf16.f32 "
                 "{%0,%1,%2,%3},{%4,%5,%6,%7},{%8,%9},{%0,%1,%2,%3};\n"
                 : "+f"(c[0]), "+f"(c[1]), "+f"(c[2]), "+f"(c[3])
                 : "r"(a[0]), "r"(a[1]), "r"(a[2]), "r"(a[3]), "r"(b[0]), "r"(b[1]));
}
__device__ __forceinline__ void ldsm_x4(uint32_t r[4], uint32_t addr) {
    asm volatile("ldmatrix.sync.aligned.m8n8.x4.shared.b16 {%0,%1,%2,%3}, [%4];"
                 : "=r"(r[0]), "=r"(r[1]), "=r"(r[2]), "=r"(r[3]) : "r"(addr));
}
__device__ __forceinline__ void ldsm_x4_t(uint32_t r[4], uint32_t addr) {
    asm volatile("ldmatrix.sync.aligned.m8n8.x4.trans.shared.b16 {%0,%1,%2,%3}, [%4];"
                 : "=r"(r[0]), "=r"(r[1]), "=r"(r[2]), "=r"(r[3]) : "r"(addr));
}
__device__ __forceinline__ uint32_t pk_bf(float a, float b) {
    __nv_bfloat162 t = __floats2bfloat162_rn(a, b);
    return *(uint32_t*)&t;
}

// ---------------- fused weight conversion ----------------
struct ConvTab {
    const float4* src[6];
    uint2*        dst[6];
    int           n4[6];
};
__global__ void conv6_kernel(ConvTab t) {
    int r = blockIdx.y;
    int i = blockIdx.x * 256 + threadIdx.x;
    if (i >= t.n4[r]) return;
    float4 v = t.src[r][i];
    __nv_bfloat162 lo = __floats2bfloat162_rn(v.x, v.y);
    __nv_bfloat162 hi = __floats2bfloat162_rn(v.z, v.w);
    uint2 o; o.x = *(uint32_t*)&lo; o.y = *(uint32_t*)&hi;
    t.dst[r][i] = o;
}
// permuting conversion for ff_wup: dst row 2j <- src row j, dst row 2j+1 <- src row j+DFF
__global__ void convup_kernel(const float* __restrict__ src, __nv_bfloat16* __restrict__ dst) {
    int i = blockIdx.x * 256 + threadIdx.x;      // over UPN_*D_/4
    if (i >= UPN_ * (D_ / 4)) return;
    int p  = i / (D_ / 4);
    int kc = (i % (D_ / 4)) * 4;
    int srow = (p & 1) ? (DFF_ + (p >> 1)) : (p >> 1);
    float4 v = *(const float4*)(src + (size_t)srow * D_ + kc);
    __nv_bfloat162 lo = __floats2bfloat162_rn(v.x, v.y);
    __nv_bfloat162 hi = __floats2bfloat162_rn(v.z, v.w);
    uint2 o; o.x = *(uint32_t*)&lo; o.y = *(uint32_t*)&hi;
    *(uint2*)(dst + (size_t)p * D_ + kc) = o;
}

// ---------------- rmsnorm -> bf16 ----------------
__global__ void rmsnorm_kernel(const float* __restrict__ x, const float* __restrict__ sc,
                               __nv_bfloat16* __restrict__ out) {
    int row = blockIdx.x;
    const float* xr = x + (size_t)row * D_;
    float s = 0.f;
    for (int i = threadIdx.x; i < D_; i += 256) { float v = xr[i]; s += v * v; }
    #pragma unroll
    for (int o = 16; o > 0; o >>= 1) s += __shfl_xor_sync(0xffffffffu, s, o);
    __shared__ float red[8];
    __shared__ float rtot;
    if ((threadIdx.x & 31) == 0) red[threadIdx.x >> 5] = s;
    __syncthreads();
    if (threadIdx.x == 0) {
        float t = 0.f;
        #pragma unroll
        for (int i = 0; i < 8; i++) t += red[i];
        rtot = rsqrtf(t / (float)D_ + 1e-6f);
    }
    __syncthreads();
    float r = rtot;
    for (int i = threadIdx.x; i < D_; i += 256)
        out[(size_t)row * D_ + i] = __float2bfloat16(xr[i] * sc[i] * r);
}

// ---------------- bf16 GEMM NT.  MODE: 0 = f32 out + resid, 1 = bf16 out,
//                  2 = paired silu epilogue -> bf16 (A*silu(G), permuted W) ---
#define SLDH 40
#define BF_TILE (128*SLDH)
#define BF_SMEM (3 * 2 * BF_TILE * 2)

template<int MODE>
__global__ __launch_bounds__(256, 2) void gemm_bf16(const __nv_bfloat16* __restrict__ A,
                                                    const __nv_bfloat16* __restrict__ Bw,
                                                    const float* __restrict__ R,
                                                    float* __restrict__ Cf,
                                                    __nv_bfloat16* __restrict__ Cb,
                                                    int M, int N, int K) {
    extern __shared__ __nv_bfloat16 smh[];
    __nv_bfloat16* As = smh;
    __nv_bfloat16* Bs = smh + 3 * BF_TILE;

    const int tid = threadIdx.x;
    const int m0 = blockIdx.y * 128, n0 = blockIdx.x * 128;
    const int w = tid >> 5, lane = tid & 31;
    const int wm = w >> 2, wn = w & 3;
    const int g = lane >> 2, t4 = lane & 3;

    const int arow = (lane & 7) + ((lane >> 3) & 1) * 8;
    const int acol = (lane >> 4) * 8;
    const int brow = (lane & 7) + (lane >> 4) * 8;
    const int bcol = ((lane >> 3) & 1) * 8;

    float acc[4][4][4];
    #pragma unroll
    for (int i = 0; i < 4; i++)
        #pragma unroll
        for (int j = 0; j < 4; j++)
            #pragma unroll
            for (int r = 0; r < 4; r++) acc[i][j][r] = 0.f;

    auto load_tiles = [&](int stage, int k0) {
        __nv_bfloat16* as = As + stage * BF_TILE;
        __nv_bfloat16* bs = Bs + stage * BF_TILE;
        #pragma unroll
        for (int i = 0; i < 2; i++) {
            int id = tid + i * 256;
            int r = id >> 2, c = (id & 3) * 8;
            uint32_t sa = (uint32_t)__cvta_generic_to_shared(as + r * SLDH + c);
            const __nv_bfloat16* ga = A + (size_t)(m0 + r) * K + k0 + c;
            asm volatile("cp.async.cg.shared.global [%0], [%1], 16;\n" :: "r"(sa), "l"(ga));
            uint32_t sb = (uint32_t)__cvta_generic_to_shared(bs + r * SLDH + c);
            const __nv_bfloat16* gb = Bw + (size_t)(n0 + r) * K + k0 + c;
            asm volatile("cp.async.cg.shared.global [%0], [%1], 16;\n" :: "r"(sb), "l"(gb));
        }
        asm volatile("cp.async.commit_group;\n");
    };

    const int numK = K >> 5;
    load_tiles(0, 0);
    load_tiles(1, 32);

    for (int kt = 0; kt < numK; kt++) {
        if (kt + 2 < numK) {
            load_tiles((kt + 2) % 3, (kt + 2) * 32);
            asm volatile("cp.async.wait_group 2;\n");
        } else if (kt + 1 < numK) {
            asm volatile("cp.async.wait_group 1;\n");
        } else {
            asm volatile("cp.async.wait_group 0;\n");
        }
        __syncthreads();

        const __nv_bfloat16* as = As + (kt % 3) * BF_TILE;
        const __nv_bfloat16* bs = Bs + (kt % 3) * BF_TILE;

        #pragma unroll
        for (int kb = 0; kb < 2; kb++) {
            uint32_t af[4][4], bf[4][2];
            #pragma unroll
            for (int mi = 0; mi < 4; mi++) {
                int mr = wm * 64 + mi * 16 + arow;
                uint32_t ad = (uint32_t)__cvta_generic_to_shared(as + mr * SLDH + kb * 16 + acol);
                ldsm_x4(af[mi], ad);
            }
            #pragma unroll
            for (int np = 0; np < 2; np++) {
                int nr = wn * 32 + np * 16 + brow;
                uint32_t bd = (uint32_t)__cvta_generic_to_shared(bs + nr * SLDH + kb * 16 + bcol);
                uint32_t q[4];
                ldsm_x4(q, bd);
                bf[np*2  ][0] = q[0]; bf[np*2  ][1] = q[1];
                bf[np*2+1][0] = q[2]; bf[np*2+1][1] = q[3];
            }
            #pragma unroll
            for (int mi = 0; mi < 4; mi++)
                #pragma unroll
                for (int ni = 0; ni < 4; ni++)
                    mma_bf16(acc[mi][ni], af[mi], bf[ni]);
        }
        __syncthreads();
    }

    #pragma unroll
    for (int mi = 0; mi < 4; mi++) {
        int r0 = m0 + wm * 64 + mi * 16 + g;
        #pragma unroll
        for (int ni = 0; ni < 4; ni++) {
            int cc = n0 + wn * 32 + ni * 8 + 2 * t4;
            float a0 = acc[mi][ni][0], a1 = acc[mi][ni][1];
            float a2 = acc[mi][ni][2], a3 = acc[mi][ni][3];
            if (MODE == 0) {
                float2 r0v = *(const float2*)(R + (size_t)r0 * N + cc);
                float2 r1v = *(const float2*)(R + (size_t)(r0 + 8) * N + cc);
                *(float2*)(Cf + (size_t)r0 * N + cc)       = make_float2(a0 + r0v.x, a1 + r0v.y);
                *(float2*)(Cf + (size_t)(r0 + 8) * N + cc) = make_float2(a2 + r1v.x, a3 + r1v.y);
            } else if (MODE == 1) {
                *(__nv_bfloat162*)(Cb + (size_t)r0 * N + cc)       = __floats2bfloat162_rn(a0, a1);
                *(__nv_bfloat162*)(Cb + (size_t)(r0 + 8) * N + cc) = __floats2bfloat162_rn(a2, a3);
            } else {
                // (even,odd) = (a_j, g_j); out = a*silu(g)
                int jj = cc >> 1;
                float s0 = a0 * (a1 / (1.f + __expf(-a1)));
                float s1 = a2 * (a3 / (1.f + __expf(-a3)));
                Cb[(size_t)r0 * DFF_ + jj]       = __float2bfloat16(s0);
                Cb[(size_t)(r0 + 8) * DFF_ + jj] = __float2bfloat16(s1);
            }
        }
    }
}

// ---------------- cos_scale + RoPE (bf16 in/out) ----------------
__device__ __forceinline__ float theta_of(int j, int h, float p0, float p1, float p2) {
    int i = j >> 3, f = j & 7;
    float pc = (i == 0) ? p0 : ((i == 1) ? p1 : p2);
    float freq = 3.14159265358979f * __expf((float)(f * 12 + h) * 0.02398526136f);
    return pc * freq;
}

__global__ void qk_transform(const __nv_bfloat16* __restrict__ src, int rowStride, int colOff,
                             const float* __restrict__ pos, const float* __restrict__ hscale,
                             __nv_bfloat16* __restrict__ dst) {
    int w = (blockIdx.x * blockDim.x + threadIdx.x) >> 5;
    int lane = threadIdx.x & 31;
    if (w >= B_ * L_ * H_) return;
    int h = w % H_;
    int bl = w / H_;
    int b = bl / L_, l = bl % L_;

    const __nv_bfloat16* sp = src + (size_t)bl * rowStride + colOff + h * DH_;
    float v0 = __bfloat162float(sp[lane]), v1 = __bfloat162float(sp[lane + 32]);
    float ss = v0 * v0 + v1 * v1;
    #pragma unroll
    for (int o = 16; o > 0; o >>= 1) ss += __shfl_xor_sync(0xffffffffu, ss, o);
    float f = sqrtf(hscale[h]) * rsqrtf(ss + 1e-6f);
    v0 *= f; v1 *= f;

    __shared__ float sh[8][64];
    int wl = threadIdx.x >> 5;
    sh[wl][lane] = v0; sh[wl][lane + 32] = v1;
    __syncwarp();

    float p0 = pos[(size_t)bl * 3 + 0];
    float p1 = pos[(size_t)bl * 3 + 1];
    float p2 = pos[(size_t)bl * 3 + 2];

    float out0, out1;
    {
        int d = lane;
        if (d < 24) {
            float th = theta_of(d, h, p0, p1, p2);
            float s, c; __sincosf(th, &s, &c);
            out0 = sh[wl][d] * c - sh[wl][d + 24] * s;
        } else {
            float th = theta_of(d - 24, h, p0, p1, p2);
            float s, c; __sincosf(th, &s, &c);
            out0 = sh[wl][d] * c + sh[wl][d - 24] * s;
        }
    }
    {
        int d = lane + 32;
        if (d < 48) {
            float th = theta_of(d - 24, h, p0, p1, p2);
            float s, c; __sincosf(th, &s, &c);
            out1 = sh[wl][d] * c + sh[wl][d - 24] * s;
        } else {
            out1 = sh[wl][d];
        }
    }
    __nv_bfloat16* dp = dst + ((size_t)(b * H_ + h) * L_ + l) * DH_;
    dp[lane] = __float2bfloat16(out0);
    dp[lane + 32] = __float2bfloat16(out1);
}

// ---------------- v copy bf16 (vectorized, layout change) ----------------
__global__ void copy_v(const __nv_bfloat16* __restrict__ src, int rowStride, int colOff,
                       __nv_bfloat16* __restrict__ dst) {
    int idx = blockIdx.x * 256 + threadIdx.x;        // chunks of 8 halves
    if (idx >= B_ * L_ * H_ * 8) return;
    int c = idx & 7;
    int h = (idx >> 3) % H_;
    int bl = idx / (8 * H_);
    int b = bl / L_, l = bl % L_;
    *(uint4*)(dst + (((size_t)(b * H_ + h) * L_ + l) * DH_ + c * 8)) =
        *(const uint4*)(src + ((size_t)bl * rowStride + colOff + h * DH_ + c * 8));
}

// ---------------- bf16 tensor-core flash attention ----------------
#define ALD 72

__global__ __launch_bounds__(128) void attn_bf(const __nv_bfloat16* __restrict__ Q,
                                               const __nv_bfloat16* __restrict__ K,
                                               const __nv_bfloat16* __restrict__ V,
                                               __nv_bfloat16* __restrict__ O) {
    __shared__ __nv_bfloat16 Ks[64 * ALD];
    __shared__ __nv_bfloat16 Vs[64 * ALD];

    const int bh = blockIdx.y;
    const int q0 = blockIdx.x * 64;
    const int tid = threadIdx.x;
    const int w = tid >> 5, lane = tid & 31;
    const int g = lane >> 2, t4 = lane & 3;

    const int arow = (lane & 7) + ((lane >> 3) & 1) * 8;
    const int acol = (lane >> 4) * 8;
    const int brow = (lane & 7) + (lane >> 4) * 8;
    const int bcol = ((lane >> 3) & 1) * 8;
    const int vrow = (lane & 7) + ((lane >> 3) & 1) * 8;
    const int vcol = (lane >> 4) * 8;

    // stage Q through Ks, build A fragments
    const __nv_bfloat16* qb = Q + ((size_t)bh * L_ + q0) * DH_;
    #pragma unroll
    for (int i = 0; i < 4; i++) {
        int idx = tid + i * 128;                 // 512 chunks of 8 halves
        int r = idx >> 3, c = (idx & 7) * 8;
        *(uint4*)(Ks + r * ALD + c) = *(const uint4*)(qb + r * 64 + c);
    }
    __syncthreads();
    uint32_t qf[4][4];
    #pragma unroll
    for (int kb = 0; kb < 4; kb++) {
        uint32_t ad = (uint32_t)__cvta_generic_to_shared(
            Ks + (w * 16 + arow) * ALD + kb * 16 + acol);
        ldsm_x4(qf[kb], ad);
    }
    __syncthreads();

    float ob[8][4];
    #pragma unroll
    for (int n = 0; n < 8; n++)
        #pragma unroll
        for (int r = 0; r < 4; r++) ob[n][r] = 0.f;
    float m0 = -1e30f, m1 = -1e30f, l0 = 0.f, l1 = 0.f;

    const __nv_bfloat16* kbase = K + (size_t)bh * L_ * DH_;
    const __nv_bfloat16* vbase = V + (size_t)bh * L_ * DH_;

    for (int kt = 0; kt < L_; kt += 64) {
        #pragma unroll
        for (int i = 0; i < 4; i++) {
            int idx = tid + i * 128;
            int r = idx >> 3, c = (idx & 7) * 8;
            *(uint4*)(Ks + r * ALD + c) = *(const uint4*)(kbase + (size_t)(kt + r) * 64 + c);
            *(uint4*)(Vs + r * ALD + c) = *(const uint4*)(vbase + (size_t)(kt + r) * 64 + c);
        }
        __syncthreads();

        // S = Q @ K^T
        float sc[8][4];
        #pragma unroll
        for (int n = 0; n < 8; n++)
            #pragma unroll
            for (int r = 0; r < 4; r++) sc[n][r] = 0.f;
        #pragma unroll
        for (int kb = 0; kb < 4; kb++) {
            uint32_t bf[8][2];
            #pragma unroll
            for (int np = 0; np < 4; np++) {
                uint32_t bd = (uint32_t)__cvta_generic_to_shared(
                    Ks + (np * 16 + brow) * ALD + kb * 16 + bcol);
                uint32_t q[4];
                ldsm_x4(q, bd);
                bf[np*2  ][0] = q[0]; bf[np*2  ][1] = q[1];
                bf[np*2+1][0] = q[2]; bf[np*2+1][1] = q[3];
            }
            #pragma unroll
            for (int n = 0; n < 8; n++)
                mma_bf16(sc[n], qf[kb], bf[n]);
        }

        // online softmax
        float rm0 = -1e30f, rm1 = -1e30f;
        #pragma unroll
        for (int n = 0; n < 8; n++) {
            rm0 = fmaxf(rm0, fmaxf(sc[n][0], sc[n][1]));
            rm1 = fmaxf(rm1, fmaxf(sc[n][2], sc[n][3]));
        }
        rm0 = fmaxf(rm0, __shfl_xor_sync(0xffffffffu, rm0, 1));
        rm0 = fmaxf(rm0, __shfl_xor_sync(0xffffffffu, rm0, 2));
        rm1 = fmaxf(rm1, __shfl_xor_sync(0xffffffffu, rm1, 1));
        rm1 = fmaxf(rm1, __shfl_xor_sync(0xffffffffu, rm1, 2));
        float nm0 = fmaxf(m0, rm0), nm1 = fmaxf(m1, rm1);
        float c0 = __expf(m0 - nm0), c1 = __expf(m1 - nm1);
        m0 = nm0; m1 = nm1;

        float ps0 = 0.f, ps1 = 0.f;
        #pragma unroll
        for (int n = 0; n < 8; n++) {
            sc[n][0] = __expf(sc[n][0] - nm0);
            sc[n][1] = __expf(sc[n][1] - nm0);
            sc[n][2] = __expf(sc[n][2] - nm1);
            sc[n][3] = __expf(sc[n][3] - nm1);
            ps0 += sc[n][0] + sc[n][1];
            ps1 += sc[n][2] + sc[n][3];
        }
        l0 = l0 * c0 + ps0;
        l1 = l1 * c1 + ps1;
        #pragma unroll
        for (int n = 0; n < 8; n++) {
            ob[n][0] *= c0; ob[n][1] *= c0;
            ob[n][2] *= c1; ob[n][3] *= c1;
        }

        // P fragments directly from sc registers
        uint32_t pf[4][4];
        #pragma unroll
        for (int kb = 0; kb < 4; kb++) {
            pf[kb][0] = pk_bf(sc[2*kb  ][0], sc[2*kb  ][1]);
            pf[kb][1] = pk_bf(sc[2*kb  ][2], sc[2*kb  ][3]);
            pf[kb][2] = pk_bf(sc[2*kb+1][0], sc[2*kb+1][1]);
            pf[kb][3] = pk_bf(sc[2*kb+1][2], sc[2*kb+1][3]);
        }

        // O += P @ V  (V via ldmatrix.trans)
        #pragma unroll
        for (int kb = 0; kb < 4; kb++) {
            #pragma unroll
            for (int np = 0; np < 4; np++) {
                uint32_t vd = (uint32_t)__cvta_generic_to_shared(
                    Vs + (kb * 16 + vrow) * ALD + np * 16 + vcol);
                uint32_t q[4];
                ldsm_x4_t(q, vd);
                uint32_t vb0[2] = {q[0], q[1]};
                uint32_t vb1[2] = {q[2], q[3]};
                mma_bf16(ob[np*2  ], pf[kb], vb0);
                mma_bf16(ob[np*2+1], pf[kb], vb1);
            }
        }
        __syncthreads();
    }

    l0 += __shfl_xor_sync(0xffffffffu, l0, 1);
    l0 += __shfl_xor_sync(0xffffffffu, l0, 2);
    l1 += __shfl_xor_sync(0xffffffffu, l1, 1);
    l1 += __shfl_xor_sync(0xffffffffu, l1, 2);
    float inv0 = 1.f / l0, inv1 = 1.f / l1;

    int b = bh / H_, h = bh % H_;
    int r0 = q0 + w * 16 + g;
    __nv_bfloat16* o0 = O + ((size_t)(b * L_ + r0)) * D_ + h * DH_;
    __nv_bfloat16* o1 = O + ((size_t)(b * L_ + r0 + 8)) * D_ + h * DH_;
    #pragma unroll
    for (int n = 0; n < 8; n++) {
        *(__nv_bfloat162*)(o0 + n * 8 + 2 * t4) = __floats2bfloat162_rn(ob[n][0] * inv0, ob[n][1] * inv0);
        *(__nv_bfloat162*)(o1 + n * 8 + 2 * t4) = __floats2bfloat162_rn(ob[n][2] * inv1, ob[n][3] * inv1);
    }
}

// ---------------- host launcher ----------------
extern "C" void kernel_launch(void* const* d_in, const int* in_sizes, int n_in,
                              void* d_out, int out_size) {
    const float* x        = (const float*)d_in[0];
    const float* pos      = (const float*)d_in[1];
    const float* x_cross  = (const float*)d_in[2];
    const float* pos_cross= (const float*)d_in[3];
    const float* sa_norm  = (const float*)d_in[4];
    const float* sa_wqkv  = (const float*)d_in[5];
    const float* sa_scale = (const float*)d_in[6];
    const float* sa_wout  = (const float*)d_in[7];
    const float* ca_norm  = (const float*)d_in[8];
    const float* ca_normc = (const float*)d_in[9];
    const float* ca_wq    = (const float*)d_in[10];
    const float* ca_wkv   = (const float*)d_in[11];
    const float* ca_scale = (const float*)d_in[12];
    const float* ca_wout  = (const float*)d_in[13];
    const float* ff_norm  = (const float*)d_in[14];
    const float* ff_wup   = (const float*)d_in[15];
    const float* ff_wdown = (const float*)d_in[16];
    float* out = (float*)d_out;

    float *x1, *x2;
    __nv_bfloat16 *norm_bf, *normc_bf, *qkv_bf, *lin2_bf, *q_bf, *k_bf, *v_bf, *ao_bf, *ag_bf;
    __nv_bfloat16 *wqkv_bf, *wout1_bf, *wq_bf, *wkv_bf, *wout2_bf, *wup_bf, *wdown_bf;
    cudaGetSymbolAddress((void**)&x1, g_x1);
    cudaGetSymbolAddress((void**)&x2, g_x2);
    cudaGetSymbolAddress((void**)&norm_bf,  g_norm_bf);
    cudaGetSymbolAddress((void**)&normc_bf, g_normc_bf);
    cudaGetSymbolAddress((void**)&qkv_bf,   g_qkv_bf);
    cudaGetSymbolAddress((void**)&lin2_bf,  g_lin2_bf);
    cudaGetSymbolAddress((void**)&q_bf,     g_q_bf);
    cudaGetSymbolAddress((void**)&k_bf,     g_k_bf);
    cudaGetSymbolAddress((void**)&v_bf,     g_v_bf);
    cudaGetSymbolAddress((void**)&ao_bf,    g_ao_bf);
    cudaGetSymbolAddress((void**)&ag_bf,    g_ag_bf);
    cudaGetSymbolAddress((void**)&wqkv_bf,  g_wqkv_bf);
    cudaGetSymbolAddress((void**)&wout1_bf, g_wout1_bf);
    cudaGetSymbolAddress((void**)&wq_bf,    g_wq_bf);
    cudaGetSymbolAddress((void**)&wkv_bf,   g_wkv_bf);
    cudaGetSymbolAddress((void**)&wout2_bf, g_wout2_bf);
    cudaGetSymbolAddress((void**)&wup_bf,   g_wup_bf);
    cudaGetSymbolAddress((void**)&wdown_bf, g_wdown_bf);

    static bool attr_done = false;
    if (!attr_done) {
        cudaFuncSetAttribute(gemm_bf16<0>, cudaFuncAttributeMaxDynamicSharedMemorySize, BF_SMEM);
        cudaFuncSetAttribute(gemm_bf16<1>, cudaFuncAttributeMaxDynamicSharedMemorySize, BF_SMEM);
        cudaFuncSetAttribute(gemm_bf16<2>, cudaFuncAttributeMaxDynamicSharedMemorySize, BF_SMEM);
        attr_done = true;
    }

    // ---- weight conversion (2 launches) ----
    ConvTab t;
    t.src[0] = (const float4*)sa_wqkv;  t.dst[0] = (uint2*)wqkv_bf;  t.n4[0] = 2304*768/4;
    t.src[1] = (const float4*)sa_wout;  t.dst[1] = (uint2*)wout1_bf; t.n4[1] = 768*768/4;
    t.src[2] = (const float4*)ca_wq;    t.dst[2] = (uint2*)wq_bf;    t.n4[2] = 768*768/4;
    t.src[3] = (const float4*)ca_wkv;   t.dst[3] = (uint2*)wkv_bf;   t.n4[3] = 1536*768/4;
    t.src[4] = (const float4*)ca_wout;  t.dst[4] = (uint2*)wout2_bf; t.n4[4] = 768*768/4;
    t.src[5] = (const float4*)ff_wdown; t.dst[5] = (uint2*)wdown_bf; t.n4[5] = 768*2304/4;
    conv6_kernel<<<dim3((2304*768/4 + 255)/256, 6), 256>>>(t);
    convup_kernel<<<(UPN_*(D_/4) + 255)/256, 256>>>(ff_wup, wup_bf);

    const int packBlocks = (B_ * L_ * H_ * 32 + 255) / 256;
    const int vBlocks = (B_ * L_ * H_ * 8 + 255) / 256;

    // ---- self attention ----
    rmsnorm_kernel<<<M_, 256>>>(x, sa_norm, norm_bf);
    gemm_bf16<1><<<dim3(2304/128, M_/128), 256, BF_SMEM>>>(norm_bf, wqkv_bf, nullptr, nullptr, qkv_bf, M_, 2304, D_);
    qk_transform<<<packBlocks, 256>>>(qkv_bf, 2304, 0,    pos, sa_scale, q_bf);
    qk_transform<<<packBlocks, 256>>>(qkv_bf, 2304, 768,  pos, sa_scale, k_bf);
    copy_v     <<<vBlocks, 256>>>(qkv_bf, 2304, 1536, v_bf);
    attn_bf<<<dim3(L_/64, B_*H_), 128>>>(q_bf, k_bf, v_bf, ao_bf);
    gemm_bf16<0><<<dim3(D_/128, M_/128), 256, BF_SMEM>>>(ao_bf, wout1_bf, x, x1, nullptr, M_, D_, D_);

    // ---- cross attention ----
    rmsnorm_kernel<<<M_, 256>>>(x1, ca_norm, norm_bf);
    rmsnorm_kernel<<<M_, 256>>>(x_cross, ca_normc, normc_bf);
    gemm_bf16<1><<<dim3(D_/128, M_/128), 256, BF_SMEM>>>(norm_bf,  wq_bf,  nullptr, nullptr, lin2_bf, M_, D_, D_);
    gemm_bf16<1><<<dim3(1536/128, M_/128), 256, BF_SMEM>>>(normc_bf, wkv_bf, nullptr, nullptr, qkv_bf, M_, 1536, D_);
    qk_transform<<<packBlocks, 256>>>(lin2_bf, 768,  0,   pos,       ca_scale, q_bf);
    qk_transform<<<packBlocks, 256>>>(qkv_bf,  1536, 0,   pos_cross, ca_scale, k_bf);
    copy_v     <<<vBlocks, 256>>>(qkv_bf,  1536, 768, v_bf);
    attn_bf<<<dim3(L_/64, B_*H_), 128>>>(q_bf, k_bf, v_bf, ao_bf);
    gemm_bf16<0><<<dim3(D_/128, M_/128), 256, BF_SMEM>>>(ao_bf, wout2_bf, x1, x2, nullptr, M_, D_, D_);

    // ---- feed forward (silu fused in up-GEMM epilogue) ----
    rmsnorm_kernel<<<M_, 256>>>(x2, ff_norm, norm_bf);
    gemm_bf16<2><<<dim3(UPN_/128, M_/128), 256, BF_SMEM>>>(norm_bf, wup_bf, nullptr, nullptr, ag_bf, M_, UPN_, D_);
    gemm_bf16<0><<<dim3(D_/128, M_/128), 256, BF_SMEM>>>(ag_bf, wdown_bf, x2, out, nullptr, M_, D_, DFF_);
}

// round 8
// speedup vs baseline: 6.9749x; 1.0827x over previous
#include <cuda_runtime.h>
#include <cuda_bf16.h>
#include <cstdint>

#define B_ 2
#define L_ 2048
#define D_ 768
#define H_ 12
#define DH_ 64
#define M_ (B_*L_)
#define DFF_ 2304
#define UPN_ (2*DFF_)

// ---------------- scratch ----------------
__device__ float g_x1 [M_*D_];
__device__ float g_x2 [M_*D_];

__device__ __nv_bfloat16 g_norm_bf [M_*D_];
__device__ __nv_bfloat16 g_normc_bf[M_*D_];
__device__ __nv_bfloat16 g_qkv_bf  [M_*2304];
__device__ __nv_bfloat16 g_lin2_bf [M_*D_];
__device__ __nv_bfloat16 g_q_bf    [B_*H_*L_*DH_];
__device__ __nv_bfloat16 g_k_bf    [B_*H_*L_*DH_];
__device__ __nv_bfloat16 g_v_bf    [B_*H_*L_*DH_];
__device__ __nv_bfloat16 g_ao_bf   [M_*D_];
__device__ __nv_bfloat16 g_ag_bf   [M_*DFF_];

__device__ __nv_bfloat16 g_wqkv_bf [2304*768];
__device__ __nv_bfloat16 g_wout1_bf[768*768];
__device__ __nv_bfloat16 g_wq_bf   [768*768];
__device__ __nv_bfloat16 g_wkv_bf  [1536*768];
__device__ __nv_bfloat16 g_wout2_bf[768*768];
__device__ __nv_bfloat16 g_wup_bf  [4608*768];   // permuted: row 2j=a_j, 2j+1=g_j
__device__ __nv_bfloat16 g_wdown_bf[768*2304];

// ---------------- mma / ldmatrix helpers ----------------
__device__ __forceinline__ void mma_bf16(float c[4], const uint32_t a[4], const uint32_t b[2]) {
    asm volatile("mma.sync.aligned.m16n8k16.row.col.f32.bf16.bf16.f32 "
                 "{%0,%1,%2,%3},{%4,%5,%6,%7},{%8,%9},{%0,%1,%2,%3};\n"
                 : "+f"(c[0]), "+f"(c[1]), "+f"(c[2]), "+f"(c[3])
                 : "r"(a[0]), "r"(a[1]), "r"(a[2]), "r"(a[3]), "r"(b[0]), "r"(b[1]));
}
__device__ __forceinline__ void ldsm_x4(uint32_t r[4], uint32_t addr) {
    asm volatile("ldmatrix.sync.aligned.m8n8.x4.shared.b16 {%0,%1,%2,%3}, [%4];"
                 : "=r"(r[0]), "=r"(r[1]), "=r"(r[2]), "=r"(r[3]) : "r"(addr));
}
__device__ __forceinline__ void ldsm_x4_t(uint32_t r[4], uint32_t addr) {
    asm volatile("ldmatrix.sync.aligned.m8n8.x4.trans.shared.b16 {%0,%1,%2,%3}, [%4];"
                 : "=r"(r[0]), "=r"(r[1]), "=r"(r[2]), "=r"(r[3]) : "r"(addr));
}
__device__ __forceinline__ uint32_t pk_bf(float a, float b) {
    __nv_bfloat162 t = __floats2bfloat162_rn(a, b);
    return *(uint32_t*)&t;
}

// ---------------- fused weight conversion ----------------
struct ConvTab {
    const float4* src[6];
    uint2*        dst[6];
    int           n4[6];
};
__global__ void conv6_kernel(ConvTab t) {
    int r = blockIdx.y;
    int i = blockIdx.x * 256 + threadIdx.x;
    if (i >= t.n4[r]) return;
    float4 v = t.src[r][i];
    __nv_bfloat162 lo = __floats2bfloat162_rn(v.x, v.y);
    __nv_bfloat162 hi = __floats2bfloat162_rn(v.z, v.w);
    uint2 o; o.x = *(uint32_t*)&lo; o.y = *(uint32_t*)&hi;
    t.dst[r][i] = o;
}
__global__ void convup_kernel(const float* __restrict__ src, __nv_bfloat16* __restrict__ dst) {
    int i = blockIdx.x * 256 + threadIdx.x;
    if (i >= UPN_ * (D_ / 4)) return;
    int p  = i / (D_ / 4);
    int kc = (i % (D_ / 4)) * 4;
    int srow = (p & 1) ? (DFF_ + (p >> 1)) : (p >> 1);
    float4 v = *(const float4*)(src + (size_t)srow * D_ + kc);
    __nv_bfloat162 lo = __floats2bfloat162_rn(v.x, v.y);
    __nv_bfloat162 hi = __floats2bfloat162_rn(v.z, v.w);
    uint2 o; o.x = *(uint32_t*)&lo; o.y = *(uint32_t*)&hi;
    *(uint2*)(dst + (size_t)p * D_ + kc) = o;
}

// ---------------- rmsnorm -> bf16 ----------------
__global__ void rmsnorm_kernel(const float* __restrict__ x, const float* __restrict__ sc,
                               __nv_bfloat16* __restrict__ out) {
    int row = blockIdx.x;
    const float* xr = x + (size_t)row * D_;
    float s = 0.f;
    for (int i = threadIdx.x; i < D_; i += 256) { float v = xr[i]; s += v * v; }
    #pragma unroll
    for (int o = 16; o > 0; o >>= 1) s += __shfl_xor_sync(0xffffffffu, s, o);
    __shared__ float red[8];
    __shared__ float rtot;
    if ((threadIdx.x & 31) == 0) red[threadIdx.x >> 5] = s;
    __syncthreads();
    if (threadIdx.x == 0) {
        float t = 0.f;
        #pragma unroll
        for (int i = 0; i < 8; i++) t += red[i];
        rtot = rsqrtf(t / (float)D_ + 1e-6f);
    }
    __syncthreads();
    float r = rtot;
    for (int i = threadIdx.x; i < D_; i += 256)
        out[(size_t)row * D_ + i] = __float2bfloat16(xr[i] * sc[i] * r);
}

// ---------------- bf16 GEMM NT, BK=64, 2-stage.
//  MODE: 0 = f32 out + resid, 1 = bf16 out, 2 = paired silu -> bf16 ---------
#define SLDH 72
#define BF_TILE (128*SLDH)
#define BF_SMEM (2 * 2 * BF_TILE * 2)   // 2 stages * 2 tiles * bytes = 73728

template<int MODE>
__global__ __launch_bounds__(256, 2) void gemm_bf16(const __nv_bfloat16* __restrict__ A,
                                                    const __nv_bfloat16* __restrict__ Bw,
                                                    const float* __restrict__ R,
                                                    float* __restrict__ Cf,
                                                    __nv_bfloat16* __restrict__ Cb,
                                                    int M, int N, int K) {
    extern __shared__ __nv_bfloat16 smh[];
    __nv_bfloat16* As = smh;                  // [2][BF_TILE]
    __nv_bfloat16* Bs = smh + 2 * BF_TILE;    // [2][BF_TILE]

    const int tid = threadIdx.x;
    const int m0 = blockIdx.y * 128, n0 = blockIdx.x * 128;
    const int w = tid >> 5, lane = tid & 31;
    const int wm = w >> 2, wn = w & 3;
    const int g = lane >> 2, t4 = lane & 3;

    const int arow = (lane & 7) + ((lane >> 3) & 1) * 8;
    const int acol = (lane >> 4) * 8;
    const int brow = (lane & 7) + (lane >> 4) * 8;
    const int bcol = ((lane >> 3) & 1) * 8;

    float acc[4][4][4];
    #pragma unroll
    for (int i = 0; i < 4; i++)
        #pragma unroll
        for (int j = 0; j < 4; j++)
            #pragma unroll
            for (int r = 0; r < 4; r++) acc[i][j][r] = 0.f;

    auto load_tiles = [&](int stage, int k0) {
        __nv_bfloat16* as = As + stage * BF_TILE;
        __nv_bfloat16* bs = Bs + stage * BF_TILE;
        #pragma unroll
        for (int i = 0; i < 4; i++) {
            int id = tid + i * 256;            // 1024 chunks of 8 halves per tile
            int r = id >> 3, c = (id & 7) * 8;
            uint32_t sa = (uint32_t)__cvta_generic_to_shared(as + r * SLDH + c);
            const __nv_bfloat16* ga = A + (size_t)(m0 + r) * K + k0 + c;
            asm volatile("cp.async.cg.shared.global [%0], [%1], 16;\n" :: "r"(sa), "l"(ga));
            uint32_t sb = (uint32_t)__cvta_generic_to_shared(bs + r * SLDH + c);
            const __nv_bfloat16* gb = Bw + (size_t)(n0 + r) * K + k0 + c;
            asm volatile("cp.async.cg.shared.global [%0], [%1], 16;\n" :: "r"(sb), "l"(gb));
        }
        asm volatile("cp.async.commit_group;\n");
    };

    const int numK = K >> 6;
    load_tiles(0, 0);

    for (int kt = 0; kt < numK; kt++) {
        if (kt + 1 < numK) {
            load_tiles((kt + 1) & 1, (kt + 1) * 64);
            asm volatile("cp.async.wait_group 1;\n");
        } else {
            asm volatile("cp.async.wait_group 0;\n");
        }
        __syncthreads();

        const __nv_bfloat16* as = As + (kt & 1) * BF_TILE;
        const __nv_bfloat16* bs = Bs + (kt & 1) * BF_TILE;

        #pragma unroll
        for (int kb = 0; kb < 4; kb++) {
            uint32_t af[4][4], bf[4][2];
            #pragma unroll
            for (int mi = 0; mi < 4; mi++) {
                int mr = wm * 64 + mi * 16 + arow;
                uint32_t ad = (uint32_t)__cvta_generic_to_shared(as + mr * SLDH + kb * 16 + acol);
                ldsm_x4(af[mi], ad);
            }
            #pragma unroll
            for (int np = 0; np < 2; np++) {
                int nr = wn * 32 + np * 16 + brow;
                uint32_t bd = (uint32_t)__cvta_generic_to_shared(bs + nr * SLDH + kb * 16 + bcol);
                uint32_t q[4];
                ldsm_x4(q, bd);
                bf[np*2  ][0] = q[0]; bf[np*2  ][1] = q[1];
                bf[np*2+1][0] = q[2]; bf[np*2+1][1] = q[3];
            }
            #pragma unroll
            for (int mi = 0; mi < 4; mi++)
                #pragma unroll
                for (int ni = 0; ni < 4; ni++)
                    mma_bf16(acc[mi][ni], af[mi], bf[ni]);
        }
        __syncthreads();
    }

    #pragma unroll
    for (int mi = 0; mi < 4; mi++) {
        int r0 = m0 + wm * 64 + mi * 16 + g;
        #pragma unroll
        for (int ni = 0; ni < 4; ni++) {
            int cc = n0 + wn * 32 + ni * 8 + 2 * t4;
            float a0 = acc[mi][ni][0], a1 = acc[mi][ni][1];
            float a2 = acc[mi][ni][2], a3 = acc[mi][ni][3];
            if (MODE == 0) {
                float2 r0v = *(const float2*)(R + (size_t)r0 * N + cc);
                float2 r1v = *(const float2*)(R + (size_t)(r0 + 8) * N + cc);
                *(float2*)(Cf + (size_t)r0 * N + cc)       = make_float2(a0 + r0v.x, a1 + r0v.y);
                *(float2*)(Cf + (size_t)(r0 + 8) * N + cc) = make_float2(a2 + r1v.x, a3 + r1v.y);
            } else if (MODE == 1) {
                *(__nv_bfloat162*)(Cb + (size_t)r0 * N + cc)       = __floats2bfloat162_rn(a0, a1);
                *(__nv_bfloat162*)(Cb + (size_t)(r0 + 8) * N + cc) = __floats2bfloat162_rn(a2, a3);
            } else {
                int jj = cc >> 1;
                float s0 = a0 * (a1 / (1.f + __expf(-a1)));
                float s1 = a2 * (a3 / (1.f + __expf(-a3)));
                Cb[(size_t)r0 * DFF_ + jj]       = __float2bfloat16(s0);
                Cb[(size_t)(r0 + 8) * DFF_ + jj] = __float2bfloat16(s1);
            }
        }
    }
}

// ---------------- fused q/k cos-scale+RoPE + v copy ----------------
__device__ __forceinline__ float theta_of(int j, int h, float p0, float p1, float p2) {
    int i = j >> 3, f = j & 7;
    float pc = (i == 0) ? p0 : ((i == 1) ? p1 : p2);
    float freq = 3.14159265358979f * __expf((float)(f * 12 + h) * 0.02398526136f);
    return pc * freq;
}

// one warp: cos-scale + rope a 64-vector staged in shrow, write bf16 to dst
__device__ __forceinline__ void rope_vec(float* shrow, float v0, float v1,
                                         int lane, int h, float sscale,
                                         float p0, float p1, float p2,
                                         __nv_bfloat16* dst) {
    float ss = v0 * v0 + v1 * v1;
    #pragma unroll
    for (int o = 16; o > 0; o >>= 1) ss += __shfl_xor_sync(0xffffffffu, ss, o);
    float f = sscale * rsqrtf(ss + 1e-6f);
    shrow[lane] = v0 * f; shrow[lane + 32] = v1 * f;
    __syncwarp();

    float out0, out1;
    {
        int d = lane;
        if (d < 24) {
            float th = theta_of(d, h, p0, p1, p2);
            float s, c; __sincosf(th, &s, &c);
            out0 = shrow[d] * c - shrow[d + 24] * s;
        } else {
            float th = theta_of(d - 24, h, p0, p1, p2);
            float s, c; __sincosf(th, &s, &c);
            out0 = shrow[d] * c + shrow[d - 24] * s;
        }
    }
    {
        int d = lane + 32;
        if (d < 48) {
            float th = theta_of(d - 24, h, p0, p1, p2);
            float s, c; __sincosf(th, &s, &c);
            out1 = shrow[d] * c + shrow[d - 24] * s;
        } else {
            out1 = shrow[d];
        }
    }
    __syncwarp();
    dst[lane] = __float2bfloat16(out0);
    dst[lane + 32] = __float2bfloat16(out1);
}

__global__ void qkv_pack(const __nv_bfloat16* __restrict__ srcq, int strq, int offq,
                         const __nv_bfloat16* __restrict__ srck, int strk, int offk, int offv,
                         const float* __restrict__ posq, const float* __restrict__ posk,
                         const float* __restrict__ hscale,
                         __nv_bfloat16* __restrict__ dq, __nv_bfloat16* __restrict__ dk,
                         __nv_bfloat16* __restrict__ dv) {
    int wg = (blockIdx.x * blockDim.x + threadIdx.x) >> 5;
    int lane = threadIdx.x & 31;
    if (wg >= B_ * L_ * H_) return;
    int h = wg % H_;
    int bl = wg / H_;
    int b = bl / L_, l = bl % L_;

    __shared__ float sh[8][64];
    float* shrow = sh[threadIdx.x >> 5];
    size_t hdst = ((size_t)(b * H_ + h) * L_ + l) * DH_;

    float s = sqrtf(hscale[h]);
    // q
    {
        const __nv_bfloat16* sp = srcq + (size_t)bl * strq + offq + h * DH_;
        float v0 = __bfloat162float(sp[lane]), v1 = __bfloat162float(sp[lane + 32]);
        float p0 = posq[(size_t)bl * 3 + 0], p1 = posq[(size_t)bl * 3 + 1], p2 = posq[(size_t)bl * 3 + 2];
        rope_vec(shrow, v0, v1, lane, h, s, p0, p1, p2, dq + hdst);
    }
    // k
    {
        const __nv_bfloat16* sp = srck + (size_t)bl * strk + offk + h * DH_;
        float v0 = __bfloat162float(sp[lane]), v1 = __bfloat162float(sp[lane + 32]);
        float p0 = posk[(size_t)bl * 3 + 0], p1 = posk[(size_t)bl * 3 + 1], p2 = posk[(size_t)bl * 3 + 2];
        rope_vec(shrow, v0, v1, lane, h, s, p0, p1, p2, dk + hdst);
    }
    // v copy: 64 halves = 8 uint4; lanes 0..7
    if (lane < 8) {
        *(uint4*)(dv + hdst + lane * 8) =
            *(const uint4*)(srck + (size_t)bl * strk + offv + h * DH_ + lane * 8);
    }
}

// ---------------- bf16 tensor-core flash attention (128 q rows/block) --------
#define ALD 72

__global__ __launch_bounds__(256) void attn_bf(const __nv_bfloat16* __restrict__ Q,
                                               const __nv_bfloat16* __restrict__ K,
                                               const __nv_bfloat16* __restrict__ V,
                                               __nv_bfloat16* __restrict__ O) {
    __shared__ __nv_bfloat16 KVs[128 * ALD];   // Ks = rows 0..63, Vs = rows 64..127
    __nv_bfloat16* Ks = KVs;
    __nv_bfloat16* Vs = KVs + 64 * ALD;

    const int bh = blockIdx.y;
    const int q0 = blockIdx.x * 128;
    const int tid = threadIdx.x;
    const int w = tid >> 5, lane = tid & 31;
    const int g = lane >> 2, t4 = lane & 3;

    const int arow = (lane & 7) + ((lane >> 3) & 1) * 8;
    const int acol = (lane >> 4) * 8;
    const int brow = (lane & 7) + (lane >> 4) * 8;
    const int bcol = ((lane >> 3) & 1) * 8;
    const int vrow = (lane & 7) + ((lane >> 3) & 1) * 8;
    const int vcol = (lane >> 4) * 8;

    // stage Q tile (128 rows) across the whole KVs buffer, build per-warp A frags
    const __nv_bfloat16* qb = Q + ((size_t)bh * L_ + q0) * DH_;
    #pragma unroll
    for (int i = 0; i < 4; i++) {
        int idx = tid + i * 256;                 // 1024 chunks of 8 halves
        int r = idx >> 3, c = (idx & 7) * 8;
        *(uint4*)(KVs + r * ALD + c) = *(const uint4*)(qb + r * 64 + c);
    }
    __syncthreads();
    uint32_t qf[4][4];
    #pragma unroll
    for (int kb = 0; kb < 4; kb++) {
        uint32_t ad = (uint32_t)__cvta_generic_to_shared(
            KVs + (w * 16 + arow) * ALD + kb * 16 + acol);
        ldsm_x4(qf[kb], ad);
    }
    __syncthreads();

    float ob[8][4];
    #pragma unroll
    for (int n = 0; n < 8; n++)
        #pragma unroll
        for (int r = 0; r < 4; r++) ob[n][r] = 0.f;
    float m0 = -1e30f, m1 = -1e30f, l0 = 0.f, l1 = 0.f;

    const __nv_bfloat16* kbase = K + (size_t)bh * L_ * DH_;
    const __nv_bfloat16* vbase = V + (size_t)bh * L_ * DH_;

    for (int kt = 0; kt < L_; kt += 64) {
        #pragma unroll
        for (int i = 0; i < 2; i++) {
            int idx = tid + i * 256;             // 512 chunks per tile
            int r = idx >> 3, c = (idx & 7) * 8;
            *(uint4*)(Ks + r * ALD + c) = *(const uint4*)(kbase + (size_t)(kt + r) * 64 + c);
            *(uint4*)(Vs + r * ALD + c) = *(const uint4*)(vbase + (size_t)(kt + r) * 64 + c);
        }
        __syncthreads();

        // S = Q @ K^T
        float sc[8][4];
        #pragma unroll
        for (int n = 0; n < 8; n++)
            #pragma unroll
            for (int r = 0; r < 4; r++) sc[n][r] = 0.f;
        #pragma unroll
        for (int kb = 0; kb < 4; kb++) {
            uint32_t bf[8][2];
            #pragma unroll
            for (int np = 0; np < 4; np++) {
                uint32_t bd = (uint32_t)__cvta_generic_to_shared(
                    Ks + (np * 16 + brow) * ALD + kb * 16 + bcol);
                uint32_t q[4];
                ldsm_x4(q, bd);
                bf[np*2  ][0] = q[0]; bf[np*2  ][1] = q[1];
                bf[np*2+1][0] = q[2]; bf[np*2+1][1] = q[3];
            }
            #pragma unroll
            for (int n = 0; n < 8; n++)
                mma_bf16(sc[n], qf[kb], bf[n]);
        }

        // online softmax
        float rm0 = -1e30f, rm1 = -1e30f;
        #pragma unroll
        for (int n = 0; n < 8; n++) {
            rm0 = fmaxf(rm0, fmaxf(sc[n][0], sc[n][1]));
            rm1 = fmaxf(rm1, fmaxf(sc[n][2], sc[n][3]));
        }
        rm0 = fmaxf(rm0, __shfl_xor_sync(0xffffffffu, rm0, 1));
        rm0 = fmaxf(rm0, __shfl_xor_sync(0xffffffffu, rm0, 2));
        rm1 = fmaxf(rm1, __shfl_xor_sync(0xffffffffu, rm1, 1));
        rm1 = fmaxf(rm1, __shfl_xor_sync(0xffffffffu, rm1, 2));
        float nm0 = fmaxf(m0, rm0), nm1 = fmaxf(m1, rm1);
        float c0 = __expf(m0 - nm0), c1 = __expf(m1 - nm1);
        m0 = nm0; m1 = nm1;

        float ps0 = 0.f, ps1 = 0.f;
        #pragma unroll
        for (int n = 0; n < 8; n++) {
            sc[n][0] = __expf(sc[n][0] - nm0);
            sc[n][1] = __expf(sc[n][1] - nm0);
            sc[n][2] = __expf(sc[n][2] - nm1);
            sc[n][3] = __expf(sc[n][3] - nm1);
            ps0 += sc[n][0] + sc[n][1];
            ps1 += sc[n][2] + sc[n][3];
        }
        l0 = l0 * c0 + ps0;
        l1 = l1 * c1 + ps1;
        #pragma unroll
        for (int n = 0; n < 8; n++) {
            ob[n][0] *= c0; ob[n][1] *= c0;
            ob[n][2] *= c1; ob[n][3] *= c1;
        }

        // P fragments directly from sc registers
        uint32_t pf[4][4];
        #pragma unroll
        for (int kb = 0; kb < 4; kb++) {
            pf[kb][0] = pk_bf(sc[2*kb  ][0], sc[2*kb  ][1]);
            pf[kb][1] = pk_bf(sc[2*kb  ][2], sc[2*kb  ][3]);
            pf[kb][2] = pk_bf(sc[2*kb+1][0], sc[2*kb+1][1]);
            pf[kb][3] = pk_bf(sc[2*kb+1][2], sc[2*kb+1][3]);
        }

        // O += P @ V
        #pragma unroll
        for (int kb = 0; kb < 4; kb++) {
            #pragma unroll
            for (int np = 0; np < 4; np++) {
                uint32_t vd = (uint32_t)__cvta_generic_to_shared(
                    Vs + (kb * 16 + vrow) * ALD + np * 16 + vcol);
                uint32_t q[4];
                ldsm_x4_t(q, vd);
                uint32_t vb0[2] = {q[0], q[1]};
                uint32_t vb1[2] = {q[2], q[3]};
                mma_bf16(ob[np*2  ], pf[kb], vb0);
                mma_bf16(ob[np*2+1], pf[kb], vb1);
            }
        }
        __syncthreads();
    }

    l0 += __shfl_xor_sync(0xffffffffu, l0, 1);
    l0 += __shfl_xor_sync(0xffffffffu, l0, 2);
    l1 += __shfl_xor_sync(0xffffffffu, l1, 1);
    l1 += __shfl_xor_sync(0xffffffffu, l1, 2);
    float inv0 = 1.f / l0, inv1 = 1.f / l1;

    int b = bh / H_, h = bh % H_;
    int r0 = q0 + w * 16 + g;
    __nv_bfloat16* o0 = O + ((size_t)(b * L_ + r0)) * D_ + h * DH_;
    __nv_bfloat16* o1 = O + ((size_t)(b * L_ + r0 + 8)) * D_ + h * DH_;
    #pragma unroll
    for (int n = 0; n < 8; n++) {
        *(__nv_bfloat162*)(o0 + n * 8 + 2 * t4) = __floats2bfloat162_rn(ob[n][0] * inv0, ob[n][1] * inv0);
        *(__nv_bfloat162*)(o1 + n * 8 + 2 * t4) = __floats2bfloat162_rn(ob[n][2] * inv1, ob[n][3] * inv1);
    }
}

// ---------------- host launcher ----------------
extern "C" void kernel_launch(void* const* d_in, const int* in_sizes, int n_in,
                              void* d_out, int out_size) {
    const float* x        = (const float*)d_in[0];
    const float* pos      = (const float*)d_in[1];
    const float* x_cross  = (const float*)d_in[2];
    const float* pos_cross= (const float*)d_in[3];
    const float* sa_norm  = (const float*)d_in[4];
    const float* sa_wqkv  = (const float*)d_in[5];
    const float* sa_scale = (const float*)d_in[6];
    const float* sa_wout  = (const float*)d_in[7];
    const float* ca_norm  = (const float*)d_in[8];
    const float* ca_normc = (const float*)d_in[9];
    const float* ca_wq    = (const float*)d_in[10];
    const float* ca_wkv   = (const float*)d_in[11];
    const float* ca_scale = (const float*)d_in[12];
    const float* ca_wout  = (const float*)d_in[13];
    const float* ff_norm  = (const float*)d_in[14];
    const float* ff_wup   = (const float*)d_in[15];
    const float* ff_wdown = (const float*)d_in[16];
    float* out = (float*)d_out;

    float *x1, *x2;
    __nv_bfloat16 *norm_bf, *normc_bf, *qkv_bf, *lin2_bf, *q_bf, *k_bf, *v_bf, *ao_bf, *ag_bf;
    __nv_bfloat16 *wqkv_bf, *wout1_bf, *wq_bf, *wkv_bf, *wout2_bf, *wup_bf, *wdown_bf;
    cudaGetSymbolAddress((void**)&x1, g_x1);
    cudaGetSymbolAddress((void**)&x2, g_x2);
    cudaGetSymbolAddress((void**)&norm_bf,  g_norm_bf);
    cudaGetSymbolAddress((void**)&normc_bf, g_normc_bf);
    cudaGetSymbolAddress((void**)&qkv_bf,   g_qkv_bf);
    cudaGetSymbolAddress((void**)&lin2_bf,  g_lin2_bf);
    cudaGetSymbolAddress((void**)&q_bf,     g_q_bf);
    cudaGetSymbolAddress((void**)&k_bf,     g_k_bf);
    cudaGetSymbolAddress((void**)&v_bf,     g_v_bf);
    cudaGetSymbolAddress((void**)&ao_bf,    g_ao_bf);
    cudaGetSymbolAddress((void**)&ag_bf,    g_ag_bf);
    cudaGetSymbolAddress((void**)&wqkv_bf,  g_wqkv_bf);
    cudaGetSymbolAddress((void**)&wout1_bf, g_wout1_bf);
    cudaGetSymbolAddress((void**)&wq_bf,    g_wq_bf);
    cudaGetSymbolAddress((void**)&wkv_bf,   g_wkv_bf);
    cudaGetSymbolAddress((void**)&wout2_bf, g_wout2_bf);
    cudaGetSymbolAddress((void**)&wup_bf,   g_wup_bf);
    cudaGetSymbolAddress((void**)&wdown_bf, g_wdown_bf);

    static bool attr_done = false;
    if (!attr_done) {
        cudaFuncSetAttribute(gemm_bf16<0>, cudaFuncAttributeMaxDynamicSharedMemorySize, BF_SMEM);
        cudaFuncSetAttribute(gemm_bf16<1>, cudaFuncAttributeMaxDynamicSharedMemorySize, BF_SMEM);
        cudaFuncSetAttribute(gemm_bf16<2>, cudaFuncAttributeMaxDynamicSharedMemorySize, BF_SMEM);
        attr_done = true;
    }

    // ---- weight conversion ----
    ConvTab t;
    t.src[0] = (const float4*)sa_wqkv;  t.dst[0] = (uint2*)wqkv_bf;  t.n4[0] = 2304*768/4;
    t.src[1] = (const float4*)sa_wout;  t.dst[1] = (uint2*)wout1_bf; t.n4[1] = 768*768/4;
    t.src[2] = (const float4*)ca_wq;    t.dst[2] = (uint2*)wq_bf;    t.n4[2] = 768*768/4;
    t.src[3] = (const float4*)ca_wkv;   t.dst[3] = (uint2*)wkv_bf;   t.n4[3] = 1536*768/4;
    t.src[4] = (const float4*)ca_wout;  t.dst[4] = (uint2*)wout2_bf; t.n4[4] = 768*768/4;
    t.src[5] = (const float4*)ff_wdown; t.dst[5] = (uint2*)wdown_bf; t.n4[5] = 768*2304/4;
    conv6_kernel<<<dim3((2304*768/4 + 255)/256, 6), 256>>>(t);
    convup_kernel<<<(UPN_*(D_/4) + 255)/256, 256>>>(ff_wup, wup_bf);

    const int packBlocks = (B_ * L_ * H_ * 32 + 255) / 256;

    // ---- self attention ----
    rmsnorm_kernel<<<M_, 256>>>(x, sa_norm, norm_bf);
    gemm_bf16<1><<<dim3(2304/128, M_/128), 256, BF_SMEM>>>(norm_bf, wqkv_bf, nullptr, nullptr, qkv_bf, M_, 2304, D_);
    qkv_pack<<<packBlocks, 256>>>(qkv_bf, 2304, 0, qkv_bf, 2304, 768, 1536,
                                  pos, pos, sa_scale, q_bf, k_bf, v_bf);
    attn_bf<<<dim3(L_/128, B_*H_), 256>>>(q_bf, k_bf, v_bf, ao_bf);
    gemm_bf16<0><<<dim3(D_/128, M_/128), 256, BF_SMEM>>>(ao_bf, wout1_bf, x, x1, nullptr, M_, D_, D_);

    // ---- cross attention ----
    rmsnorm_kernel<<<M_, 256>>>(x1, ca_norm, norm_bf);
    rmsnorm_kernel<<<M_, 256>>>(x_cross, ca_normc, normc_bf);
    gemm_bf16<1><<<dim3(D_/128, M_/128), 256, BF_SMEM>>>(norm_bf,  wq_bf,  nullptr, nullptr, lin2_bf, M_, D_, D_);
    gemm_bf16<1><<<dim3(1536/128, M_/128), 256, BF_SMEM>>>(normc_bf, wkv_bf, nullptr, nullptr, qkv_bf, M_, 1536, D_);
    qkv_pack<<<packBlocks, 256>>>(lin2_bf, 768, 0, qkv_bf, 1536, 0, 768,
                                  pos, pos_cross, ca_scale, q_bf, k_bf, v_bf);
    attn_bf<<<dim3(L_/128, B_*H_), 256>>>(q_bf, k_bf, v_bf, ao_bf);
    gemm_bf16<0><<<dim3(D_/128, M_/128), 256, BF_SMEM>>>(ao_bf, wout2_bf, x1, x2, nullptr, M_, D_, D_);

    // ---- feed forward (silu fused in up-GEMM epilogue) ----
    rmsnorm_kernel<<<M_, 256>>>(x2, ff_norm, norm_bf);
    gemm_bf16<2><<<dim3(UPN_/128, M_/128), 256, BF_SMEM>>>(norm_bf, wup_bf, nullptr, nullptr, ag_bf, M_, UPN_, D_);
    gemm_bf16<0><<<dim3(D_/128, M_/128), 256, BF_SMEM>>>(ag_bf, wdown_bf, x2, out, nullptr, M_, D_, DFF_);
}

// round 10
// speedup vs baseline: 7.1744x; 1.0286x over previous
#include <cuda_runtime.h>
#include <cuda_bf16.h>
#include <cstdint>

#define B_ 2
#define L_ 2048
#define D_ 768
#define H_ 12
#define DH_ 64
#define M_ (B_*L_)
#define DFF_ 2304
#define UPN_ (2*DFF_)

// ---------------- scratch ----------------
__device__ float g_x1 [M_*D_];
__device__ float g_x2 [M_*D_];

__device__ __nv_bfloat16 g_norm_bf [M_*D_];
__device__ __nv_bfloat16 g_normc_bf[M_*D_];
__device__ __nv_bfloat16 g_qkv_bf  [M_*2304];
__device__ __nv_bfloat16 g_lin2_bf [M_*D_];
__device__ __nv_bfloat16 g_q_bf    [B_*H_*L_*DH_];
__device__ __nv_bfloat16 g_k_bf    [B_*H_*L_*DH_];
__device__ __nv_bfloat16 g_v_bf    [B_*H_*L_*DH_];
__device__ __nv_bfloat16 g_ao_bf   [M_*D_];
__device__ __nv_bfloat16 g_ag_bf   [M_*DFF_];

__device__ __nv_bfloat16 g_wqkv_bf [2304*768];
__device__ __nv_bfloat16 g_wout1_bf[768*768];
__device__ __nv_bfloat16 g_wq_bf   [768*768];
__device__ __nv_bfloat16 g_wkv_bf  [1536*768];
__device__ __nv_bfloat16 g_wout2_bf[768*768];
__device__ __nv_bfloat16 g_wup_bf  [4608*768];   // permuted: row 2j=a_j, 2j+1=g_j
__device__ __nv_bfloat16 g_wdown_bf[768*2304];

// ---------------- mma / ldmatrix helpers ----------------
__device__ __forceinline__ void mma_bf16(float c[4], const uint32_t a[4], const uint32_t b[2]) {
    asm volatile("mma.sync.aligned.m16n8k16.row.col.f32.bf16.bf16.f32 "
                 "{%0,%1,%2,%3},{%4,%5,%6,%7},{%8,%9},{%0,%1,%2,%3};\n"
                 : "+f"(c[0]), "+f"(c[1]), "+f"(c[2]), "+f"(c[3])
                 : "r"(a[0]), "r"(a[1]), "r"(a[2]), "r"(a[3]), "r"(b[0]), "r"(b[1]));
}
__device__ __forceinline__ void ldsm_x4(uint32_t r[4], uint32_t addr) {
    asm volatile("ldmatrix.sync.aligned.m8n8.x4.shared.b16 {%0,%1,%2,%3}, [%4];"
                 : "=r"(r[0]), "=r"(r[1]), "=r"(r[2]), "=r"(r[3]) : "r"(addr));
}
__device__ __forceinline__ void ldsm_x4_t(uint32_t r[4], uint32_t addr) {
    asm volatile("ldmatrix.sync.aligned.m8n8.x4.trans.shared.b16 {%0,%1,%2,%3}, [%4];"
                 : "=r"(r[0]), "=r"(r[1]), "=r"(r[2]), "=r"(r[3]) : "r"(addr));
}
__device__ __forceinline__ uint32_t pk_bf(float a, float b) {
    __nv_bfloat162 t = __floats2bfloat162_rn(a, b);
    return *(uint32_t*)&t;
}

// ---------------- fused weight conversion ----------------
struct ConvTab {
    const float4* src[6];
    uint2*        dst[6];
    int           n4[6];
};
__global__ void conv6_kernel(ConvTab t) {
    int r = blockIdx.y;
    int i = blockIdx.x * 256 + threadIdx.x;
    if (i >= t.n4[r]) return;
    float4 v = t.src[r][i];
    __nv_bfloat162 lo = __floats2bfloat162_rn(v.x, v.y);
    __nv_bfloat162 hi = __floats2bfloat162_rn(v.z, v.w);
    uint2 o; o.x = *(uint32_t*)&lo; o.y = *(uint32_t*)&hi;
    t.dst[r][i] = o;
}
__global__ void convup_kernel(const float* __restrict__ src, __nv_bfloat16* __restrict__ dst) {
    int i = blockIdx.x * 256 + threadIdx.x;
    if (i >= UPN_ * (D_ / 4)) return;
    int p  = i / (D_ / 4);
    int kc = (i % (D_ / 4)) * 4;
    int srow = (p & 1) ? (DFF_ + (p >> 1)) : (p >> 1);
    float4 v = *(const float4*)(src + (size_t)srow * D_ + kc);
    __nv_bfloat162 lo = __floats2bfloat162_rn(v.x, v.y);
    __nv_bfloat162 hi = __floats2bfloat162_rn(v.z, v.w);
    uint2 o; o.x = *(uint32_t*)&lo; o.y = *(uint32_t*)&hi;
    *(uint2*)(dst + (size_t)p * D_ + kc) = o;
}

// ---------------- rmsnorm -> bf16 ----------------
__global__ void rmsnorm_kernel(const float* __restrict__ x, const float* __restrict__ sc,
                               __nv_bfloat16* __restrict__ out) {
    int row = blockIdx.x;
    const float* xr = x + (size_t)row * D_;
    float s = 0.f;
    for (int i = threadIdx.x; i < D_; i += 256) { float v = xr[i]; s += v * v; }
    #pragma unroll
    for (int o = 16; o > 0; o >>= 1) s += __shfl_xor_sync(0xffffffffu, s, o);
    __shared__ float red[8];
    __shared__ float rtot;
    if ((threadIdx.x & 31) == 0) red[threadIdx.x >> 5] = s;
    __syncthreads();
    if (threadIdx.x == 0) {
        float t = 0.f;
        #pragma unroll
        for (int i = 0; i < 8; i++) t += red[i];
        rtot = rsqrtf(t / (float)D_ + 1e-6f);
    }
    __syncthreads();
    float r = rtot;
    for (int i = threadIdx.x; i < D_; i += 256)
        out[(size_t)row * D_ + i] = __float2bfloat16(xr[i] * sc[i] * r);
}

// ---------------- bf16 GEMM NT, BK=64, 2-stage, BM in {64,128}.
//  MODE: 0 = f32 out + resid, 1 = bf16 out, 2 = paired silu -> bf16 ---------
#define SLDH 72
#define GSMEM(BM) (2 * ((BM) + 128) * SLDH * 2)

template<int BM, int MODE>
__global__ __launch_bounds__(256, BM == 64 ? 3 : 2)
void gemm_bf16(const __nv_bfloat16* __restrict__ A,
               const __nv_bfloat16* __restrict__ Bw,
               const float* __restrict__ R,
               float* __restrict__ Cf,
               __nv_bfloat16* __restrict__ Cb,
               int M, int N, int K) {
    extern __shared__ __nv_bfloat16 smh[];
    constexpr int ATILE = BM * SLDH;
    constexpr int BTILE = 128 * SLDH;
    constexpr int MI = BM / 32;               // m-fragment count per warp
    __nv_bfloat16* As = smh;                  // [2][ATILE]
    __nv_bfloat16* Bs = smh + 2 * ATILE;      // [2][BTILE]

    const int tid = threadIdx.x;
    const int m0 = blockIdx.y * BM, n0 = blockIdx.x * 128;
    const int w = tid >> 5, lane = tid & 31;
    const int wm = w >> 2, wn = w & 3;
    const int g = lane >> 2, t4 = lane & 3;

    const int arow = (lane & 7) + ((lane >> 3) & 1) * 8;
    const int acol = (lane >> 4) * 8;
    const int brow = (lane & 7) + (lane >> 4) * 8;
    const int bcol = ((lane >> 3) & 1) * 8;

    float acc[MI][4][4];
    #pragma unroll
    for (int i = 0; i < MI; i++)
        #pragma unroll
        for (int j = 0; j < 4; j++)
            #pragma unroll
            for (int r = 0; r < 4; r++) acc[i][j][r] = 0.f;

    auto load_tiles = [&](int stage, int k0) {
        __nv_bfloat16* as = As + stage * ATILE;
        __nv_bfloat16* bs = Bs + stage * BTILE;
        #pragma unroll
        for (int i = 0; i < BM / 32; i++) {
            int id = tid + i * 256;
            int r = id >> 3, c = (id & 7) * 8;
            uint32_t sa = (uint32_t)__cvta_generic_to_shared(as + r * SLDH + c);
            const __nv_bfloat16* ga = A + (size_t)(m0 + r) * K + k0 + c;
            asm volatile("cp.async.cg.shared.global [%0], [%1], 16;\n" :: "r"(sa), "l"(ga));
        }
        #pragma unroll
        for (int i = 0; i < 4; i++) {
            int id = tid + i * 256;
            int r = id >> 3, c = (id & 7) * 8;
            uint32_t sb = (uint32_t)__cvta_generic_to_shared(bs + r * SLDH + c);
            const __nv_bfloat16* gb = Bw + (size_t)(n0 + r) * K + k0 + c;
            asm volatile("cp.async.cg.shared.global [%0], [%1], 16;\n" :: "r"(sb), "l"(gb));
        }
        asm volatile("cp.async.commit_group;\n");
    };

    const int numK = K >> 6;
    load_tiles(0, 0);

    for (int kt = 0; kt < numK; kt++) {
        if (kt + 1 < numK) {
            load_tiles((kt + 1) & 1, (kt + 1) * 64);
            asm volatile("cp.async.wait_group 1;\n");
        } else {
            asm volatile("cp.async.wait_group 0;\n");
        }
        __syncthreads();

        const __nv_bfloat16* as = As + (kt & 1) * ATILE;
        const __nv_bfloat16* bs = Bs + (kt & 1) * BTILE;

        #pragma unroll
        for (int kb = 0; kb < 4; kb++) {
            uint32_t af[MI][4], bf[4][2];
            #pragma unroll
            for (int mi = 0; mi < MI; mi++) {
                int mr = wm * (BM / 2) + mi * 16 + arow;
                uint32_t ad = (uint32_t)__cvta_generic_to_shared(as + mr * SLDH + kb * 16 + acol);
                ldsm_x4(af[mi], ad);
            }
            #pragma unroll
            for (int np = 0; np < 2; np++) {
                int nr = wn * 32 + np * 16 + brow;
                uint32_t bd = (uint32_t)__cvta_generic_to_shared(bs + nr * SLDH + kb * 16 + bcol);
                uint32_t q[4];
                ldsm_x4(q, bd);
                bf[np*2  ][0] = q[0]; bf[np*2  ][1] = q[1];
                bf[np*2+1][0] = q[2]; bf[np*2+1][1] = q[3];
            }
            #pragma unroll
            for (int mi = 0; mi < MI; mi++)
                #pragma unroll
                for (int ni = 0; ni < 4; ni++)
                    mma_bf16(acc[mi][ni], af[mi], bf[ni]);
        }
        __syncthreads();
    }

    #pragma unroll
    for (int mi = 0; mi < MI; mi++) {
        int r0 = m0 + wm * (BM / 2) + mi * 16 + g;
        #pragma unroll
        for (int ni = 0; ni < 4; ni++) {
            int cc = n0 + wn * 32 + ni * 8 + 2 * t4;
            float a0 = acc[mi][ni][0], a1 = acc[mi][ni][1];
            float a2 = acc[mi][ni][2], a3 = acc[mi][ni][3];
            if (MODE == 0) {
                float2 r0v = *(const float2*)(R + (size_t)r0 * N + cc);
                float2 r1v = *(const float2*)(R + (size_t)(r0 + 8) * N + cc);
                *(float2*)(Cf + (size_t)r0 * N + cc)       = make_float2(a0 + r0v.x, a1 + r0v.y);
                *(float2*)(Cf + (size_t)(r0 + 8) * N + cc) = make_float2(a2 + r1v.x, a3 + r1v.y);
            } else if (MODE == 1) {
                *(__nv_bfloat162*)(Cb + (size_t)r0 * N + cc)       = __floats2bfloat162_rn(a0, a1);
                *(__nv_bfloat162*)(Cb + (size_t)(r0 + 8) * N + cc) = __floats2bfloat162_rn(a2, a3);
            } else {
                int jj = cc >> 1;
                float s0 = a0 * (a1 / (1.f + __expf(-a1)));
                float s1 = a2 * (a3 / (1.f + __expf(-a3)));
                Cb[(size_t)r0 * DFF_ + jj]       = __float2bfloat16(s0);
                Cb[(size_t)(r0 + 8) * DFF_ + jj] = __float2bfloat16(s1);
            }
        }
    }
}

// ---------------- fused q/k cos-scale+RoPE + v copy ----------------
__device__ __forceinline__ float theta_of(int j, int h, float p0, float p1, float p2) {
    int i = j >> 3, f = j & 7;
    float pc = (i == 0) ? p0 : ((i == 1) ? p1 : p2);
    float freq = 3.14159265358979f * __expf((float)(f * 12 + h) * 0.02398526136f);
    return pc * freq;
}

__device__ __forceinline__ void rope_vec(float* shrow, float v0, float v1,
                                         int lane, int h, float sscale,
                                         float p0, float p1, float p2,
                                         __nv_bfloat16* dst) {
    float ss = v0 * v0 + v1 * v1;
    #pragma unroll
    for (int o = 16; o > 0; o >>= 1) ss += __shfl_xor_sync(0xffffffffu, ss, o);
    float f = sscale * rsqrtf(ss + 1e-6f);
    shrow[lane] = v0 * f; shrow[lane + 32] = v1 * f;
    __syncwarp();

    float out0, out1;
    {
        int d = lane;
        if (d < 24) {
            float th = theta_of(d, h, p0, p1, p2);
            float s, c; __sincosf(th, &s, &c);
            out0 = shrow[d] * c - shrow[d + 24] * s;
        } else {
            float th = theta_of(d - 24, h, p0, p1, p2);
            float s, c; __sincosf(th, &s, &c);
            out0 = shrow[d] * c + shrow[d - 24] * s;
        }
    }
    {
        int d = lane + 32;
        if (d < 48) {
            float th = theta_of(d - 24, h, p0, p1, p2);
            float s, c; __sincosf(th, &s, &c);
            out1 = shrow[d] * c + shrow[d - 24] * s;
        } else {
            out1 = shrow[d];
        }
    }
    __syncwarp();
    dst[lane] = __float2bfloat16(out0);
    dst[lane + 32] = __float2bfloat16(out1);
}

__global__ void qkv_pack(const __nv_bfloat16* __restrict__ srcq, int strq, int offq,
                         const __nv_bfloat16* __restrict__ srck, int strk, int offk, int offv,
                         const float* __restrict__ posq, const float* __restrict__ posk,
                         const float* __restrict__ hscale,
                         __nv_bfloat16* __restrict__ dq, __nv_bfloat16* __restrict__ dk,
                         __nv_bfloat16* __restrict__ dv) {
    int wg = (blockIdx.x * blockDim.x + threadIdx.x) >> 5;
    int lane = threadIdx.x & 31;
    if (wg >= B_ * L_ * H_) return;
    int h = wg % H_;
    int bl = wg / H_;
    int b = bl / L_, l = bl % L_;

    __shared__ float sh[8][64];
    float* shrow = sh[threadIdx.x >> 5];
    size_t hdst = ((size_t)(b * H_ + h) * L_ + l) * DH_;

    float s = sqrtf(hscale[h]);
    {
        const __nv_bfloat16* sp = srcq + (size_t)bl * strq + offq + h * DH_;
        float v0 = __bfloat162float(sp[lane]), v1 = __bfloat162float(sp[lane + 32]);
        float p0 = posq[(size_t)bl * 3 + 0], p1 = posq[(size_t)bl * 3 + 1], p2 = posq[(size_t)bl * 3 + 2];
        rope_vec(shrow, v0, v1, lane, h, s, p0, p1, p2, dq + hdst);
    }
    {
        const __nv_bfloat16* sp = srck + (size_t)bl * strk + offk + h * DH_;
        float v0 = __bfloat162float(sp[lane]), v1 = __bfloat162float(sp[lane + 32]);
        float p0 = posk[(size_t)bl * 3 + 0], p1 = posk[(size_t)bl * 3 + 1], p2 = posk[(size_t)bl * 3 + 2];
        rope_vec(shrow, v0, v1, lane, h, s, p0, p1, p2, dk + hdst);
    }
    if (lane < 8) {
        *(uint4*)(dv + hdst + lane * 8) =
            *(const uint4*)(srck + (size_t)bl * strk + offv + h * DH_ + lane * 8);
    }
}

// ---------------- bf16 tensor-core flash attention (128 q rows/block) --------
#define ALD 72

__global__ __launch_bounds__(256) void attn_bf(const __nv_bfloat16* __restrict__ Q,
                                               const __nv_bfloat16* __restrict__ K,
                                               const __nv_bfloat16* __restrict__ V,
                                               __nv_bfloat16* __restrict__ O) {
    __shared__ __nv_bfloat16 KVs[128 * ALD];
    __nv_bfloat16* Ks = KVs;
    __nv_bfloat16* Vs = KVs + 64 * ALD;

    const int bh = blockIdx.y;
    const int q0 = blockIdx.x * 128;
    const int tid = threadIdx.x;
    const int w = tid >> 5, lane = tid & 31;
    const int g = lane >> 2, t4 = lane & 3;

    const int arow = (lane & 7) + ((lane >> 3) & 1) * 8;
    const int acol = (lane >> 4) * 8;
    const int brow = (lane & 7) + (lane >> 4) * 8;
    const int bcol = ((lane >> 3) & 1) * 8;
    const int vrow = (lane & 7) + ((lane >> 3) & 1) * 8;
    const int vcol = (lane >> 4) * 8;

    const __nv_bfloat16* qb = Q + ((size_t)bh * L_ + q0) * DH_;
    #pragma unroll
    for (int i = 0; i < 4; i++) {
        int idx = tid + i * 256;
        int r = idx >> 3, c = (idx & 7) * 8;
        *(uint4*)(KVs + r * ALD + c) = *(const uint4*)(qb + r * 64 + c);
    }
    __syncthreads();
    uint32_t qf[4][4];
    #pragma unroll
    for (int kb = 0; kb < 4; kb++) {
        uint32_t ad = (uint32_t)__cvta_generic_to_shared(
            KVs + (w * 16 + arow) * ALD + kb * 16 + acol);
        ldsm_x4(qf[kb], ad);
    }
    __syncthreads();

    float ob[8][4];
    #pragma unroll
    for (int n = 0; n < 8; n++)
        #pragma unroll
        for (int r = 0; r < 4; r++) ob[n][r] = 0.f;
    float m0 = -1e30f, m1 = -1e30f, l0 = 0.f, l1 = 0.f;

    const __nv_bfloat16* kbase = K + (size_t)bh * L_ * DH_;
    const __nv_bfloat16* vbase = V + (size_t)bh * L_ * DH_;

    for (int kt = 0; kt < L_; kt += 64) {
        #pragma unroll
        for (int i = 0; i < 2; i++) {
            int idx = tid + i * 256;
            int r = idx >> 3, c = (idx & 7) * 8;
            *(uint4*)(Ks + r * ALD + c) = *(const uint4*)(kbase + (size_t)(kt + r) * 64 + c);
            *(uint4*)(Vs + r * ALD + c) = *(const uint4*)(vbase + (size_t)(kt + r) * 64 + c);
        }
        __syncthreads();

        float sc[8][4];
        #pragma unroll
        for (int n = 0; n < 8; n++)
            #pragma unroll
            for (int r = 0; r < 4; r++) sc[n][r] = 0.f;
        #pragma unroll
        for (int kb = 0; kb < 4; kb++) {
            uint32_t bf[8][2];
            #pragma unroll
            for (int np = 0; np < 4; np++) {
                uint32_t bd = (uint32_t)__cvta_generic_to_shared(
                    Ks + (np * 16 + brow) * ALD + kb * 16 + bcol);
                uint32_t q[4];
                ldsm_x4(q, bd);
                bf[np*2  ][0] = q[0]; bf[np*2  ][1] = q[1];
                bf[np*2+1][0] = q[2]; bf[np*2+1][1] = q[3];
            }
            #pragma unroll
            for (int n = 0; n < 8; n++)
                mma_bf16(sc[n], qf[kb], bf[n]);
        }

        float rm0 = -1e30f, rm1 = -1e30f;
        #pragma unroll
        for (int n = 0; n < 8; n++) {
            rm0 = fmaxf(rm0, fmaxf(sc[n][0], sc[n][1]));
            rm1 = fmaxf(rm1, fmaxf(sc[n][2], sc[n][3]));
        }
        rm0 = fmaxf(rm0, __shfl_xor_sync(0xffffffffu, rm0, 1));
        rm0 = fmaxf(rm0, __shfl_xor_sync(0xffffffffu, rm0, 2));
        rm1 = fmaxf(rm1, __shfl_xor_sync(0xffffffffu, rm1, 1));
        rm1 = fmaxf(rm1, __shfl_xor_sync(0xffffffffu, rm1, 2));
        float nm0 = fmaxf(m0, rm0), nm1 = fmaxf(m1, rm1);
        float c0 = __expf(m0 - nm0), c1 = __expf(m1 - nm1);
        m0 = nm0; m1 = nm1;

        float ps0 = 0.f, ps1 = 0.f;
        #pragma unroll
        for (int n = 0; n < 8; n++) {
            sc[n][0] = __expf(sc[n][0] - nm0);
            sc[n][1] = __expf(sc[n][1] - nm0);
            sc[n][2] = __expf(sc[n][2] - nm1);
            sc[n][3] = __expf(sc[n][3] - nm1);
            ps0 += sc[n][0] + sc[n][1];
            ps1 += sc[n][2] + sc[n][3];
        }
        l0 = l0 * c0 + ps0;
        l1 = l1 * c1 + ps1;
        #pragma unroll
        for (int n = 0; n < 8; n++) {
            ob[n][0] *= c0; ob[n][1] *= c0;
            ob[n][2] *= c1; ob[n][3] *= c1;
        }

        uint32_t pf[4][4];
        #pragma unroll
        for (int kb = 0; kb < 4; kb++) {
            pf[kb][0] = pk_bf(sc[2*kb  ][0], sc[2*kb  ][1]);
            pf[kb][1] = pk_bf(sc[2*kb  ][2], sc[2*kb  ][3]);
            pf[kb][2] = pk_bf(sc[2*kb+1][0], sc[2*kb+1][1]);
            pf[kb][3] = pk_bf(sc[2*kb+1][2], sc[2*kb+1][3]);
        }

        #pragma unroll
        for (int kb = 0; kb < 4; kb++) {
            #pragma unroll
            for (int np = 0; np < 4; np++) {
                uint32_t vd = (uint32_t)__cvta_generic_to_shared(
                    Vs + (kb * 16 + vrow) * ALD + np * 16 + vcol);
                uint32_t q[4];
                ldsm_x4_t(q, vd);
                uint32_t vb0[2] = {q[0], q[1]};
                uint32_t vb1[2] = {q[2], q[3]};
                mma_bf16(ob[np*2  ], pf[kb], vb0);
                mma_bf16(ob[np*2+1], pf[kb], vb1);
            }
        }
        __syncthreads();
    }

    l0 += __shfl_xor_sync(0xffffffffu, l0, 1);
    l0 += __shfl_xor_sync(0xffffffffu, l0, 2);
    l1 += __shfl_xor_sync(0xffffffffu, l1, 1);
    l1 += __shfl_xor_sync(0xffffffffu, l1, 2);
    float inv0 = 1.f / l0, inv1 = 1.f / l1;

    int b = bh / H_, h = bh % H_;
    int r0 = q0 + w * 16 + g;
    __nv_bfloat16* o0 = O + ((size_t)(b * L_ + r0)) * D_ + h * DH_;
    __nv_bfloat16* o1 = O + ((size_t)(b * L_ + r0 + 8)) * D_ + h * DH_;
    #pragma unroll
    for (int n = 0; n < 8; n++) {
        *(__nv_bfloat162*)(o0 + n * 8 + 2 * t4) = __floats2bfloat162_rn(ob[n][0] * inv0, ob[n][1] * inv0);
        *(__nv_bfloat162*)(o1 + n * 8 + 2 * t4) = __floats2bfloat162_rn(ob[n][2] * inv1, ob[n][3] * inv1);
    }
}

// ---------------- host launcher ----------------
extern "C" void kernel_launch(void* const* d_in, const int* in_sizes, int n_in,
                              void* d_out, int out_size) {
    const float* x        = (const float*)d_in[0];
    const float* pos      = (const float*)d_in[1];
    const float* x_cross  = (const float*)d_in[2];
    const float* pos_cross= (const float*)d_in[3];
    const float* sa_norm  = (const float*)d_in[4];
    const float* sa_wqkv  = (const float*)d_in[5];
    const float* sa_scale = (const float*)d_in[6];
    const float* sa_wout  = (const float*)d_in[7];
    const float* ca_norm  = (const float*)d_in[8];
    const float* ca_normc = (const float*)d_in[9];
    const float* ca_wq    = (const float*)d_in[10];
    const float* ca_wkv   = (const float*)d_in[11];
    const float* ca_scale = (const float*)d_in[12];
    const float* ca_wout  = (const float*)d_in[13];
    const float* ff_norm  = (const float*)d_in[14];
    const float* ff_wup   = (const float*)d_in[15];
    const float* ff_wdown = (const float*)d_in[16];
    float* out = (float*)d_out;

    float *x1, *x2;
    __nv_bfloat16 *norm_bf, *normc_bf, *qkv_bf, *lin2_bf, *q_bf, *k_bf, *v_bf, *ao_bf, *ag_bf;
    __nv_bfloat16 *wqkv_bf, *wout1_bf, *wq_bf, *wkv_bf, *wout2_bf, *wup_bf, *wdown_bf;
    cudaGetSymbolAddress((void**)&x1, g_x1);
    cudaGetSymbolAddress((void**)&x2, g_x2);
    cudaGetSymbolAddress((void**)&norm_bf,  g_norm_bf);
    cudaGetSymbolAddress((void**)&normc_bf, g_normc_bf);
    cudaGetSymbolAddress((void**)&qkv_bf,   g_qkv_bf);
    cudaGetSymbolAddress((void**)&lin2_bf,  g_lin2_bf);
    cudaGetSymbolAddress((void**)&q_bf,     g_q_bf);
    cudaGetSymbolAddress((void**)&k_bf,     g_k_bf);
    cudaGetSymbolAddress((void**)&v_bf,     g_v_bf);
    cudaGetSymbolAddress((void**)&ao_bf,    g_ao_bf);
    cudaGetSymbolAddress((void**)&ag_bf,    g_ag_bf);
    cudaGetSymbolAddress((void**)&wqkv_bf,  g_wqkv_bf);
    cudaGetSymbolAddress((void**)&wout1_bf, g_wout1_bf);
    cudaGetSymbolAddress((void**)&wq_bf,    g_wq_bf);
    cudaGetSymbolAddress((void**)&wkv_bf,   g_wkv_bf);
    cudaGetSymbolAddress((void**)&wout2_bf, g_wout2_bf);
    cudaGetSymbolAddress((void**)&wup_bf,   g_wup_bf);
    cudaGetSymbolAddress((void**)&wdown_bf, g_wdown_bf);

    static bool attr_done = false;
    if (!attr_done) {
        cudaFuncSetAttribute((const void*)gemm_bf16<128,1>, cudaFuncAttributeMaxDynamicSharedMemorySize, GSMEM(128));
        cudaFuncSetAttribute((const void*)gemm_bf16<128,2>, cudaFuncAttributeMaxDynamicSharedMemorySize, GSMEM(128));
        cudaFuncSetAttribute((const void*)gemm_bf16<64,0>,  cudaFuncAttributeMaxDynamicSharedMemorySize, GSMEM(64));
        cudaFuncSetAttribute((const void*)gemm_bf16<64,1>,  cudaFuncAttributeMaxDynamicSharedMemorySize, GSMEM(64));
        attr_done = true;
    }

    // ---- weight conversion ----
    ConvTab t;
    t.src[0] = (const float4*)sa_wqkv;  t.dst[0] = (uint2*)wqkv_bf;  t.n4[0] = 2304*768/4;
    t.src[1] = (const float4*)sa_wout;  t.dst[1] = (uint2*)wout1_bf; t.n4[1] = 768*768/4;
    t.src[2] = (const float4*)ca_wq;    t.dst[2] = (uint2*)wq_bf;    t.n4[2] = 768*768/4;
    t.src[3] = (const float4*)ca_wkv;   t.dst[3] = (uint2*)wkv_bf;   t.n4[3] = 1536*768/4;
    t.src[4] = (const float4*)ca_wout;  t.dst[4] = (uint2*)wout2_bf; t.n4[4] = 768*768/4;
    t.src[5] = (const float4*)ff_wdown; t.dst[5] = (uint2*)wdown_bf; t.n4[5] = 768*2304/4;
    conv6_kernel<<<dim3((2304*768/4 + 255)/256, 6), 256>>>(t);
    convup_kernel<<<(UPN_*(D_/4) + 255)/256, 256>>>(ff_wup, wup_bf);

    const int packBlocks = (B_ * L_ * H_ * 32 + 255) / 256;

    // ---- self attention ----
    rmsnorm_kernel<<<M_, 256>>>(x, sa_norm, norm_bf);
    gemm_bf16<128,1><<<dim3(2304/128, M_/128), 256, GSMEM(128)>>>(norm_bf, wqkv_bf, nullptr, nullptr, qkv_bf, M_, 2304, D_);
    qkv_pack<<<packBlocks, 256>>>(qkv_bf, 2304, 0, qkv_bf, 2304, 768, 1536,
                                  pos, pos, sa_scale, q_bf, k_bf, v_bf);
    attn_bf<<<dim3(L_/128, B_*H_), 256>>>(q_bf, k_bf, v_bf, ao_bf);
    gemm_bf16<64,0><<<dim3(D_/128, M_/64), 256, GSMEM(64)>>>(ao_bf, wout1_bf, x, x1, nullptr, M_, D_, D_);

    // ---- cross attention ----
    rmsnorm_kernel<<<M_, 256>>>(x1, ca_norm, norm_bf);
    rmsnorm_kernel<<<M_, 256>>>(x_cross, ca_normc, normc_bf);
    gemm_bf16<64,1><<<dim3(D_/128, M_/64), 256, GSMEM(64)>>>(norm_bf,  wq_bf,  nullptr, nullptr, lin2_bf, M_, D_, D_);
    gemm_bf16<128,1><<<dim3(1536/128, M_/128), 256, GSMEM(128)>>>(normc_bf, wkv_bf, nullptr, nullptr, qkv_bf, M_, 1536, D_);
    qkv_pack<<<packBlocks, 256>>>(lin2_bf, 768, 0, qkv_bf, 1536, 0, 768,
                                  pos, pos_cross, ca_scale, q_bf, k_bf, v_bf);
    attn_bf<<<dim3(L_/128, B_*H_), 256>>>(q_bf, k_bf, v_bf, ao_bf);
    gemm_bf16<64,0><<<dim3(D_/128, M_/64), 256, GSMEM(64)>>>(ao_bf, wout2_bf, x1, x2, nullptr, M_, D_, D_);

    // ---- feed forward (silu fused in up-GEMM epilogue) ----
    rmsnorm_kernel<<<M_, 256>>>(x2, ff_norm, norm_bf);
    gemm_bf16<128,2><<<dim3(UPN_/128, M_/128), 256, GSMEM(128)>>>(norm_bf, wup_bf, nullptr, nullptr, ag_bf, M_, UPN_, D_);
    gemm_bf16<64,0><<<dim3(D_/128, M_/64), 256, GSMEM(64)>>>(ag_bf, wdown_bf, x2, out, nullptr, M_, D_, DFF_);
}

// round 11
// speedup vs baseline: 7.3999x; 1.0314x over previous
#include <cuda_runtime.h>
#include <cuda_bf16.h>
#include <cstdint>

#define B_ 2
#define L_ 2048
#define D_ 768
#define H_ 12
#define DH_ 64
#define M_ (B_*L_)
#define DFF_ 2304
#define UPN_ (2*DFF_)

// ---------------- scratch ----------------
__device__ float g_x1 [M_*D_];
__device__ float g_x2 [M_*D_];

__device__ __nv_bfloat16 g_norm_bf [M_*D_];
__device__ __nv_bfloat16 g_normc_bf[M_*D_];
__device__ __nv_bfloat16 g_qkv_bf  [M_*2304];
__device__ __nv_bfloat16 g_lin2_bf [M_*D_];
__device__ __nv_bfloat16 g_q_bf    [B_*H_*L_*DH_];
__device__ __nv_bfloat16 g_k_bf    [B_*H_*L_*DH_];
__device__ __nv_bfloat16 g_v_bf    [B_*H_*L_*DH_];
__device__ __nv_bfloat16 g_ao_bf   [M_*D_];
__device__ __nv_bfloat16 g_ag_bf   [M_*DFF_];

__device__ __nv_bfloat16 g_wqkv_bf [2304*768];
__device__ __nv_bfloat16 g_wout1_bf[768*768];
__device__ __nv_bfloat16 g_wq_bf   [768*768];
__device__ __nv_bfloat16 g_wkv_bf  [1536*768];
__device__ __nv_bfloat16 g_wout2_bf[768*768];
__device__ __nv_bfloat16 g_wup_bf  [4608*768];   // permuted: row 2j=a_j, 2j+1=g_j
__device__ __nv_bfloat16 g_wdown_bf[768*2304];

// ---------------- mma / ldmatrix helpers ----------------
__device__ __forceinline__ void mma_bf16(float c[4], const uint32_t a[4], const uint32_t b[2]) {
    asm volatile("mma.sync.aligned.m16n8k16.row.col.f32.bf16.bf16.f32 "
                 "{%0,%1,%2,%3},{%4,%5,%6,%7},{%8,%9},{%0,%1,%2,%3};\n"
                 : "+f"(c[0]), "+f"(c[1]), "+f"(c[2]), "+f"(c[3])
                 : "r"(a[0]), "r"(a[1]), "r"(a[2]), "r"(a[3]), "r"(b[0]), "r"(b[1]));
}
__device__ __forceinline__ void ldsm_x4(uint32_t r[4], uint32_t addr) {
    asm volatile("ldmatrix.sync.aligned.m8n8.x4.shared.b16 {%0,%1,%2,%3}, [%4];"
                 : "=r"(r[0]), "=r"(r[1]), "=r"(r[2]), "=r"(r[3]) : "r"(addr));
}
__device__ __forceinline__ void ldsm_x4_t(uint32_t r[4], uint32_t addr) {
    asm volatile("ldmatrix.sync.aligned.m8n8.x4.trans.shared.b16 {%0,%1,%2,%3}, [%4];"
                 : "=r"(r[0]), "=r"(r[1]), "=r"(r[2]), "=r"(r[3]) : "r"(addr));
}
__device__ __forceinline__ uint32_t pk_bf(float a, float b) {
    __nv_bfloat162 t = __floats2bfloat162_rn(a, b);
    return *(uint32_t*)&t;
}

// ---------------- fused weight conversion ----------------
struct ConvTab {
    const float4* src[6];
    uint2*        dst[6];
    int           n4[6];
};
__global__ void conv6_kernel(ConvTab t) {
    int r = blockIdx.y;
    int i = blockIdx.x * 256 + threadIdx.x;
    if (i >= t.n4[r]) return;
    float4 v = t.src[r][i];
    __nv_bfloat162 lo = __floats2bfloat162_rn(v.x, v.y);
    __nv_bfloat162 hi = __floats2bfloat162_rn(v.z, v.w);
    uint2 o; o.x = *(uint32_t*)&lo; o.y = *(uint32_t*)&hi;
    t.dst[r][i] = o;
}
__global__ void convup_kernel(const float* __restrict__ src, __nv_bfloat16* __restrict__ dst) {
    int i = blockIdx.x * 256 + threadIdx.x;
    if (i >= UPN_ * (D_ / 4)) return;
    int p  = i / (D_ / 4);
    int kc = (i % (D_ / 4)) * 4;
    int srow = (p & 1) ? (DFF_ + (p >> 1)) : (p >> 1);
    float4 v = *(const float4*)(src + (size_t)srow * D_ + kc);
    __nv_bfloat162 lo = __floats2bfloat162_rn(v.x, v.y);
    __nv_bfloat162 hi = __floats2bfloat162_rn(v.z, v.w);
    uint2 o; o.x = *(uint32_t*)&lo; o.y = *(uint32_t*)&hi;
    *(uint2*)(dst + (size_t)p * D_ + kc) = o;
}

// ---------------- rmsnorm -> bf16 ----------------
__global__ void rmsnorm_kernel(const float* __restrict__ x, const float* __restrict__ sc,
                               __nv_bfloat16* __restrict__ out) {
    int row = blockIdx.x;
    const float* xr = x + (size_t)row * D_;
    float s = 0.f;
    for (int i = threadIdx.x; i < D_; i += 256) { float v = xr[i]; s += v * v; }
    #pragma unroll
    for (int o = 16; o > 0; o >>= 1) s += __shfl_xor_sync(0xffffffffu, s, o);
    __shared__ float red[8];
    __shared__ float rtot;
    if ((threadIdx.x & 31) == 0) red[threadIdx.x >> 5] = s;
    __syncthreads();
    if (threadIdx.x == 0) {
        float t = 0.f;
        #pragma unroll
        for (int i = 0; i < 8; i++) t += red[i];
        rtot = rsqrtf(t / (float)D_ + 1e-6f);
    }
    __syncthreads();
    float r = rtot;
    for (int i = threadIdx.x; i < D_; i += 256)
        out[(size_t)row * D_ + i] = __float2bfloat16(xr[i] * sc[i] * r);
}

// ---------------- bf16 GEMM NT, BK=64, 3-stage, one barrier per K-iter.
//  MODE: 0 = f32 out + resid, 1 = bf16 out, 2 = paired silu -> bf16 ---------
#define SLDH 72
#define GSMEM(BM) (3 * ((BM) + 128) * SLDH * 2)

template<int BM, int MODE>
__global__ __launch_bounds__(256, 2)
void gemm_bf16(const __nv_bfloat16* __restrict__ A,
               const __nv_bfloat16* __restrict__ Bw,
               const float* __restrict__ R,
               float* __restrict__ Cf,
               __nv_bfloat16* __restrict__ Cb,
               int M, int N, int K) {
    extern __shared__ __nv_bfloat16 smh[];
    constexpr int ATILE = BM * SLDH;
    constexpr int BTILE = 128 * SLDH;
    constexpr int MI = BM / 32;
    __nv_bfloat16* As = smh;                  // [3][ATILE]
    __nv_bfloat16* Bs = smh + 3 * ATILE;      // [3][BTILE]

    const int tid = threadIdx.x;
    const int m0 = blockIdx.y * BM, n0 = blockIdx.x * 128;
    const int w = tid >> 5, lane = tid & 31;
    const int wm = w >> 2, wn = w & 3;
    const int g = lane >> 2, t4 = lane & 3;

    const int arow = (lane & 7) + ((lane >> 3) & 1) * 8;
    const int acol = (lane >> 4) * 8;
    const int brow = (lane & 7) + (lane >> 4) * 8;
    const int bcol = ((lane >> 3) & 1) * 8;

    float acc[MI][4][4];
    #pragma unroll
    for (int i = 0; i < MI; i++)
        #pragma unroll
        for (int j = 0; j < 4; j++)
            #pragma unroll
            for (int r = 0; r < 4; r++) acc[i][j][r] = 0.f;

    auto load_tiles = [&](int stage, int k0) {
        __nv_bfloat16* as = As + stage * ATILE;
        __nv_bfloat16* bs = Bs + stage * BTILE;
        #pragma unroll
        for (int i = 0; i < BM / 32; i++) {
            int id = tid + i * 256;
            int r = id >> 3, c = (id & 7) * 8;
            uint32_t sa = (uint32_t)__cvta_generic_to_shared(as + r * SLDH + c);
            const __nv_bfloat16* ga = A + (size_t)(m0 + r) * K + k0 + c;
            asm volatile("cp.async.cg.shared.global [%0], [%1], 16;\n" :: "r"(sa), "l"(ga));
        }
        #pragma unroll
        for (int i = 0; i < 4; i++) {
            int id = tid + i * 256;
            int r = id >> 3, c = (id & 7) * 8;
            uint32_t sb = (uint32_t)__cvta_generic_to_shared(bs + r * SLDH + c);
            const __nv_bfloat16* gb = Bw + (size_t)(n0 + r) * K + k0 + c;
            asm volatile("cp.async.cg.shared.global [%0], [%1], 16;\n" :: "r"(sb), "l"(gb));
        }
        asm volatile("cp.async.commit_group;\n");
    };

    const int numK = K >> 6;
    load_tiles(0, 0);
    load_tiles(1, 64);

    for (int kt = 0; kt < numK; kt++) {
        if (kt + 1 < numK) asm volatile("cp.async.wait_group 1;\n");
        else               asm volatile("cp.async.wait_group 0;\n");
        __syncthreads();
        if (kt + 2 < numK) load_tiles((kt + 2) % 3, (kt + 2) * 64);

        const __nv_bfloat16* as = As + (kt % 3) * ATILE;
        const __nv_bfloat16* bs = Bs + (kt % 3) * BTILE;

        #pragma unroll
        for (int kb = 0; kb < 4; kb++) {
            uint32_t af[MI][4], bf[4][2];
            #pragma unroll
            for (int mi = 0; mi < MI; mi++) {
                int mr = wm * (BM / 2) + mi * 16 + arow;
                uint32_t ad = (uint32_t)__cvta_generic_to_shared(as + mr * SLDH + kb * 16 + acol);
                ldsm_x4(af[mi], ad);
            }
            #pragma unroll
            for (int np = 0; np < 2; np++) {
                int nr = wn * 32 + np * 16 + brow;
                uint32_t bd = (uint32_t)__cvta_generic_to_shared(bs + nr * SLDH + kb * 16 + bcol);
                uint32_t q[4];
                ldsm_x4(q, bd);
                bf[np*2  ][0] = q[0]; bf[np*2  ][1] = q[1];
                bf[np*2+1][0] = q[2]; bf[np*2+1][1] = q[3];
            }
            #pragma unroll
            for (int mi = 0; mi < MI; mi++)
                #pragma unroll
                for (int ni = 0; ni < 4; ni++)
                    mma_bf16(acc[mi][ni], af[mi], bf[ni]);
        }
    }

    #pragma unroll
    for (int mi = 0; mi < MI; mi++) {
        int r0 = m0 + wm * (BM / 2) + mi * 16 + g;
        #pragma unroll
        for (int ni = 0; ni < 4; ni++) {
            int cc = n0 + wn * 32 + ni * 8 + 2 * t4;
            float a0 = acc[mi][ni][0], a1 = acc[mi][ni][1];
            float a2 = acc[mi][ni][2], a3 = acc[mi][ni][3];
            if (MODE == 0) {
                float2 r0v = *(const float2*)(R + (size_t)r0 * N + cc);
                float2 r1v = *(const float2*)(R + (size_t)(r0 + 8) * N + cc);
                *(float2*)(Cf + (size_t)r0 * N + cc)       = make_float2(a0 + r0v.x, a1 + r0v.y);
                *(float2*)(Cf + (size_t)(r0 + 8) * N + cc) = make_float2(a2 + r1v.x, a3 + r1v.y);
            } else if (MODE == 1) {
                *(__nv_bfloat162*)(Cb + (size_t)r0 * N + cc)       = __floats2bfloat162_rn(a0, a1);
                *(__nv_bfloat162*)(Cb + (size_t)(r0 + 8) * N + cc) = __floats2bfloat162_rn(a2, a3);
            } else {
                int jj = cc >> 1;
                float s0 = a0 * (a1 / (1.f + __expf(-a1)));
                float s1 = a2 * (a3 / (1.f + __expf(-a3)));
                Cb[(size_t)r0 * DFF_ + jj]       = __float2bfloat16(s0);
                Cb[(size_t)(r0 + 8) * DFF_ + jj] = __float2bfloat16(s1);
            }
        }
    }
}

// ---------------- fused q/k cos-scale+RoPE + v copy ----------------
__device__ __forceinline__ float theta_of(int j, int h, float p0, float p1, float p2) {
    int i = j >> 3, f = j & 7;
    float pc = (i == 0) ? p0 : ((i == 1) ? p1 : p2);
    float freq = 3.14159265358979f * __expf((float)(f * 12 + h) * 0.02398526136f);
    return pc * freq;
}

__device__ __forceinline__ void rope_vec(float* shrow, float v0, float v1,
                                         int lane, int h, float sscale,
                                         float p0, float p1, float p2,
                                         __nv_bfloat16* dst) {
    float ss = v0 * v0 + v1 * v1;
    #pragma unroll
    for (int o = 16; o > 0; o >>= 1) ss += __shfl_xor_sync(0xffffffffu, ss, o);
    float f = sscale * rsqrtf(ss + 1e-6f);
    shrow[lane] = v0 * f; shrow[lane + 32] = v1 * f;
    __syncwarp();

    float out0, out1;
    {
        int d = lane;
        if (d < 24) {
            float th = theta_of(d, h, p0, p1, p2);
            float s, c; __sincosf(th, &s, &c);
            out0 = shrow[d] * c - shrow[d + 24] * s;
        } else {
            float th = theta_of(d - 24, h, p0, p1, p2);
            float s, c; __sincosf(th, &s, &c);
            out0 = shrow[d] * c + shrow[d - 24] * s;
        }
    }
    {
        int d = lane + 32;
        if (d < 48) {
            float th = theta_of(d - 24, h, p0, p1, p2);
            float s, c; __sincosf(th, &s, &c);
            out1 = shrow[d] * c + shrow[d - 24] * s;
        } else {
            out1 = shrow[d];
        }
    }
    __syncwarp();
    dst[lane] = __float2bfloat16(out0);
    dst[lane + 32] = __float2bfloat16(out1);
}

__global__ void qkv_pack(const __nv_bfloat16* __restrict__ srcq, int strq, int offq,
                         const __nv_bfloat16* __restrict__ srck, int strk, int offk, int offv,
                         const float* __restrict__ posq, const float* __restrict__ posk,
                         const float* __restrict__ hscale,
                         __nv_bfloat16* __restrict__ dq, __nv_bfloat16* __restrict__ dk,
                         __nv_bfloat16* __restrict__ dv) {
    int wg = (blockIdx.x * blockDim.x + threadIdx.x) >> 5;
    int lane = threadIdx.x & 31;
    if (wg >= B_ * L_ * H_) return;
    int h = wg % H_;
    int bl = wg / H_;
    int b = bl / L_, l = bl % L_;

    __shared__ float sh[8][64];
    float* shrow = sh[threadIdx.x >> 5];
    size_t hdst = ((size_t)(b * H_ + h) * L_ + l) * DH_;

    float s = sqrtf(hscale[h]);
    {
        const __nv_bfloat16* sp = srcq + (size_t)bl * strq + offq + h * DH_;
        float v0 = __bfloat162float(sp[lane]), v1 = __bfloat162float(sp[lane + 32]);
        float p0 = posq[(size_t)bl * 3 + 0], p1 = posq[(size_t)bl * 3 + 1], p2 = posq[(size_t)bl * 3 + 2];
        rope_vec(shrow, v0, v1, lane, h, s, p0, p1, p2, dq + hdst);
    }
    {
        const __nv_bfloat16* sp = srck + (size_t)bl * strk + offk + h * DH_;
        float v0 = __bfloat162float(sp[lane]), v1 = __bfloat162float(sp[lane + 32]);
        float p0 = posk[(size_t)bl * 3 + 0], p1 = posk[(size_t)bl * 3 + 1], p2 = posk[(size_t)bl * 3 + 2];
        rope_vec(shrow, v0, v1, lane, h, s, p0, p1, p2, dk + hdst);
    }
    if (lane < 8) {
        *(uint4*)(dv + hdst + lane * 8) =
            *(const uint4*)(srck + (size_t)bl * strk + offv + h * DH_ + lane * 8);
    }
}

// ---------------- bf16 flash attention, 3-stage cp.async KV pipeline ---------
#define ALD 72
#define ATT_STAGE (128 * ALD)              // halves per stage: K(64 rows)+V(64 rows)
#define ATT_SMEM (3 * ATT_STAGE * 2)       // 55296 bytes

__global__ __launch_bounds__(256, 2) void attn_bf(const __nv_bfloat16* __restrict__ Q,
                                                  const __nv_bfloat16* __restrict__ K,
                                                  const __nv_bfloat16* __restrict__ V,
                                                  __nv_bfloat16* __restrict__ O) {
    extern __shared__ __nv_bfloat16 KVs[];

    const int bh = blockIdx.y;
    const int q0 = blockIdx.x * 128;
    const int tid = threadIdx.x;
    const int w = tid >> 5, lane = tid & 31;
    const int g = lane >> 2, t4 = lane & 3;

    const int arow = (lane & 7) + ((lane >> 3) & 1) * 8;
    const int acol = (lane >> 4) * 8;
    const int brow = (lane & 7) + (lane >> 4) * 8;
    const int bcol = ((lane >> 3) & 1) * 8;
    const int vrow = (lane & 7) + ((lane >> 3) & 1) * 8;
    const int vcol = (lane >> 4) * 8;

    // stage Q (128 rows) into stage-0 region, build per-warp A fragments
    const __nv_bfloat16* qb = Q + ((size_t)bh * L_ + q0) * DH_;
    #pragma unroll
    for (int i = 0; i < 4; i++) {
        int idx = tid + i * 256;
        int r = idx >> 3, c = (idx & 7) * 8;
        *(uint4*)(KVs + r * ALD + c) = *(const uint4*)(qb + r * 64 + c);
    }
    __syncthreads();
    uint32_t qf[4][4];
    #pragma unroll
    for (int kb = 0; kb < 4; kb++) {
        uint32_t ad = (uint32_t)__cvta_generic_to_shared(
            KVs + (w * 16 + arow) * ALD + kb * 16 + acol);
        ldsm_x4(qf[kb], ad);
    }
    __syncthreads();

    const __nv_bfloat16* kbase = K + (size_t)bh * L_ * DH_;
    const __nv_bfloat16* vbase = V + (size_t)bh * L_ * DH_;

    auto load_kv = [&](int stage, int kt) {
        __nv_bfloat16* Ks = KVs + stage * ATT_STAGE;
        __nv_bfloat16* Vs = Ks + 64 * ALD;
        #pragma unroll
        for (int i = 0; i < 2; i++) {
            int idx = tid + i * 256;
            int r = idx >> 3, c = (idx & 7) * 8;
            uint32_t sk = (uint32_t)__cvta_generic_to_shared(Ks + r * ALD + c);
            asm volatile("cp.async.cg.shared.global [%0], [%1], 16;\n"
                         :: "r"(sk), "l"(kbase + (size_t)(kt + r) * 64 + c));
            uint32_t sv = (uint32_t)__cvta_generic_to_shared(Vs + r * ALD + c);
            asm volatile("cp.async.cg.shared.global [%0], [%1], 16;\n"
                         :: "r"(sv), "l"(vbase + (size_t)(kt + r) * 64 + c));
        }
        asm volatile("cp.async.commit_group;\n");
    };

    float ob[8][4];
    #pragma unroll
    for (int n = 0; n < 8; n++)
        #pragma unroll
        for (int r = 0; r < 4; r++) ob[n][r] = 0.f;
    float m0 = -1e30f, m1 = -1e30f, l0 = 0.f, l1 = 0.f;

    const int nt = L_ / 64;
    load_kv(0, 0);
    load_kv(1, 64);

    for (int t = 0; t < nt; t++) {
        if (t + 1 < nt) asm volatile("cp.async.wait_group 1;\n");
        else            asm volatile("cp.async.wait_group 0;\n");
        __syncthreads();
        if (t + 2 < nt) load_kv((t + 2) % 3, (t + 2) * 64);

        const __nv_bfloat16* Ks = KVs + (t % 3) * ATT_STAGE;
        const __nv_bfloat16* Vs = Ks + 64 * ALD;

        // S = Q @ K^T
        float sc[8][4];
        #pragma unroll
        for (int n = 0; n < 8; n++)
            #pragma unroll
            for (int r = 0; r < 4; r++) sc[n][r] = 0.f;
        #pragma unroll
        for (int kb = 0; kb < 4; kb++) {
            uint32_t bf[8][2];
            #pragma unroll
            for (int np = 0; np < 4; np++) {
                uint32_t bd = (uint32_t)__cvta_generic_to_shared(
                    Ks + (np * 16 + brow) * ALD + kb * 16 + bcol);
                uint32_t q[4];
                ldsm_x4(q, bd);
                bf[np*2  ][0] = q[0]; bf[np*2  ][1] = q[1];
                bf[np*2+1][0] = q[2]; bf[np*2+1][1] = q[3];
            }
            #pragma unroll
            for (int n = 0; n < 8; n++)
                mma_bf16(sc[n], qf[kb], bf[n]);
        }

        // online softmax
        float rm0 = -1e30f, rm1 = -1e30f;
        #pragma unroll
        for (int n = 0; n < 8; n++) {
            rm0 = fmaxf(rm0, fmaxf(sc[n][0], sc[n][1]));
            rm1 = fmaxf(rm1, fmaxf(sc[n][2], sc[n][3]));
        }
        rm0 = fmaxf(rm0, __shfl_xor_sync(0xffffffffu, rm0, 1));
        rm0 = fmaxf(rm0, __shfl_xor_sync(0xffffffffu, rm0, 2));
        rm1 = fmaxf(rm1, __shfl_xor_sync(0xffffffffu, rm1, 1));
        rm1 = fmaxf(rm1, __shfl_xor_sync(0xffffffffu, rm1, 2));
        float nm0 = fmaxf(m0, rm0), nm1 = fmaxf(m1, rm1);
        float c0 = __expf(m0 - nm0), c1 = __expf(m1 - nm1);
        m0 = nm0; m1 = nm1;

        float ps0 = 0.f, ps1 = 0.f;
        #pragma unroll
        for (int n = 0; n < 8; n++) {
            sc[n][0] = __expf(sc[n][0] - nm0);
            sc[n][1] = __expf(sc[n][1] - nm0);
            sc[n][2] = __expf(sc[n][2] - nm1);
            sc[n][3] = __expf(sc[n][3] - nm1);
            ps0 += sc[n][0] + sc[n][1];
            ps1 += sc[n][2] + sc[n][3];
        }
        l0 = l0 * c0 + ps0;
        l1 = l1 * c1 + ps1;
        #pragma unroll
        for (int n = 0; n < 8; n++) {
            ob[n][0] *= c0; ob[n][1] *= c0;
            ob[n][2] *= c1; ob[n][3] *= c1;
        }

        // P fragments from registers
        uint32_t pf[4][4];
        #pragma unroll
        for (int kb = 0; kb < 4; kb++) {
            pf[kb][0] = pk_bf(sc[2*kb  ][0], sc[2*kb  ][1]);
            pf[kb][1] = pk_bf(sc[2*kb  ][2], sc[2*kb  ][3]);
            pf[kb][2] = pk_bf(sc[2*kb+1][0], sc[2*kb+1][1]);
            pf[kb][3] = pk_bf(sc[2*kb+1][2], sc[2*kb+1][3]);
        }

        // O += P @ V
        #pragma unroll
        for (int kb = 0; kb < 4; kb++) {
            #pragma unroll
            for (int np = 0; np < 4; np++) {
                uint32_t vd = (uint32_t)__cvta_generic_to_shared(
                    Vs + (kb * 16 + vrow) * ALD + np * 16 + vcol);
                uint32_t q[4];
                ldsm_x4_t(q, vd);
                uint32_t vb0[2] = {q[0], q[1]};
                uint32_t vb1[2] = {q[2], q[3]};
                mma_bf16(ob[np*2  ], pf[kb], vb0);
                mma_bf16(ob[np*2+1], pf[kb], vb1);
            }
        }
    }

    l0 += __shfl_xor_sync(0xffffffffu, l0, 1);
    l0 += __shfl_xor_sync(0xffffffffu, l0, 2);
    l1 += __shfl_xor_sync(0xffffffffu, l1, 1);
    l1 += __shfl_xor_sync(0xffffffffu, l1, 2);
    float inv0 = 1.f / l0, inv1 = 1.f / l1;

    int b = bh / H_, h = bh % H_;
    int r0 = q0 + w * 16 + g;
    __nv_bfloat16* o0 = O + ((size_t)(b * L_ + r0)) * D_ + h * DH_;
    __nv_bfloat16* o1 = O + ((size_t)(b * L_ + r0 + 8)) * D_ + h * DH_;
    #pragma unroll
    for (int n = 0; n < 8; n++) {
        *(__nv_bfloat162*)(o0 + n * 8 + 2 * t4) = __floats2bfloat162_rn(ob[n][0] * inv0, ob[n][1] * inv0);
        *(__nv_bfloat162*)(o1 + n * 8 + 2 * t4) = __floats2bfloat162_rn(ob[n][2] * inv1, ob[n][3] * inv1);
    }
}

// ---------------- host launcher ----------------
extern "C" void kernel_launch(void* const* d_in, const int* in_sizes, int n_in,
                              void* d_out, int out_size) {
    const float* x        = (const float*)d_in[0];
    const float* pos      = (const float*)d_in[1];
    const float* x_cross  = (const float*)d_in[2];
    const float* pos_cross= (const float*)d_in[3];
    const float* sa_norm  = (const float*)d_in[4];
    const float* sa_wqkv  = (const float*)d_in[5];
    const float* sa_scale = (const float*)d_in[6];
    const float* sa_wout  = (const float*)d_in[7];
    const float* ca_norm  = (const float*)d_in[8];
    const float* ca_normc = (const float*)d_in[9];
    const float* ca_wq    = (const float*)d_in[10];
    const float* ca_wkv   = (const float*)d_in[11];
    const float* ca_scale = (const float*)d_in[12];
    const float* ca_wout  = (const float*)d_in[13];
    const float* ff_norm  = (const float*)d_in[14];
    const float* ff_wup   = (const float*)d_in[15];
    const float* ff_wdown = (const float*)d_in[16];
    float* out = (float*)d_out;

    float *x1, *x2;
    __nv_bfloat16 *norm_bf, *normc_bf, *qkv_bf, *lin2_bf, *q_bf, *k_bf, *v_bf, *ao_bf, *ag_bf;
    __nv_bfloat16 *wqkv_bf, *wout1_bf, *wq_bf, *wkv_bf, *wout2_bf, *wup_bf, *wdown_bf;
    cudaGetSymbolAddress((void**)&x1, g_x1);
    cudaGetSymbolAddress((void**)&x2, g_x2);
    cudaGetSymbolAddress((void**)&norm_bf,  g_norm_bf);
    cudaGetSymbolAddress((void**)&normc_bf, g_normc_bf);
    cudaGetSymbolAddress((void**)&qkv_bf,   g_qkv_bf);
    cudaGetSymbolAddress((void**)&lin2_bf,  g_lin2_bf);
    cudaGetSymbolAddress((void**)&q_bf,     g_q_bf);
    cudaGetSymbolAddress((void**)&k_bf,     g_k_bf);
    cudaGetSymbolAddress((void**)&v_bf,     g_v_bf);
    cudaGetSymbolAddress((void**)&ao_bf,    g_ao_bf);
    cudaGetSymbolAddress((void**)&ag_bf,    g_ag_bf);
    cudaGetSymbolAddress((void**)&wqkv_bf,  g_wqkv_bf);
    cudaGetSymbolAddress((void**)&wout1_bf, g_wout1_bf);
    cudaGetSymbolAddress((void**)&wq_bf,    g_wq_bf);
    cudaGetSymbolAddress((void**)&wkv_bf,   g_wkv_bf);
    cudaGetSymbolAddress((void**)&wout2_bf, g_wout2_bf);
    cudaGetSymbolAddress((void**)&wup_bf,   g_wup_bf);
    cudaGetSymbolAddress((void**)&wdown_bf, g_wdown_bf);

    static bool attr_done = false;
    if (!attr_done) {
        cudaFuncSetAttribute((const void*)gemm_bf16<128,1>, cudaFuncAttributeMaxDynamicSharedMemorySize, GSMEM(128));
        cudaFuncSetAttribute((const void*)gemm_bf16<128,2>, cudaFuncAttributeMaxDynamicSharedMemorySize, GSMEM(128));
        cudaFuncSetAttribute((const void*)gemm_bf16<64,0>,  cudaFuncAttributeMaxDynamicSharedMemorySize, GSMEM(64));
        cudaFuncSetAttribute((const void*)gemm_bf16<64,1>,  cudaFuncAttributeMaxDynamicSharedMemorySize, GSMEM(64));
        cudaFuncSetAttribute((const void*)attn_bf, cudaFuncAttributeMaxDynamicSharedMemorySize, ATT_SMEM);
        attr_done = true;
    }

    // ---- weight conversion ----
    ConvTab t;
    t.src[0] = (const float4*)sa_wqkv;  t.dst[0] = (uint2*)wqkv_bf;  t.n4[0] = 2304*768/4;
    t.src[1] = (const float4*)sa_wout;  t.dst[1] = (uint2*)wout1_bf; t.n4[1] = 768*768/4;
    t.src[2] = (const float4*)ca_wq;    t.dst[2] = (uint2*)wq_bf;    t.n4[2] = 768*768/4;
    t.src[3] = (const float4*)ca_wkv;   t.dst[3] = (uint2*)wkv_bf;   t.n4[3] = 1536*768/4;
    t.src[4] = (const float4*)ca_wout;  t.dst[4] = (uint2*)wout2_bf; t.n4[4] = 768*768/4;
    t.src[5] = (const float4*)ff_wdown; t.dst[5] = (uint2*)wdown_bf; t.n4[5] = 768*2304/4;
    conv6_kernel<<<dim3((2304*768/4 + 255)/256, 6), 256>>>(t);
    convup_kernel<<<(UPN_*(D_/4) + 255)/256, 256>>>(ff_wup, wup_bf);

    const int packBlocks = (B_ * L_ * H_ * 32 + 255) / 256;

    // ---- self attention ----
    rmsnorm_kernel<<<M_, 256>>>(x, sa_norm, norm_bf);
    gemm_bf16<128,1><<<dim3(2304/128, M_/128), 256, GSMEM(128)>>>(norm_bf, wqkv_bf, nullptr, nullptr, qkv_bf, M_, 2304, D_);
    qkv_pack<<<packBlocks, 256>>>(qkv_bf, 2304, 0, qkv_bf, 2304, 768, 1536,
                                  pos, pos, sa_scale, q_bf, k_bf, v_bf);
    attn_bf<<<dim3(L_/128, B_*H_), 256, ATT_SMEM>>>(q_bf, k_bf, v_bf, ao_bf);
    gemm_bf16<64,0><<<dim3(D_/128, M_/64), 256, GSMEM(64)>>>(ao_bf, wout1_bf, x, x1, nullptr, M_, D_, D_);

    // ---- cross attention ----
    rmsnorm_kernel<<<M_, 256>>>(x1, ca_norm, norm_bf);
    rmsnorm_kernel<<<M_, 256>>>(x_cross, ca_normc, normc_bf);
    gemm_bf16<64,1><<<dim3(D_/128, M_/64), 256, GSMEM(64)>>>(norm_bf,  wq_bf,  nullptr, nullptr, lin2_bf, M_, D_, D_);
    gemm_bf16<128,1><<<dim3(1536/128, M_/128), 256, GSMEM(128)>>>(normc_bf, wkv_bf, nullptr, nullptr, qkv_bf, M_, 1536, D_);
    qkv_pack<<<packBlocks, 256>>>(lin2_bf, 768, 0, qkv_bf, 1536, 0, 768,
                                  pos, pos_cross, ca_scale, q_bf, k_bf, v_bf);
    attn_bf<<<dim3(L_/128, B_*H_), 256, ATT_SMEM>>>(q_bf, k_bf, v_bf, ao_bf);
    gemm_bf16<64,0><<<dim3(D_/128, M_/64), 256, GSMEM(64)>>>(ao_bf, wout2_bf, x1, x2, nullptr, M_, D_, D_);

    // ---- feed forward (silu fused in up-GEMM epilogue) ----
    rmsnorm_kernel<<<M_, 256>>>(x2, ff_norm, norm_bf);
    gemm_bf16<128,2><<<dim3(UPN_/128, M_/128), 256, GSMEM(128)>>>(norm_bf, wup_bf, nullptr, nullptr, ag_bf, M_, UPN_, D_);
    gemm_bf16<64,0><<<dim3(D_/128, M_/64), 256, GSMEM(64)>>>(ag_bf, wdown_bf, x2, out, nullptr, M_, D_, DFF_);
}